// round 1
// baseline (speedup 1.0000x reference)
#include <cuda_runtime.h>

// ---------------- problem constants ----------------
#define BATCH   4
#define CIN     64
#define CMID    256
#define HH      192
#define WW      192
#define HW      36864          // 192*192
#define NPOLY   128            // B*MAXC
#define PPTS    128            // NPT
#define FPK     8256           // (NPT+1)*CIN
#define NSPLIT  12             // split-K for GEMM1 (8256 = 12*688, 688 = 43*16)

// output layout (floats)
#define O_INIT   0
#define O_COARSE 32768
#define O_MBI    65536
#define O_MBC    (65536 + 4718592)
#define O_FEAT   (65536 + 2*4718592)

// ---------------- device scratch (no allocations allowed) ----------------
__device__ float g_t[BATCH * CMID * HW];     // conv1 output (relu), ~151MB
__device__ float g_mask[64 * HW];            // pnp masks for polys 0..63
__device__ float g_union[BATCH * HW];        // per-batch union mask
__device__ float g_init[NPOLY * PPTS * 2];   // init polys (raw)
__device__ float g_coarse[NPOLY * PPTS * 2]; // coarse polys (raw)
__device__ float g_fp[NPOLY * FPK];          // sampled features
__device__ float g_tmp[NPOLY * 512];         // fp @ w_poly^T
__device__ float g_part[NSPLIT * NPOLY * 512]; // split-K partials

// ---------------- K0: init polys ----------------
__global__ void k_init(const float* __restrict__ wh, const int* __restrict__ ct_ind,
                       const int* __restrict__ ct_img, float* __restrict__ out_init) {
    int n = blockIdx.x;          // 0..127
    int p = threadIdx.x;         // 0..127
    int ind = ct_ind[n];
    int img = ct_img[n];
    int cx = ind % WW;
    int cy = ind / WW;
    size_t base = (size_t)img * CMID * HW + (size_t)cy * WW + cx;
    float ox = wh[base + (size_t)(2 * p) * HW];
    float oy = wh[base + (size_t)(2 * p + 1) * HW];
    float ix = ox * 10.0f + (float)cx;   // INIT_STRIDE, exact op order vs ref
    float iy = oy * 10.0f + (float)cy;
    int o = (n * PPTS + p) * 2;
    g_init[o + 0] = ix;
    g_init[o + 1] = iy;
    out_init[o + 0] = ix * 4.0f;         // DOWN
    out_init[o + 1] = iy * 4.0f;
}

// ---------------- K1: conv1 3x3, 64 -> 256, relu ----------------
// grid (12,12, B*4), block 256. Block tile: 64 oc x 16x16 px. Thread: 8 oc x (2x4) px.
__global__ __launch_bounds__(256) void k_conv1(const float* __restrict__ x,
                                               const float* __restrict__ w,
                                               const float* __restrict__ bias) {
    __shared__ float sIn[18 * 18];
    __shared__ float sW[64 * 9];
    int b = blockIdx.z >> 2;
    int ocbase = (blockIdx.z & 3) * 64;
    int y0 = blockIdx.y * 16, x0 = blockIdx.x * 16;
    int tid = threadIdx.x;
    int g = tid >> 5;            // 0..7  oc subgroup
    int p = tid & 31;
    int prow = p >> 2;           // 0..7
    int pcol = p & 3;            // 0..3

    float acc[8][8];
#pragma unroll
    for (int k = 0; k < 8; k++) {
        float bv = bias[ocbase + g * 8 + k];
#pragma unroll
        for (int j = 0; j < 8; j++) acc[k][j] = bv;
    }

    for (int ic = 0; ic < CIN; ic++) {
        __syncthreads();
        // stage input patch 18x18 (pad=1, zero border)
        for (int i = tid; i < 324; i += 256) {
            int r = i / 18, c = i - r * 18;
            int gy = y0 + r - 1, gx = x0 + c - 1;
            float v = 0.0f;
            if (gy >= 0 && gy < HH && gx >= 0 && gx < WW)
                v = x[((b * CIN + ic) * HH + gy) * WW + gx];
            sIn[i] = v;
        }
        // stage weights 64 oc x 9 taps
#pragma unroll
        for (int rnd = 0; rnd < 3; rnd++) {
            int idx = tid + rnd * 256;
            if (idx < 576) {
                int ocl = idx / 9, tap = idx - ocl * 9;
                sW[idx] = w[((ocbase + ocl) * CIN + ic) * 9 + tap];
            }
        }
        __syncthreads();

        float rIn[4][6];
#pragma unroll
        for (int dy = 0; dy < 4; dy++)
#pragma unroll
            for (int dx = 0; dx < 6; dx++)
                rIn[dy][dx] = sIn[(prow * 2 + dy) * 18 + pcol * 4 + dx];

#pragma unroll
        for (int k = 0; k < 8; k++) {
            const float* wp = &sW[(g * 8 + k) * 9];
            float w0 = wp[0], w1 = wp[1], w2 = wp[2];
            float w3 = wp[3], w4 = wp[4], w5 = wp[5];
            float w6 = wp[6], w7 = wp[7], w8 = wp[8];
#pragma unroll
            for (int py = 0; py < 2; py++)
#pragma unroll
                for (int px = 0; px < 4; px++) {
                    float s = acc[k][py * 4 + px];
                    s += w0 * rIn[py + 0][px + 0];
                    s += w1 * rIn[py + 0][px + 1];
                    s += w2 * rIn[py + 0][px + 2];
                    s += w3 * rIn[py + 1][px + 0];
                    s += w4 * rIn[py + 1][px + 1];
                    s += w5 * rIn[py + 1][px + 2];
                    s += w6 * rIn[py + 2][px + 0];
                    s += w7 * rIn[py + 2][px + 1];
                    s += w8 * rIn[py + 2][px + 2];
                    acc[k][py * 4 + px] = s;
                }
        }
    }

    int gx = x0 + pcol * 4;
#pragma unroll
    for (int k = 0; k < 8; k++) {
        int oc = ocbase + g * 8 + k;
#pragma unroll
        for (int py = 0; py < 2; py++) {
            int gy = y0 + prow * 2 + py;
            float4 v;
            v.x = fmaxf(acc[k][py * 4 + 0], 0.0f);
            v.y = fmaxf(acc[k][py * 4 + 1], 0.0f);
            v.z = fmaxf(acc[k][py * 4 + 2], 0.0f);
            v.w = fmaxf(acc[k][py * 4 + 3], 0.0f);
            *(float4*)&g_t[((size_t)(b * CMID + oc) * HH + gy) * WW + gx] = v;
        }
    }
}

// ---------------- K2: conv2 1x1, 256 -> 64 (+bias, no relu) ----------------
// grid (144, B), block 256. Block: 64 oc x 256 px. Thread: 8 oc x 8 px.
__global__ __launch_bounds__(256) void k_conv2(const float* __restrict__ w2,
                                               const float* __restrict__ b2,
                                               float* __restrict__ feat) {
    __shared__ float sT[8][256];
    __shared__ float sW[8][64];
    int b = blockIdx.y;
    int px0 = blockIdx.x * 256;
    int tid = threadIdx.x;
    int g = tid >> 5;
    int p = tid & 31;

    float acc[8][8];
#pragma unroll
    for (int k = 0; k < 8; k++)
#pragma unroll
        for (int j = 0; j < 8; j++) acc[k][j] = 0.0f;

    for (int m0 = 0; m0 < CMID; m0 += 8) {
        __syncthreads();
#pragma unroll
        for (int r = 0; r < 8; r++)
            sT[r][tid] = g_t[(size_t)(b * CMID + m0 + r) * HW + px0 + tid];
        for (int i = tid; i < 512; i += 256) {
            int mm = i >> 6, oc = i & 63;
            sW[mm][oc] = w2[oc * CMID + m0 + mm];
        }
        __syncthreads();
#pragma unroll
        for (int mm = 0; mm < 8; mm++) {
            float wr[8], tv[8];
#pragma unroll
            for (int k = 0; k < 8; k++) wr[k] = sW[mm][g * 8 + k];
#pragma unroll
            for (int j = 0; j < 8; j++) tv[j] = sT[mm][p + 32 * j];
#pragma unroll
            for (int k = 0; k < 8; k++)
#pragma unroll
                for (int j = 0; j < 8; j++) acc[k][j] += wr[k] * tv[j];
        }
    }
#pragma unroll
    for (int k = 0; k < 8; k++) {
        int oc = g * 8 + k;
        float bb = b2[oc];
#pragma unroll
        for (int j = 0; j < 8; j++)
            feat[(size_t)(b * CIN + oc) * HW + px0 + p + 32 * j] = acc[k][j] + bb;
    }
}

// ---------------- K3: point-in-polygon (scanline compaction) ----------------
// grid (24 rowgroups, 64 polys), block 256. Masks for polys 0..63 only.
__global__ __launch_bounds__(256) void k_pnp(int src) {
    __shared__ float verts[256];
    __shared__ float xint[8][132];
    __shared__ int cnt[8];
    const float* polys = src ? g_coarse : g_init;
    int poly = blockIdx.y;
    int rb = blockIdx.x * 8;
    int tid = threadIdx.x;
    verts[tid] = polys[poly * 256 + tid];
    if (tid < 8) cnt[tid] = 0;
    __syncthreads();

    for (int i = tid; i < 1024; i += 256) {
        int e = i & 127, r = i >> 7;
        float yy = (float)(rb + r);
        int e2 = (e + 1) & 127;
        float y1 = verts[2 * e + 1];
        float y2 = verts[2 * e2 + 1];
        if ((y1 > yy) != (y2 > yy)) {
            float x1 = verts[2 * e];
            float x2 = verts[2 * e2];
            float den = y2 - y1;
            if (fabsf(den) < 1e-9f) den = 1e-9f;
            float xi = x1 + (x2 - x1) * (yy - y1) / den;   // exact ref op order
            int s = atomicAdd(&cnt[r], 1);
            xint[r][s] = xi;
        }
    }
    __syncthreads();

    for (int i = tid; i < 1536; i += 256) {
        int r = i / 192;
        int xp = i - r * 192;
        int c = cnt[r];
        float fx = (float)xp;
        unsigned par = 0;
        for (int j = 0; j < c; j++) par ^= (fx < xint[r][j]) ? 1u : 0u;
        g_mask[(size_t)poly * HW + (rb + r) * WW + xp] = (float)par;
    }
}

// ---------------- K4: mask_batch (with the reference's slicing quirk) + union ----
__global__ void k_mb(const int* __restrict__ ct_num, float* __restrict__ mb) {
    int b = blockIdx.y;
    int px = blockIdx.x * 256 + threadIdx.x;
    int count = ct_num[b];
    int start = (b == 0) ? 0 : ct_num[b - 1];   // quirk: NOT cumulative
    float u = 0.0f;
    for (int c = 0; c < 32; c++) {
        float v = (c < count) ? g_mask[(size_t)(start + c) * HW + px] : 0.0f;
        mb[(size_t)(b * 32 + c) * HW + px] = v;
        u = fmaxf(u, v);
    }
    g_union[b * HW + px] = u;
}

// ---------------- K5: feat = relu(feat * (1 + union)) ----------------
__global__ void k_featmul(float* __restrict__ feat) {
    int idx = blockIdx.x * 256 + threadIdx.x;   // 9437184 total
    int b = idx / (CIN * HW);
    int px = idx % HW;
    float u = g_union[b * HW + px];
    float v = feat[idx];
    feat[idx] = fmaxf(v * (1.0f + u), 0.0f);    // u in {0,1}: exact
}

// ---------------- K6: bilinear sampling -> g_fp ----------------
__global__ __launch_bounds__(256) void k_sample(const float* __restrict__ feat,
                                                const int* __restrict__ ct_ind,
                                                const int* __restrict__ ct_img) {
    __shared__ float s_w[129][4];
    __shared__ int s_off[129][4];
    int n = blockIdx.x;
    int tid = threadIdx.x;
    int img = ct_img[n];
    if (tid < 129) {
        float ptx, pty;
        if (tid == 0) {
            int ind = ct_ind[n];
            ptx = (float)(ind % WW);
            pty = (float)(ind / WW);
        } else {
            ptx = g_init[(n * PPTS + tid - 1) * 2 + 0];
            pty = g_init[(n * PPTS + tid - 1) * 2 + 1];
        }
        float xs = ptx - 0.5f, ys = pty - 0.5f;
        float x0f = floorf(xs), y0f = floorf(ys);
        float wx = xs - x0f, wy = ys - y0f;
        int x0 = (int)x0f, y0 = (int)y0f;
#pragma unroll
        for (int k = 0; k < 4; k++) {
            int xi = x0 + (k & 1);
            int yi = y0 + (k >> 1);
            bool valid = (xi >= 0) && (xi < WW) && (yi >= 0) && (yi < HH);
            int xc = min(max(xi, 0), WW - 1);
            int yc = min(max(yi, 0), HH - 1);
            s_off[tid][k] = yc * WW + xc;
            float wxx = (k & 1) ? wx : (1.0f - wx);
            float wyy = (k >> 1) ? wy : (1.0f - wy);
            s_w[tid][k] = valid ? wxx * wyy : 0.0f;
        }
    }
    __syncthreads();
    for (int i = tid; i < FPK; i += 256) {
        int c = i / 129;
        int p = i - c * 129;
        const float* fc = feat + (size_t)(img * CIN + c) * HW;
        float v = s_w[p][0] * fc[s_off[p][0]]
                + s_w[p][1] * fc[s_off[p][1]]
                + s_w[p][2] * fc[s_off[p][2]]
                + s_w[p][3] * fc[s_off[p][3]];
        g_fp[(size_t)n * FPK + i] = v;
    }
}

// ---------------- K7/K9: tiled NT GEMM (C[M,N] = A[M,K] * B[N,K]^T) ----------------
// MODE 0: g_fp(128x8256) * w_poly^T -> g_part (split-K over blockIdx.z)
// MODE 1: g_tmp(128x512) * w_fuse^T + b_fuse, epilogue -> coarse
template <int MODE>
__global__ __launch_bounds__(256) void k_gemm(const float* __restrict__ Bm,
                                              const float* __restrict__ bias,
                                              float* __restrict__ outc) {
    const int K = (MODE == 0) ? FPK : 512;
    const float* A = (MODE == 0) ? (const float*)g_fp : (const float*)g_tmp;
    __shared__ float sA[16][68];
    __shared__ float sB[16][68];
    int m0 = blockIdx.y * 64, n0 = blockIdx.x * 64;
    int tid = threadIdx.x;
    int tx = tid & 15, ty = tid >> 4;
    int kk = tid & 15, rr = tid >> 4;
    float acc[4][4];
#pragma unroll
    for (int i = 0; i < 4; i++)
#pragma unroll
        for (int j = 0; j < 4; j++) acc[i][j] = 0.0f;

    int kbeg = (MODE == 0) ? blockIdx.z * 688 : 0;
    int kend = (MODE == 0) ? kbeg + 688 : 512;

    for (int k0 = kbeg; k0 < kend; k0 += 16) {
        __syncthreads();
#pragma unroll
        for (int pass = 0; pass < 4; pass++) {
            int row = rr + pass * 16;
            sA[kk][row] = A[(size_t)(m0 + row) * K + k0 + kk];
            sB[kk][row] = Bm[(size_t)(n0 + row) * K + k0 + kk];
        }
        __syncthreads();
#pragma unroll
        for (int k2 = 0; k2 < 16; k2++) {
            float4 a4 = *(const float4*)&sA[k2][ty * 4];
            float4 b4 = *(const float4*)&sB[k2][tx * 4];
            acc[0][0] += a4.x * b4.x; acc[0][1] += a4.x * b4.y; acc[0][2] += a4.x * b4.z; acc[0][3] += a4.x * b4.w;
            acc[1][0] += a4.y * b4.x; acc[1][1] += a4.y * b4.y; acc[1][2] += a4.y * b4.z; acc[1][3] += a4.y * b4.w;
            acc[2][0] += a4.z * b4.x; acc[2][1] += a4.z * b4.y; acc[2][2] += a4.z * b4.z; acc[2][3] += a4.z * b4.w;
            acc[3][0] += a4.w * b4.x; acc[3][1] += a4.w * b4.y; acc[3][2] += a4.w * b4.z; acc[3][3] += a4.w * b4.w;
        }
    }

    if (MODE == 0) {
#pragma unroll
        for (int i = 0; i < 4; i++)
#pragma unroll
            for (int j = 0; j < 4; j++)
                g_part[((size_t)blockIdx.z * 128 + m0 + ty * 4 + i) * 512 + n0 + tx * 4 + j] = acc[i][j];
    } else {
#pragma unroll
        for (int i = 0; i < 4; i++) {
            int m = m0 + ty * 4 + i;
#pragma unroll
            for (int j = 0; j < 4; j++) {
                int nn = n0 + tx * 4 + j;
                float v = acc[i][j] + bias[nn];
                float cr = v * 4.0f + g_init[m * 256 + nn];   // COARSE_STRIDE
                g_coarse[m * 256 + nn] = cr;
                outc[m * 256 + nn] = cr * 4.0f;               // DOWN
            }
        }
    }
}

// ---------------- K8: deterministic split-K reduce ----------------
__global__ void k_reduce() {
    int i = blockIdx.x * 256 + threadIdx.x;   // 65536 total
    float s = 0.0f;
#pragma unroll
    for (int p = 0; p < NSPLIT; p++) s += g_part[(size_t)p * 65536 + i];
    g_tmp[i] = s;
}

// ---------------- launcher ----------------
extern "C" void kernel_launch(void* const* d_in, const int* in_sizes, int n_in,
                              void* d_out, int out_size) {
    const float* wh     = (const float*)d_in[0];
    const float* cnn    = (const float*)d_in[1];
    const float* w1     = (const float*)d_in[2];
    const float* b1     = (const float*)d_in[3];
    const float* w2     = (const float*)d_in[4];
    const float* b2     = (const float*)d_in[5];
    const float* wpoly  = (const float*)d_in[6];
    const float* wfuse  = (const float*)d_in[7];
    const float* bfuse  = (const float*)d_in[8];
    const int*   ct_ind = (const int*)d_in[9];
    const int*   ct_img = (const int*)d_in[10];
    const int*   ct_num = (const int*)d_in[11];

    float* out        = (float*)d_out;
    float* out_init   = out + O_INIT;
    float* out_coarse = out + O_COARSE;
    float* out_mbi    = out + O_MBI;
    float* out_mbc    = out + O_MBC;
    float* feat       = out + O_FEAT;

    k_init<<<128, 128>>>(wh, ct_ind, ct_img, out_init);
    k_conv1<<<dim3(12, 12, 16), 256>>>(cnn, w1, b1);
    k_conv2<<<dim3(144, 4), 256>>>(w2, b2, feat);

    k_pnp<<<dim3(24, 64), 256>>>(0);
    k_mb<<<dim3(144, 4), 256>>>(ct_num, out_mbi);
    k_featmul<<<36864, 256>>>(feat);

    k_sample<<<128, 256>>>(feat, ct_ind, ct_img);
    k_gemm<0><<<dim3(8, 2, NSPLIT), 256>>>(wpoly, nullptr, nullptr);
    k_reduce<<<256, 256>>>();
    k_gemm<1><<<dim3(4, 2), 256>>>(wfuse, bfuse, out_coarse);

    k_pnp<<<dim3(24, 64), 256>>>(1);
    k_mb<<<dim3(144, 4), 256>>>(ct_num, out_mbc);
    k_featmul<<<36864, 256>>>(feat);
}

// round 3
// speedup vs baseline: 2.0851x; 2.0851x over previous
#include <cuda_runtime.h>
#include <cuda_fp16.h>
#include <cstdint>

// ---------------- problem constants ----------------
#define BATCH   4
#define CIN     64
#define HH      192
#define WW      192
#define HW      36864
#define NPOLY   128
#define PPTS    128
#define FPK     8256
#define NSPLIT  12

// output layout (floats)
#define O_INIT   0
#define O_COARSE 32768
#define O_MBI    65536
#define O_MBC    (65536 + 4718592)
#define O_FEAT   (65536 + 2*4718592)

// ---------------- device scratch ----------------
__device__ __half g_xh_h[BATCH * HW * CIN];     // input NHWC hi
__device__ __half g_xh_l[BATCH * HW * CIN];     // input NHWC lo
__device__ __half g_w1h[256 * 576];             // conv1 w, k = tap*64+ic, hi
__device__ __half g_w1l[256 * 576];
__device__ __half g_w2h[64 * 256];              // conv2 w hi
__device__ __half g_w2l[64 * 256];
__device__ __half g_th[(size_t)BATCH * HW * 256]; // t = relu(conv1) NHWC hi
__device__ __half g_tl[(size_t)BATCH * HW * 256];
__device__ float  g_feat[BATCH * HW * CIN];     // feat NHWC fp32
__device__ float  g_mask[64 * HW];
__device__ float  g_union[BATCH * HW];
__device__ float  g_init[NPOLY * PPTS * 2];
__device__ float  g_coarse[NPOLY * PPTS * 2];
__device__ float  g_fp[NPOLY * FPK];
__device__ float  g_tmp[NPOLY * 512];
__device__ float  g_part[NSPLIT * NPOLY * 512];

// ---------------- helpers ----------------
__device__ __forceinline__ uint32_t smem_u32(const void* p) {
    uint32_t a;
    asm("{ .reg .u64 t; cvta.to.shared.u64 t, %1; cvt.u32.u64 %0, t; }" : "=r"(a) : "l"(p));
    return a;
}
__device__ __forceinline__ void cp16(uint32_t dst, const void* src, int sz) {
    asm volatile("cp.async.ca.shared.global [%0], [%1], 16, %2;" :: "r"(dst), "l"(src), "r"(sz));
}
#define CP_COMMIT() asm volatile("cp.async.commit_group;")
#define CP_WAIT1()  asm volatile("cp.async.wait_group 1;")
#define CP_WAIT0()  asm volatile("cp.async.wait_group 0;")
__device__ __forceinline__ void ldmx4(uint32_t addr, uint32_t* r) {
    asm volatile("ldmatrix.sync.aligned.m8n8.x4.shared.b16 {%0,%1,%2,%3}, [%4];"
        : "=r"(r[0]), "=r"(r[1]), "=r"(r[2]), "=r"(r[3]) : "r"(addr));
}
__device__ __forceinline__ void hmma(float* d, const uint32_t* a, const uint32_t* b) {
    asm volatile("mma.sync.aligned.m16n8k16.row.col.f32.f16.f16.f32 "
        "{%0,%1,%2,%3}, {%4,%5,%6,%7}, {%8,%9}, {%0,%1,%2,%3};"
        : "+f"(d[0]), "+f"(d[1]), "+f"(d[2]), "+f"(d[3])
        : "r"(a[0]), "r"(a[1]), "r"(a[2]), "r"(a[3]), "r"(b[0]), "r"(b[1]));
}
// 128B-row tile swizzle
__device__ __forceinline__ uint32_t swz(int row, int colb) {
    return (uint32_t)(row * 128 + (colb ^ ((row & 7) << 4)));
}
__device__ __forceinline__ void split_store(__half* hp, __half* lp, float v) {
    __half h = __float2half_rn(v);
    *hp = h;
    *lp = __float2half_rn(v - __half2float(h));
}

// ---------------- K0: init polys (exact) ----------------
__global__ void k_init(const float* __restrict__ wh, const int* __restrict__ ct_ind,
                       const int* __restrict__ ct_img, float* __restrict__ out_init) {
    int n = blockIdx.x;
    int p = threadIdx.x;
    int ind = ct_ind[n];
    int img = ct_img[n];
    int cx = ind % WW;
    int cy = ind / WW;
    size_t base = (size_t)img * 256 * HW + (size_t)cy * WW + cx;
    float ox = wh[base + (size_t)(2 * p) * HW];
    float oy = wh[base + (size_t)(2 * p + 1) * HW];
    float ix = ox * 10.0f + (float)cx;
    float iy = oy * 10.0f + (float)cy;
    int o = (n * PPTS + p) * 2;
    g_init[o + 0] = ix;
    g_init[o + 1] = iy;
    out_init[o + 0] = ix * 4.0f;
    out_init[o + 1] = iy * 4.0f;
}

// ---------------- prep: NCHW -> NHWC + fp16 hi/lo split ----------------
__global__ void k_prep_x(const float* __restrict__ x) {
    __shared__ float t[32][33];
    int b = blockIdx.z;
    int c0 = blockIdx.y * 32;
    int p0 = blockIdx.x * 32;
    int tx = threadIdx.x, ty = threadIdx.y;
#pragma unroll
    for (int i = 0; i < 32; i += 8)
        t[ty + i][tx] = x[((size_t)b * CIN + c0 + ty + i) * HW + p0 + tx];
    __syncthreads();
#pragma unroll
    for (int i = 0; i < 32; i += 8) {
        size_t o = ((size_t)b * HW + p0 + ty + i) * CIN + c0 + tx;
        split_store(&g_xh_h[o], &g_xh_l[o], t[tx][ty + i]);
    }
}

// ---------------- prep: weights reorder + split ----------------
__global__ void k_prep_w(const float* __restrict__ w1, const float* __restrict__ w2) {
    int i = blockIdx.x * 256 + threadIdx.x;   // 147456 + 16384 = 163840
    if (i < 147456) {
        int oc = i / 576, k = i - oc * 576;
        int tap = k >> 6, ic = k & 63;
        split_store(&g_w1h[i], &g_w1l[i], w1[(oc * 64 + ic) * 9 + tap]);
    } else {
        int j = i - 147456;                   // 64*256, w2[oc][ic]
        split_store(&g_w2h[j], &g_w2l[j], w2[j]);
    }
}

// ---------------- conv1: implicit GEMM, fp16-split 3-MMA ----------------
// grid (288 pxblk, 2 ochalf, 4 b), 256 threads. CTA tile 128px x 128oc, K=576 (9 taps x 64).
// stage (65536B): Ah +0, Al +16384, Bh +32768, Bl +49152. 2 stages = 131072 dyn smem.
__global__ __launch_bounds__(256, 1) void k_conv1(const float* __restrict__ b1) {
    extern __shared__ char sm[];
    uint32_t sb = smem_u32(sm);
    int tid = threadIdx.x, lane = tid & 31, wid = tid >> 5;
    int b = blockIdx.z, oh = blockIdx.y;
    int p0 = blockIdx.x * 128;
    int wm = wid & 3, wn = wid >> 2;

    float acc[2][8][4];
#pragma unroll
    for (int i = 0; i < 2; i++)
#pragma unroll
        for (int j = 0; j < 8; j++)
#pragma unroll
            for (int k = 0; k < 4; k++) acc[i][j][k] = 0.0f;

    int lrow = tid >> 1, lseg = tid & 1;
    int lp = p0 + lrow;
    int ly = lp / 192, lx = lp - ly * 192;
    int locg = oh * 128 + lrow;

    auto load_chunk = [&](int stage, int tap) {
        uint32_t st = sb + (uint32_t)stage * 65536u;
        int dy = tap / 3 - 1, dx = tap % 3 - 1;
        int ny = ly + dy, nx = lx + dx;
        bool v = ((unsigned)ny < 192u) && ((unsigned)nx < 192u);
        size_t np = (size_t)b * HW + (v ? (ny * 192 + nx) : 0);
        const __half* sh = g_xh_h + np * 64 + lseg * 32;
        const __half* sl = g_xh_l + np * 64 + lseg * 32;
        int sz = v ? 16 : 0;
        const __half* wh_ = g_w1h + (size_t)locg * 576 + tap * 64 + lseg * 32;
        const __half* wl_ = g_w1l + (size_t)locg * 576 + tap * 64 + lseg * 32;
#pragma unroll
        for (int q = 0; q < 4; q++) {
            int colb = lseg * 64 + q * 16;
            uint32_t d = swz(lrow, colb);
            cp16(st + d, sh + q * 8, sz);
            cp16(st + 16384u + d, sl + q * 8, sz);
            cp16(st + 32768u + d, wh_ + q * 8, 16);
            cp16(st + 49152u + d, wl_ + q * 8, 16);
        }
    };

    load_chunk(0, 0); CP_COMMIT();

    for (int tap = 0; tap < 9; tap++) {
        if (tap < 8) { load_chunk((tap + 1) & 1, tap + 1); CP_COMMIT(); CP_WAIT1(); }
        else CP_WAIT0();
        __syncthreads();
        uint32_t st = sb + (uint32_t)(tap & 1) * 65536u;
#pragma unroll
        for (int k16 = 0; k16 < 4; k16++) {
            int kb = k16 * 32;
            uint32_t ah[2][4], al[2][4];
#pragma unroll
            for (int mt = 0; mt < 2; mt++) {
                int row = wm * 32 + mt * 16 + (lane & 15);
                int colb = kb + (lane >> 4) * 16;
                uint32_t d = swz(row, colb);
                ldmx4(st + d, ah[mt]);
                ldmx4(st + 16384u + d, al[mt]);
            }
            uint32_t bh[8][2], bl[8][2];
#pragma unroll
            for (int ng = 0; ng < 4; ng++) {
                int row = wn * 64 + ng * 16 + ((lane >> 4) << 3) + (lane & 7);
                int colb = kb + ((lane >> 3) & 1) * 16;
                uint32_t d = swz(row, colb);
                uint32_t r[4];
                ldmx4(st + 32768u + d, r);
                bh[ng * 2][0] = r[0]; bh[ng * 2][1] = r[1];
                bh[ng * 2 + 1][0] = r[2]; bh[ng * 2 + 1][1] = r[3];
                ldmx4(st + 49152u + d, r);
                bl[ng * 2][0] = r[0]; bl[ng * 2][1] = r[1];
                bl[ng * 2 + 1][0] = r[2]; bl[ng * 2 + 1][1] = r[3];
            }
#pragma unroll
            for (int mt = 0; mt < 2; mt++)
#pragma unroll
                for (int nt = 0; nt < 8; nt++) {
                    hmma(acc[mt][nt], ah[mt], bh[nt]);
                    hmma(acc[mt][nt], al[mt], bh[nt]);
                    hmma(acc[mt][nt], ah[mt], bl[nt]);
                }
        }
        __syncthreads();
    }

    // epilogue: t = relu(D + b1) -> hi/lo fp16 NHWC [b][px][256]
#pragma unroll
    for (int mt = 0; mt < 2; mt++) {
        int m = wm * 32 + mt * 16 + (lane >> 2);
#pragma unroll
        for (int nt = 0; nt < 8; nt++) {
            int oc = oh * 128 + wn * 64 + nt * 8 + (lane & 3) * 2;
            float bb0 = __ldg(&b1[oc]), bb1 = __ldg(&b1[oc + 1]);
#pragma unroll
            for (int rh = 0; rh < 2; rh++) {
                int px = p0 + m + rh * 8;
                float t0 = fmaxf(acc[mt][nt][rh * 2 + 0] + bb0, 0.0f);
                float t1 = fmaxf(acc[mt][nt][rh * 2 + 1] + bb1, 0.0f);
                __half h0 = __float2half_rn(t0), h1 = __float2half_rn(t1);
                size_t o = ((size_t)b * HW + px) * 256 + oc;
                *(__half2*)&g_th[o] = __halves2half2(h0, h1);
                *(__half2*)&g_tl[o] = __halves2half2(
                    __float2half_rn(t0 - __half2float(h0)),
                    __float2half_rn(t1 - __half2float(h1)));
            }
        }
    }
}

// ---------------- conv2: 1x1 GEMM 256->64, fp16-split 3-MMA ----------------
// grid (288, 1, 4), 256 threads. CTA 128px x 64oc, K=256 (4 chunks of 64).
// stage (49152B): Ah +0, Al +16384, Bh +32768(8KB), Bl +40960. 2 stages = 98304 dyn.
__global__ __launch_bounds__(256, 1) void k_conv2(const float* __restrict__ b2) {
    extern __shared__ char sm[];
    uint32_t sb = smem_u32(sm);
    int tid = threadIdx.x, lane = tid & 31, wid = tid >> 5;
    int b = blockIdx.z;
    int p0 = blockIdx.x * 128;
    int wm = wid & 3, wn = wid >> 2;   // wn 0..1

    float acc[2][4][4];
#pragma unroll
    for (int i = 0; i < 2; i++)
#pragma unroll
        for (int j = 0; j < 4; j++)
#pragma unroll
            for (int k = 0; k < 4; k++) acc[i][j][k] = 0.0f;

    int lrow = tid >> 1, lseg = tid & 1;
    int brow = tid >> 2, bq = tid & 3;

    auto load_chunk = [&](int stage, int ch) {
        uint32_t st = sb + (uint32_t)stage * 49152u;
        const __half* ah_ = g_th + ((size_t)b * HW + p0 + lrow) * 256 + ch * 64 + lseg * 32;
        const __half* al_ = g_tl + ((size_t)b * HW + p0 + lrow) * 256 + ch * 64 + lseg * 32;
#pragma unroll
        for (int q = 0; q < 4; q++) {
            int colb = lseg * 64 + q * 16;
            uint32_t d = swz(lrow, colb);
            cp16(st + d, ah_ + q * 8, 16);
            cp16(st + 16384u + d, al_ + q * 8, 16);
        }
        const __half* bh_ = g_w2h + (size_t)brow * 256 + ch * 64 + bq * 16;
        const __half* bl_ = g_w2l + (size_t)brow * 256 + ch * 64 + bq * 16;
#pragma unroll
        for (int q = 0; q < 2; q++) {
            int colb = bq * 32 + q * 16;
            uint32_t d = swz(brow, colb);
            cp16(st + 32768u + d, bh_ + q * 8, 16);
            cp16(st + 40960u + d, bl_ + q * 8, 16);
        }
    };

    load_chunk(0, 0); CP_COMMIT();

    for (int ch = 0; ch < 4; ch++) {
        if (ch < 3) { load_chunk((ch + 1) & 1, ch + 1); CP_COMMIT(); CP_WAIT1(); }
        else CP_WAIT0();
        __syncthreads();
        uint32_t st = sb + (uint32_t)(ch & 1) * 49152u;
#pragma unroll
        for (int k16 = 0; k16 < 4; k16++) {
            int kb = k16 * 32;
            uint32_t ah[2][4], al[2][4];
#pragma unroll
            for (int mt = 0; mt < 2; mt++) {
                int row = wm * 32 + mt * 16 + (lane & 15);
                int colb = kb + (lane >> 4) * 16;
                uint32_t d = swz(row, colb);
                ldmx4(st + d, ah[mt]);
                ldmx4(st + 16384u + d, al[mt]);
            }
            uint32_t bh[4][2], bl[4][2];
#pragma unroll
            for (int ng = 0; ng < 2; ng++) {
                int row = wn * 32 + ng * 16 + ((lane >> 4) << 3) + (lane & 7);
                int colb = kb + ((lane >> 3) & 1) * 16;
                uint32_t d = swz(row, colb);
                uint32_t r[4];
                ldmx4(st + 32768u + d, r);
                bh[ng * 2][0] = r[0]; bh[ng * 2][1] = r[1];
                bh[ng * 2 + 1][0] = r[2]; bh[ng * 2 + 1][1] = r[3];
                ldmx4(st + 40960u + d, r);
                bl[ng * 2][0] = r[0]; bl[ng * 2][1] = r[1];
                bl[ng * 2 + 1][0] = r[2]; bl[ng * 2 + 1][1] = r[3];
            }
#pragma unroll
            for (int mt = 0; mt < 2; mt++)
#pragma unroll
                for (int nt = 0; nt < 4; nt++) {
                    hmma(acc[mt][nt], ah[mt], bh[nt]);
                    hmma(acc[mt][nt], al[mt], bh[nt]);
                    hmma(acc[mt][nt], ah[mt], bl[nt]);
                }
        }
        __syncthreads();
    }

    // epilogue: feat = D + b2 -> fp32 NHWC
#pragma unroll
    for (int mt = 0; mt < 2; mt++) {
        int m = wm * 32 + mt * 16 + (lane >> 2);
#pragma unroll
        for (int nt = 0; nt < 4; nt++) {
            int oc = wn * 32 + nt * 8 + (lane & 3) * 2;
            float bb0 = __ldg(&b2[oc]), bb1 = __ldg(&b2[oc + 1]);
#pragma unroll
            for (int rh = 0; rh < 2; rh++) {
                int px = p0 + m + rh * 8;
                float2 v;
                v.x = acc[mt][nt][rh * 2 + 0] + bb0;
                v.y = acc[mt][nt][rh * 2 + 1] + bb1;
                *(float2*)&g_feat[((size_t)b * HW + px) * 64 + oc] = v;
            }
        }
    }
}

// ---------------- point-in-polygon ----------------
__global__ __launch_bounds__(256) void k_pnp(int src) {
    __shared__ float verts[256];
    __shared__ float xint[8][132];
    __shared__ int cnt[8];
    const float* polys = src ? g_coarse : g_init;
    int poly = blockIdx.y;
    int rb = blockIdx.x * 8;
    int tid = threadIdx.x;
    verts[tid] = polys[poly * 256 + tid];
    if (tid < 8) cnt[tid] = 0;
    __syncthreads();
    for (int i = tid; i < 1024; i += 256) {
        int e = i & 127, r = i >> 7;
        float yy = (float)(rb + r);
        int e2 = (e + 1) & 127;
        float y1 = verts[2 * e + 1];
        float y2 = verts[2 * e2 + 1];
        if ((y1 > yy) != (y2 > yy)) {
            float x1 = verts[2 * e];
            float x2 = verts[2 * e2];
            float den = y2 - y1;
            if (fabsf(den) < 1e-9f) den = 1e-9f;
            float xi = x1 + (x2 - x1) * (yy - y1) / den;
            int s = atomicAdd(&cnt[r], 1);
            xint[r][s] = xi;
        }
    }
    __syncthreads();
    for (int i = tid; i < 1536; i += 256) {
        int r = i / 192;
        int xp = i - r * 192;
        int c = cnt[r];
        float fx = (float)xp;
        unsigned par = 0;
        for (int j = 0; j < c; j++) par ^= (fx < xint[r][j]) ? 1u : 0u;
        g_mask[(size_t)poly * HW + (rb + r) * WW + xp] = (float)par;
    }
}

// ---------------- mask_batch + union ----------------
__global__ void k_mb(const int* __restrict__ ct_num, float* __restrict__ mb) {
    int b = blockIdx.y;
    int px = blockIdx.x * 256 + threadIdx.x;
    int count = ct_num[b];
    int start = (b == 0) ? 0 : ct_num[b - 1];   // reference slicing quirk
    float u = 0.0f;
    for (int c = 0; c < 32; c++) {
        float v = (c < count) ? g_mask[(size_t)(start + c) * HW + px] : 0.0f;
        mb[(size_t)(b * 32 + c) * HW + px] = v;
        u = fmaxf(u, v);
    }
    g_union[b * HW + px] = u;
}

// ---------------- featmul pass 1 (NHWC in-place) ----------------
__global__ void k_featmul_h() {
    int idx = blockIdx.x * 256 + threadIdx.x;
    float u = g_union[idx >> 6];
    float v = g_feat[idx];
    g_feat[idx] = fmaxf(v * (1.0f + u), 0.0f);
}

// ---------------- final: featmul pass 2 + NHWC -> NCHW ----------------
__global__ void k_final(float* __restrict__ out) {
    __shared__ float t[32][33];
    int b = blockIdx.z;
    int c0 = blockIdx.y * 32;
    int p0 = blockIdx.x * 32;
    int tx = threadIdx.x, ty = threadIdx.y;
#pragma unroll
    for (int i = 0; i < 32; i += 8) {
        int p = p0 + ty + i;
        float u = g_union[b * HW + p];
        float v = g_feat[((size_t)b * HW + p) * CIN + c0 + tx];
        t[ty + i][tx] = fmaxf(v * (1.0f + u), 0.0f);
    }
    __syncthreads();
#pragma unroll
    for (int i = 0; i < 32; i += 8)
        out[((size_t)b * CIN + c0 + ty + i) * HW + p0 + tx] = t[tx][ty + i];
}

// ---------------- bilinear sampling (NHWC) ----------------
__global__ __launch_bounds__(256) void k_sample(const int* __restrict__ ct_ind,
                                                const int* __restrict__ ct_img) {
    __shared__ float s_w[129][4];
    __shared__ int s_off[129][4];
    int n = blockIdx.x;
    int tid = threadIdx.x;
    int img = ct_img[n];
    if (tid < 129) {
        float ptx, pty;
        if (tid == 0) {
            int ind = ct_ind[n];
            ptx = (float)(ind % WW);
            pty = (float)(ind / WW);
        } else {
            ptx = g_init[(n * PPTS + tid - 1) * 2 + 0];
            pty = g_init[(n * PPTS + tid - 1) * 2 + 1];
        }
        float xs = ptx - 0.5f, ys = pty - 0.5f;
        float x0f = floorf(xs), y0f = floorf(ys);
        float wx = xs - x0f, wy = ys - y0f;
        int x0 = (int)x0f, y0 = (int)y0f;
#pragma unroll
        for (int k = 0; k < 4; k++) {
            int xi = x0 + (k & 1);
            int yi = y0 + (k >> 1);
            bool valid = (xi >= 0) && (xi < WW) && (yi >= 0) && (yi < HH);
            int xc = min(max(xi, 0), WW - 1);
            int yc = min(max(yi, 0), HH - 1);
            s_off[tid][k] = yc * WW + xc;
            float wxx = (k & 1) ? wx : (1.0f - wx);
            float wyy = (k >> 1) ? wy : (1.0f - wy);
            s_w[tid][k] = valid ? wxx * wyy : 0.0f;
        }
    }
    __syncthreads();
    const float* fb = g_feat + (size_t)img * HW * CIN;
    for (int i = tid; i < FPK; i += 256) {
        int pp = i >> 6;
        int c = i & 63;
        float v = s_w[pp][0] * fb[(size_t)s_off[pp][0] * CIN + c]
                + s_w[pp][1] * fb[(size_t)s_off[pp][1] * CIN + c]
                + s_w[pp][2] * fb[(size_t)s_off[pp][2] * CIN + c]
                + s_w[pp][3] * fb[(size_t)s_off[pp][3] * CIN + c];
        g_fp[(size_t)n * FPK + c * 129 + pp] = v;
    }
}

// ---------------- NT GEMMs for offsets (fp32, exact path) ----------------
template <int MODE>
__global__ __launch_bounds__(256) void k_gemm(const float* __restrict__ Bm,
                                              const float* __restrict__ bias,
                                              float* __restrict__ outc) {
    const int K = (MODE == 0) ? FPK : 512;
    const float* A = (MODE == 0) ? (const float*)g_fp : (const float*)g_tmp;
    __shared__ float sA[16][68];
    __shared__ float sB[16][68];
    int m0 = blockIdx.y * 64, n0 = blockIdx.x * 64;
    int tid = threadIdx.x;
    int tx = tid & 15, ty = tid >> 4;
    int kk = tid & 15, rr = tid >> 4;
    float acc[4][4];
#pragma unroll
    for (int i = 0; i < 4; i++)
#pragma unroll
        for (int j = 0; j < 4; j++) acc[i][j] = 0.0f;

    int kbeg = (MODE == 0) ? blockIdx.z * 688 : 0;
    int kend = (MODE == 0) ? kbeg + 688 : 512;
    for (int k0 = kbeg; k0 < kend; k0 += 16) {
        __syncthreads();
#pragma unroll
        for (int pass = 0; pass < 4; pass++) {
            int row = rr + pass * 16;
            sA[kk][row] = A[(size_t)(m0 + row) * K + k0 + kk];
            sB[kk][row] = Bm[(size_t)(n0 + row) * K + k0 + kk];
        }
        __syncthreads();
#pragma unroll
        for (int k2 = 0; k2 < 16; k2++) {
            float4 a4 = *(const float4*)&sA[k2][ty * 4];
            float4 b4 = *(const float4*)&sB[k2][tx * 4];
            acc[0][0] += a4.x * b4.x; acc[0][1] += a4.x * b4.y; acc[0][2] += a4.x * b4.z; acc[0][3] += a4.x * b4.w;
            acc[1][0] += a4.y * b4.x; acc[1][1] += a4.y * b4.y; acc[1][2] += a4.y * b4.z; acc[1][3] += a4.y * b4.w;
            acc[2][0] += a4.z * b4.x; acc[2][1] += a4.z * b4.y; acc[2][2] += a4.z * b4.z; acc[2][3] += a4.z * b4.w;
            acc[3][0] += a4.w * b4.x; acc[3][1] += a4.w * b4.y; acc[3][2] += a4.w * b4.z; acc[3][3] += a4.w * b4.w;
        }
    }
    if (MODE == 0) {
#pragma unroll
        for (int i = 0; i < 4; i++)
#pragma unroll
            for (int j = 0; j < 4; j++)
                g_part[((size_t)blockIdx.z * 128 + m0 + ty * 4 + i) * 512 + n0 + tx * 4 + j] = acc[i][j];
    } else {
#pragma unroll
        for (int i = 0; i < 4; i++) {
            int m = m0 + ty * 4 + i;
#pragma unroll
            for (int j = 0; j < 4; j++) {
                int nn = n0 + tx * 4 + j;
                float v = acc[i][j] + bias[nn];
                float cr = v * 4.0f + g_init[m * 256 + nn];
                g_coarse[m * 256 + nn] = cr;
                outc[m * 256 + nn] = cr * 4.0f;
            }
        }
    }
}

__global__ void k_reduce() {
    int i = blockIdx.x * 256 + threadIdx.x;
    float s = 0.0f;
#pragma unroll
    for (int p = 0; p < NSPLIT; p++) s += g_part[(size_t)p * 65536 + i];
    g_tmp[i] = s;
}

// ---------------- launcher ----------------
extern "C" void kernel_launch(void* const* d_in, const int* in_sizes, int n_in,
                              void* d_out, int out_size) {
    const float* wh     = (const float*)d_in[0];
    const float* cnn    = (const float*)d_in[1];
    const float* w1     = (const float*)d_in[2];
    const float* b1     = (const float*)d_in[3];
    const float* w2     = (const float*)d_in[4];
    const float* b2     = (const float*)d_in[5];
    const float* wpoly  = (const float*)d_in[6];
    const float* wfuse  = (const float*)d_in[7];
    const float* bfuse  = (const float*)d_in[8];
    const int*   ct_ind = (const int*)d_in[9];
    const int*   ct_img = (const int*)d_in[10];
    const int*   ct_num = (const int*)d_in[11];

    float* out        = (float*)d_out;
    float* out_init   = out + O_INIT;
    float* out_coarse = out + O_COARSE;
    float* out_mbi    = out + O_MBI;
    float* out_mbc    = out + O_MBC;
    float* out_feat   = out + O_FEAT;

    cudaFuncSetAttribute(k_conv1, cudaFuncAttributeMaxDynamicSharedMemorySize, 131072);
    cudaFuncSetAttribute(k_conv2, cudaFuncAttributeMaxDynamicSharedMemorySize, 98304);

    k_init<<<128, 128>>>(wh, ct_ind, ct_img, out_init);
    k_prep_x<<<dim3(1152, 2, 4), dim3(32, 8)>>>(cnn);
    k_prep_w<<<640, 256>>>(w1, w2);
    k_conv1<<<dim3(288, 2, 4), 256, 131072>>>(b1);
    k_conv2<<<dim3(288, 1, 4), 256, 98304>>>(b2);

    k_pnp<<<dim3(24, 64), 256>>>(0);
    k_mb<<<dim3(144, 4), 256>>>(ct_num, out_mbi);
    k_featmul_h<<<36864, 256>>>();

    k_sample<<<128, 256>>>(ct_ind, ct_img);
    k_gemm<0><<<dim3(8, 2, NSPLIT), 256>>>(wpoly, nullptr, nullptr);
    k_reduce<<<256, 256>>>();
    k_gemm<1><<<dim3(4, 2), 256>>>(wfuse, bfuse, out_coarse);

    k_pnp<<<dim3(24, 64), 256>>>(1);
    k_mb<<<dim3(144, 4), 256>>>(ct_num, out_mbc);
    k_final<<<dim3(1152, 2, 4), dim3(32, 8)>>>(out_feat);
}

// round 4
// speedup vs baseline: 2.4184x; 1.1598x over previous
#include <cuda_runtime.h>
#include <cuda_fp16.h>
#include <cstdint>

// ---------------- problem constants ----------------
#define BATCH   4
#define CIN     64
#define HH      192
#define WW      192
#define HW      36864
#define NPOLY   128
#define PPTS    128
#define FPK     8256
#define NSPLIT  12

// output layout (floats)
#define O_INIT   0
#define O_COARSE 32768
#define O_MBI    65536
#define O_MBC    (65536 + 4718592)
#define O_FEAT   (65536 + 2*4718592)

// ---------------- device scratch ----------------
__device__ __half g_xh_h[BATCH * HW * CIN];
__device__ __half g_xh_l[BATCH * HW * CIN];
__device__ __half g_w1h[256 * 576];
__device__ __half g_w1l[256 * 576];
__device__ __half g_w2h[64 * 256];
__device__ __half g_w2l[64 * 256];
__device__ __half g_th[(size_t)BATCH * HW * 256];
__device__ __half g_tl[(size_t)BATCH * HW * 256];
__device__ float  g_feat[BATCH * HW * CIN];
__device__ float  g_mask[64 * HW];
__device__ float  g_union[BATCH * HW];
__device__ float  g_init[NPOLY * PPTS * 2];
__device__ float  g_coarse[NPOLY * PPTS * 2];
__device__ float  g_fp[NPOLY * FPK];
__device__ float  g_tmp[NPOLY * 512];
__device__ float  g_part[NSPLIT * NPOLY * 512];

// ---------------- helpers ----------------
__device__ __forceinline__ uint32_t smem_u32(const void* p) {
    uint32_t a;
    asm("{ .reg .u64 t; cvta.to.shared.u64 t, %1; cvt.u32.u64 %0, t; }" : "=r"(a) : "l"(p));
    return a;
}
__device__ __forceinline__ void cp16(uint32_t dst, const void* src, int sz) {
    asm volatile("cp.async.ca.shared.global [%0], [%1], 16, %2;" :: "r"(dst), "l"(src), "r"(sz));
}
#define CP_COMMIT() asm volatile("cp.async.commit_group;")
#define CP_WAIT2()  asm volatile("cp.async.wait_group 2;")
#define CP_WAIT1()  asm volatile("cp.async.wait_group 1;")
#define CP_WAIT0()  asm volatile("cp.async.wait_group 0;")
__device__ __forceinline__ void ldmx4(uint32_t addr, uint32_t* r) {
    asm volatile("ldmatrix.sync.aligned.m8n8.x4.shared.b16 {%0,%1,%2,%3}, [%4];"
        : "=r"(r[0]), "=r"(r[1]), "=r"(r[2]), "=r"(r[3]) : "r"(addr));
}
__device__ __forceinline__ void hmma(float* d, const uint32_t* a, const uint32_t* b) {
    asm volatile("mma.sync.aligned.m16n8k16.row.col.f32.f16.f16.f32 "
        "{%0,%1,%2,%3}, {%4,%5,%6,%7}, {%8,%9}, {%0,%1,%2,%3};"
        : "+f"(d[0]), "+f"(d[1]), "+f"(d[2]), "+f"(d[3])
        : "r"(a[0]), "r"(a[1]), "r"(a[2]), "r"(a[3]), "r"(b[0]), "r"(b[1]));
}
// 64B-row tile swizzle: conflict-free for 8-row ldmatrix phases
__device__ __forceinline__ uint32_t swz64(int row, int colb) {
    return (uint32_t)(row * 64 + (colb ^ (((row >> 1) & 3) << 4)));
}
__device__ __forceinline__ void split_store(__half* hp, __half* lp, float v) {
    __half h = __float2half_rn(v);
    *hp = h;
    *lp = __float2half_rn(v - __half2float(h));
}

// ---------------- K0: init polys (exact) ----------------
__global__ void k_init(const float* __restrict__ wh, const int* __restrict__ ct_ind,
                       const int* __restrict__ ct_img, float* __restrict__ out_init) {
    int n = blockIdx.x;
    int p = threadIdx.x;
    int ind = ct_ind[n];
    int img = ct_img[n];
    int cx = ind % WW;
    int cy = ind / WW;
    size_t base = (size_t)img * 256 * HW + (size_t)cy * WW + cx;
    float ox = wh[base + (size_t)(2 * p) * HW];
    float oy = wh[base + (size_t)(2 * p + 1) * HW];
    float ix = ox * 10.0f + (float)cx;
    float iy = oy * 10.0f + (float)cy;
    int o = (n * PPTS + p) * 2;
    g_init[o + 0] = ix;
    g_init[o + 1] = iy;
    out_init[o + 0] = ix * 4.0f;
    out_init[o + 1] = iy * 4.0f;
}

// ---------------- prep: NCHW -> NHWC + fp16 hi/lo split ----------------
__global__ void k_prep_x(const float* __restrict__ x) {
    __shared__ float t[32][33];
    int b = blockIdx.z;
    int c0 = blockIdx.y * 32;
    int p0 = blockIdx.x * 32;
    int tx = threadIdx.x, ty = threadIdx.y;
#pragma unroll
    for (int i = 0; i < 32; i += 8)
        t[ty + i][tx] = x[((size_t)b * CIN + c0 + ty + i) * HW + p0 + tx];
    __syncthreads();
#pragma unroll
    for (int i = 0; i < 32; i += 8) {
        size_t o = ((size_t)b * HW + p0 + ty + i) * CIN + c0 + tx;
        split_store(&g_xh_h[o], &g_xh_l[o], t[tx][ty + i]);
    }
}

// ---------------- prep: weights reorder + split ----------------
__global__ void k_prep_w(const float* __restrict__ w1, const float* __restrict__ w2) {
    int i = blockIdx.x * 256 + threadIdx.x;
    if (i < 147456) {
        int oc = i / 576, k = i - oc * 576;
        int tap = k >> 6, ic = k & 63;
        split_store(&g_w1h[i], &g_w1l[i], w1[(oc * 64 + ic) * 9 + tap]);
    } else {
        int j = i - 147456;
        split_store(&g_w2h[j], &g_w2l[j], w2[j]);
    }
}

// ---------------- conv1: implicit GEMM, fp16-split 3-MMA, 2 CTA/SM ----------------
// grid (288, 2, 4), 256 thr. CTA 128px x 128oc, K = 18 chunks of 32 (half-taps).
// 3 stages x 32KB = 98304 dyn smem. Stage: Ah@0 Al@8192 Bh@16384 Bl@24576.
__global__ __launch_bounds__(256, 2) void k_conv1(const float* __restrict__ b1) {
    extern __shared__ char sm[];
    uint32_t sb = smem_u32(sm);
    int tid = threadIdx.x, lane = tid & 31, wid = tid >> 5;
    int b = blockIdx.z, oh = blockIdx.y;
    int p0 = blockIdx.x * 128;
    int wm = wid & 1, wn = wid >> 1;   // warp tile M64 x N32

    float acc[4][4][4];
#pragma unroll
    for (int i = 0; i < 4; i++)
#pragma unroll
        for (int j = 0; j < 4; j++)
#pragma unroll
            for (int k = 0; k < 4; k++) acc[i][j][k] = 0.0f;

    auto load_chunk = [&](int chunk) {
        uint32_t st = sb + (uint32_t)(chunk % 3) * 32768u;
        int tap = chunk >> 1, half = chunk & 1;
        int dy = tap / 3 - 1, dx = tap % 3 - 1;
        int seg = tid & 3;
#pragma unroll
        for (int rr = 0; rr < 2; rr++) {
            int row = (tid >> 2) + rr * 64;
            uint32_t d = swz64(row, seg * 16);
            // A
            int px = p0 + row;
            int yy = px / 192, xx = px - yy * 192;
            int ny = yy + dy, nx = xx + dx;
            bool v = ((unsigned)ny < 192u) && ((unsigned)nx < 192u);
            size_t np = ((size_t)b * HW + (v ? (ny * 192 + nx) : 0)) * 64 + half * 32 + seg * 8;
            int sz = v ? 16 : 0;
            cp16(st + d, g_xh_h + np, sz);
            cp16(st + 8192u + d, g_xh_l + np, sz);
            // B
            size_t wp = (size_t)(oh * 128 + row) * 576 + tap * 64 + half * 32 + seg * 8;
            cp16(st + 16384u + d, g_w1h + wp, 16);
            cp16(st + 24576u + d, g_w1l + wp, 16);
        }
    };

    load_chunk(0); CP_COMMIT();
    load_chunk(1); CP_COMMIT();
    load_chunk(2); CP_COMMIT();

    for (int c = 0; c < 18; c++) {
        CP_WAIT2();
        __syncthreads();
        uint32_t st = sb + (uint32_t)(c % 3) * 32768u;
#pragma unroll
        for (int k16 = 0; k16 < 2; k16++) {
            int kb = k16 * 32;
            uint32_t ah[4][4], al[4][4];
#pragma unroll
            for (int mt = 0; mt < 4; mt++) {
                int row = wm * 64 + mt * 16 + (lane & 15);
                int colb = kb + (lane >> 4) * 16;
                uint32_t d = swz64(row, colb);
                ldmx4(st + d, ah[mt]);
                ldmx4(st + 8192u + d, al[mt]);
            }
            uint32_t bh[4][2], bl[4][2];
#pragma unroll
            for (int ng = 0; ng < 2; ng++) {
                int row = wn * 32 + ng * 16 + ((lane >> 4) << 3) + (lane & 7);
                int colb = kb + ((lane >> 3) & 1) * 16;
                uint32_t d = swz64(row, colb);
                uint32_t r[4];
                ldmx4(st + 16384u + d, r);
                bh[ng * 2][0] = r[0]; bh[ng * 2][1] = r[1];
                bh[ng * 2 + 1][0] = r[2]; bh[ng * 2 + 1][1] = r[3];
                ldmx4(st + 24576u + d, r);
                bl[ng * 2][0] = r[0]; bl[ng * 2][1] = r[1];
                bl[ng * 2 + 1][0] = r[2]; bl[ng * 2 + 1][1] = r[3];
            }
#pragma unroll
            for (int mt = 0; mt < 4; mt++)
#pragma unroll
                for (int nt = 0; nt < 4; nt++) {
                    hmma(acc[mt][nt], ah[mt], bh[nt]);
                    hmma(acc[mt][nt], al[mt], bh[nt]);
                    hmma(acc[mt][nt], ah[mt], bl[nt]);
                }
        }
        __syncthreads();
        if (c + 3 < 18) load_chunk(c + 3);
        CP_COMMIT();
    }

    // epilogue: t = relu(D + b1) -> hi/lo fp16 NHWC
#pragma unroll
    for (int mt = 0; mt < 4; mt++) {
        int m = wm * 64 + mt * 16 + (lane >> 2);
#pragma unroll
        for (int nt = 0; nt < 4; nt++) {
            int oc = oh * 128 + wn * 32 + nt * 8 + (lane & 3) * 2;
            float bb0 = __ldg(&b1[oc]), bb1 = __ldg(&b1[oc + 1]);
#pragma unroll
            for (int rh = 0; rh < 2; rh++) {
                int px = p0 + m + rh * 8;
                float t0 = fmaxf(acc[mt][nt][rh * 2 + 0] + bb0, 0.0f);
                float t1 = fmaxf(acc[mt][nt][rh * 2 + 1] + bb1, 0.0f);
                __half h0 = __float2half_rn(t0), h1 = __float2half_rn(t1);
                size_t o = ((size_t)b * HW + px) * 256 + oc;
                *(__half2*)&g_th[o] = __halves2half2(h0, h1);
                *(__half2*)&g_tl[o] = __halves2half2(
                    __float2half_rn(t0 - __half2float(h0)),
                    __float2half_rn(t1 - __half2float(h1)));
            }
        }
    }
}

// ---------------- conv2: 1x1 GEMM 256->64, fused featmul1, 2 CTA/SM ----------------
// grid (288, 1, 4), 256 thr. CTA 128px x 64oc, K = 8 chunks of 32.
// 3 stages x 24KB = 73728 dyn. Stage: Ah@0 Al@8192 Bh@16384 Bl@20480.
__global__ __launch_bounds__(256, 2) void k_conv2(const float* __restrict__ b2) {
    extern __shared__ char sm[];
    uint32_t sb = smem_u32(sm);
    int tid = threadIdx.x, lane = tid & 31, wid = tid >> 5;
    int b = blockIdx.z;
    int p0 = blockIdx.x * 128;
    int wm = wid & 3, wn = wid >> 2;   // warp tile M32 x N32

    float acc[2][4][4];
#pragma unroll
    for (int i = 0; i < 2; i++)
#pragma unroll
        for (int j = 0; j < 4; j++)
#pragma unroll
            for (int k = 0; k < 4; k++) acc[i][j][k] = 0.0f;

    auto load_chunk = [&](int chunk) {
        uint32_t st = sb + (uint32_t)(chunk % 3) * 24576u;
        int seg = tid & 3;
#pragma unroll
        for (int rr = 0; rr < 2; rr++) {
            int row = (tid >> 2) + rr * 64;
            uint32_t d = swz64(row, seg * 16);
            size_t ap = ((size_t)b * HW + p0 + row) * 256 + chunk * 32 + seg * 8;
            cp16(st + d, g_th + ap, 16);
            cp16(st + 8192u + d, g_tl + ap, 16);
        }
        {
            int row = tid >> 2;   // 0..63
            uint32_t d = swz64(row, seg * 16);
            size_t wp = (size_t)row * 256 + chunk * 32 + seg * 8;
            cp16(st + 16384u + d, g_w2h + wp, 16);
            cp16(st + 20480u + d, g_w2l + wp, 16);
        }
    };

    load_chunk(0); CP_COMMIT();
    load_chunk(1); CP_COMMIT();
    load_chunk(2); CP_COMMIT();

    for (int c = 0; c < 8; c++) {
        CP_WAIT2();
        __syncthreads();
        uint32_t st = sb + (uint32_t)(c % 3) * 24576u;
#pragma unroll
        for (int k16 = 0; k16 < 2; k16++) {
            int kb = k16 * 32;
            uint32_t ah[2][4], al[2][4];
#pragma unroll
            for (int mt = 0; mt < 2; mt++) {
                int row = wm * 32 + mt * 16 + (lane & 15);
                int colb = kb + (lane >> 4) * 16;
                uint32_t d = swz64(row, colb);
                ldmx4(st + d, ah[mt]);
                ldmx4(st + 8192u + d, al[mt]);
            }
            uint32_t bh[4][2], bl[4][2];
#pragma unroll
            for (int ng = 0; ng < 2; ng++) {
                int row = wn * 32 + ng * 16 + ((lane >> 4) << 3) + (lane & 7);
                int colb = kb + ((lane >> 3) & 1) * 16;
                uint32_t d = swz64(row, colb);
                uint32_t r[4];
                ldmx4(st + 16384u + d, r);
                bh[ng * 2][0] = r[0]; bh[ng * 2][1] = r[1];
                bh[ng * 2 + 1][0] = r[2]; bh[ng * 2 + 1][1] = r[3];
                ldmx4(st + 20480u + d, r);
                bl[ng * 2][0] = r[0]; bl[ng * 2][1] = r[1];
                bl[ng * 2 + 1][0] = r[2]; bl[ng * 2 + 1][1] = r[3];
            }
#pragma unroll
            for (int mt = 0; mt < 2; mt++)
#pragma unroll
                for (int nt = 0; nt < 4; nt++) {
                    hmma(acc[mt][nt], ah[mt], bh[nt]);
                    hmma(acc[mt][nt], al[mt], bh[nt]);
                    hmma(acc[mt][nt], ah[mt], bl[nt]);
                }
        }
        __syncthreads();
        if (c + 3 < 8) load_chunk(c + 3);
        CP_COMMIT();
    }

    // epilogue: feat = relu((D + b2) * (1 + union_init)) -> fp32 NHWC
#pragma unroll
    for (int mt = 0; mt < 2; mt++) {
        int m = wm * 32 + mt * 16 + (lane >> 2);
#pragma unroll
        for (int nt = 0; nt < 4; nt++) {
            int oc = wn * 32 + nt * 8 + (lane & 3) * 2;
            float bb0 = __ldg(&b2[oc]), bb1 = __ldg(&b2[oc + 1]);
#pragma unroll
            for (int rh = 0; rh < 2; rh++) {
                int px = p0 + m + rh * 8;
                float u = g_union[b * HW + px];
                float s = 1.0f + u;
                float2 v;
                v.x = fmaxf((acc[mt][nt][rh * 2 + 0] + bb0) * s, 0.0f);
                v.y = fmaxf((acc[mt][nt][rh * 2 + 1] + bb1) * s, 0.0f);
                *(float2*)&g_feat[((size_t)b * HW + px) * 64 + oc] = v;
            }
        }
    }
}

// ---------------- point-in-polygon ----------------
__global__ __launch_bounds__(256) void k_pnp(int src) {
    __shared__ float verts[256];
    __shared__ float xint[8][132];
    __shared__ int cnt[8];
    const float* polys = src ? g_coarse : g_init;
    int poly = blockIdx.y;
    int rb = blockIdx.x * 8;
    int tid = threadIdx.x;
    verts[tid] = polys[poly * 256 + tid];
    if (tid < 8) cnt[tid] = 0;
    __syncthreads();
    for (int i = tid; i < 1024; i += 256) {
        int e = i & 127, r = i >> 7;
        float yy = (float)(rb + r);
        int e2 = (e + 1) & 127;
        float y1 = verts[2 * e + 1];
        float y2 = verts[2 * e2 + 1];
        if ((y1 > yy) != (y2 > yy)) {
            float x1 = verts[2 * e];
            float x2 = verts[2 * e2];
            float den = y2 - y1;
            if (fabsf(den) < 1e-9f) den = 1e-9f;
            float xi = x1 + (x2 - x1) * (yy - y1) / den;
            int s = atomicAdd(&cnt[r], 1);
            xint[r][s] = xi;
        }
    }
    __syncthreads();
    for (int i = tid; i < 1536; i += 256) {
        int r = i / 192;
        int xp = i - r * 192;
        int c = cnt[r];
        float fx = (float)xp;
        unsigned par = 0;
        for (int j = 0; j < c; j++) par ^= (fx < xint[r][j]) ? 1u : 0u;
        g_mask[(size_t)poly * HW + (rb + r) * WW + xp] = (float)par;
    }
}

// ---------------- mask_batch + union ----------------
__global__ void k_mb(const int* __restrict__ ct_num, float* __restrict__ mb) {
    int b = blockIdx.y;
    int px = blockIdx.x * 256 + threadIdx.x;
    int count = ct_num[b];
    int start = (b == 0) ? 0 : ct_num[b - 1];   // reference slicing quirk
    float u = 0.0f;
    for (int c = 0; c < 32; c++) {
        float v = (c < count) ? g_mask[(size_t)(start + c) * HW + px] : 0.0f;
        mb[(size_t)(b * 32 + c) * HW + px] = v;
        u = fmaxf(u, v);
    }
    g_union[b * HW + px] = u;
}

// ---------------- final: featmul pass 2 + NHWC -> NCHW ----------------
__global__ void k_final(float* __restrict__ out) {
    __shared__ float t[32][33];
    int b = blockIdx.z;
    int c0 = blockIdx.y * 32;
    int p0 = blockIdx.x * 32;
    int tx = threadIdx.x, ty = threadIdx.y;
#pragma unroll
    for (int i = 0; i < 32; i += 8) {
        int p = p0 + ty + i;
        float u = g_union[b * HW + p];
        float v = g_feat[((size_t)b * HW + p) * CIN + c0 + tx];
        t[ty + i][tx] = fmaxf(v * (1.0f + u), 0.0f);
    }
    __syncthreads();
#pragma unroll
    for (int i = 0; i < 32; i += 8)
        out[((size_t)b * CIN + c0 + ty + i) * HW + p0 + tx] = t[tx][ty + i];
}

// ---------------- bilinear sampling (NHWC) ----------------
__global__ __launch_bounds__(256) void k_sample(const int* __restrict__ ct_ind,
                                                const int* __restrict__ ct_img) {
    __shared__ float s_w[129][4];
    __shared__ int s_off[129][4];
    int n = blockIdx.x;
    int tid = threadIdx.x;
    int img = ct_img[n];
    if (tid < 129) {
        float ptx, pty;
        if (tid == 0) {
            int ind = ct_ind[n];
            ptx = (float)(ind % WW);
            pty = (float)(ind / WW);
        } else {
            ptx = g_init[(n * PPTS + tid - 1) * 2 + 0];
            pty = g_init[(n * PPTS + tid - 1) * 2 + 1];
        }
        float xs = ptx - 0.5f, ys = pty - 0.5f;
        float x0f = floorf(xs), y0f = floorf(ys);
        float wx = xs - x0f, wy = ys - y0f;
        int x0 = (int)x0f, y0 = (int)y0f;
#pragma unroll
        for (int k = 0; k < 4; k++) {
            int xi = x0 + (k & 1);
            int yi = y0 + (k >> 1);
            bool valid = (xi >= 0) && (xi < WW) && (yi >= 0) && (yi < HH);
            int xc = min(max(xi, 0), WW - 1);
            int yc = min(max(yi, 0), HH - 1);
            s_off[tid][k] = yc * WW + xc;
            float wxx = (k & 1) ? wx : (1.0f - wx);
            float wyy = (k >> 1) ? wy : (1.0f - wy);
            s_w[tid][k] = valid ? wxx * wyy : 0.0f;
        }
    }
    __syncthreads();
    const float* fb = g_feat + (size_t)img * HW * CIN;
    for (int i = tid; i < FPK; i += 256) {
        int pp = i >> 6;
        int c = i & 63;
        float v = s_w[pp][0] * fb[(size_t)s_off[pp][0] * CIN + c]
                + s_w[pp][1] * fb[(size_t)s_off[pp][1] * CIN + c]
                + s_w[pp][2] * fb[(size_t)s_off[pp][2] * CIN + c]
                + s_w[pp][3] * fb[(size_t)s_off[pp][3] * CIN + c];
        g_fp[(size_t)n * FPK + c * 129 + pp] = v;
    }
}

// ---------------- NT GEMMs for offsets (fp32, exact path) ----------------
template <int MODE>
__global__ __launch_bounds__(256) void k_gemm(const float* __restrict__ Bm,
                                              const float* __restrict__ bias,
                                              float* __restrict__ outc) {
    const int K = (MODE == 0) ? FPK : 512;
    const float* A = (MODE == 0) ? (const float*)g_fp : (const float*)g_tmp;
    __shared__ float sA[16][68];
    __shared__ float sB[16][68];
    int m0 = blockIdx.y * 64, n0 = blockIdx.x * 64;
    int tid = threadIdx.x;
    int tx = tid & 15, ty = tid >> 4;
    int kk = tid & 15, rr = tid >> 4;
    float acc[4][4];
#pragma unroll
    for (int i = 0; i < 4; i++)
#pragma unroll
        for (int j = 0; j < 4; j++) acc[i][j] = 0.0f;

    int kbeg = (MODE == 0) ? blockIdx.z * 688 : 0;
    int kend = (MODE == 0) ? kbeg + 688 : 512;
    for (int k0 = kbeg; k0 < kend; k0 += 16) {
        __syncthreads();
#pragma unroll
        for (int pass = 0; pass < 4; pass++) {
            int row = rr + pass * 16;
            sA[kk][row] = A[(size_t)(m0 + row) * K + k0 + kk];
            sB[kk][row] = Bm[(size_t)(n0 + row) * K + k0 + kk];
        }
        __syncthreads();
#pragma unroll
        for (int k2 = 0; k2 < 16; k2++) {
            float4 a4 = *(const float4*)&sA[k2][ty * 4];
            float4 b4 = *(const float4*)&sB[k2][tx * 4];
            acc[0][0] += a4.x * b4.x; acc[0][1] += a4.x * b4.y; acc[0][2] += a4.x * b4.z; acc[0][3] += a4.x * b4.w;
            acc[1][0] += a4.y * b4.x; acc[1][1] += a4.y * b4.y; acc[1][2] += a4.y * b4.z; acc[1][3] += a4.y * b4.w;
            acc[2][0] += a4.z * b4.x; acc[2][1] += a4.z * b4.y; acc[2][2] += a4.z * b4.z; acc[2][3] += a4.z * b4.w;
            acc[3][0] += a4.w * b4.x; acc[3][1] += a4.w * b4.y; acc[3][2] += a4.w * b4.z; acc[3][3] += a4.w * b4.w;
        }
    }
    if (MODE == 0) {
#pragma unroll
        for (int i = 0; i < 4; i++)
#pragma unroll
            for (int j = 0; j < 4; j++)
                g_part[((size_t)blockIdx.z * 128 + m0 + ty * 4 + i) * 512 + n0 + tx * 4 + j] = acc[i][j];
    } else {
#pragma unroll
        for (int i = 0; i < 4; i++) {
            int m = m0 + ty * 4 + i;
#pragma unroll
            for (int j = 0; j < 4; j++) {
                int nn = n0 + tx * 4 + j;
                float v = acc[i][j] + bias[nn];
                float cr = v * 4.0f + g_init[m * 256 + nn];
                g_coarse[m * 256 + nn] = cr;
                outc[m * 256 + nn] = cr * 4.0f;
            }
        }
    }
}

__global__ void k_reduce() {
    int i = blockIdx.x * 256 + threadIdx.x;
    float s = 0.0f;
#pragma unroll
    for (int p = 0; p < NSPLIT; p++) s += g_part[(size_t)p * 65536 + i];
    g_tmp[i] = s;
}

// ---------------- launcher ----------------
extern "C" void kernel_launch(void* const* d_in, const int* in_sizes, int n_in,
                              void* d_out, int out_size) {
    const float* wh     = (const float*)d_in[0];
    const float* cnn    = (const float*)d_in[1];
    const float* w1     = (const float*)d_in[2];
    const float* b1     = (const float*)d_in[3];
    const float* w2     = (const float*)d_in[4];
    const float* b2     = (const float*)d_in[5];
    const float* wpoly  = (const float*)d_in[6];
    const float* wfuse  = (const float*)d_in[7];
    const float* bfuse  = (const float*)d_in[8];
    const int*   ct_ind = (const int*)d_in[9];
    const int*   ct_img = (const int*)d_in[10];
    const int*   ct_num = (const int*)d_in[11];

    float* out        = (float*)d_out;
    float* out_init   = out + O_INIT;
    float* out_coarse = out + O_COARSE;
    float* out_mbi    = out + O_MBI;
    float* out_mbc    = out + O_MBC;
    float* out_feat   = out + O_FEAT;

    cudaFuncSetAttribute(k_conv1, cudaFuncAttributeMaxDynamicSharedMemorySize, 98304);
    cudaFuncSetAttribute(k_conv2, cudaFuncAttributeMaxDynamicSharedMemorySize, 73728);

    k_init<<<128, 128>>>(wh, ct_ind, ct_img, out_init);
    k_prep_x<<<dim3(1152, 2, 4), dim3(32, 8)>>>(cnn);
    k_prep_w<<<640, 256>>>(w1, w2);

    // init-mask path only needs g_init: run before convs so conv2 can fuse featmul1
    k_pnp<<<dim3(24, 64), 256>>>(0);
    k_mb<<<dim3(144, 4), 256>>>(ct_num, out_mbi);

    k_conv1<<<dim3(288, 2, 4), 256, 98304>>>(b1);
    k_conv2<<<dim3(288, 1, 4), 256, 73728>>>(b2);

    k_sample<<<128, 256>>>(ct_ind, ct_img);
    k_gemm<0><<<dim3(8, 2, NSPLIT), 256>>>(wpoly, nullptr, nullptr);
    k_reduce<<<256, 256>>>();
    k_gemm<1><<<dim3(4, 2), 256>>>(wfuse, bfuse, out_coarse);

    k_pnp<<<dim3(24, 64), 256>>>(1);
    k_mb<<<dim3(144, 4), 256>>>(ct_num, out_mbc);
    k_final<<<dim3(1152, 2, 4), dim3(32, 8)>>>(out_feat);
}

// round 5
// speedup vs baseline: 2.4237x; 1.0022x over previous
#include <cuda_runtime.h>
#include <cuda_fp16.h>
#include <cstdint>

// ---------------- problem constants ----------------
#define BATCH   4
#define CIN     64
#define HH      192
#define WW      192
#define HW      36864
#define NPOLY   128
#define PPTS    128
#define FPK     8256
#define NSPLIT  12

// output layout (floats)
#define O_INIT   0
#define O_COARSE 32768
#define O_MBI    65536
#define O_MBC    (65536 + 4718592)
#define O_FEAT   (65536 + 2*4718592)

// ---------------- device scratch ----------------
__device__ __half g_xh_h[BATCH * HW * CIN];
__device__ __half g_xh_l[BATCH * HW * CIN];
__device__ __half g_w1h[256 * 576];
__device__ __half g_w1l[256 * 576];
__device__ __half g_w2h[64 * 256];
__device__ __half g_w2l[64 * 256];
__device__ __half g_th[(size_t)BATCH * HW * 256];
__device__ __half g_tl[(size_t)BATCH * HW * 256];
__device__ float  g_feat[BATCH * HW * CIN];
__device__ float  g_mask[64 * HW];
__device__ float  g_union[BATCH * HW];
__device__ float  g_init[NPOLY * PPTS * 2];
__device__ float  g_coarse[NPOLY * PPTS * 2];
__device__ float  g_fp[NPOLY * FPK];
__device__ float  g_tmp[NPOLY * 512];
__device__ float  g_part[NSPLIT * NPOLY * 512];

// ---------------- helpers ----------------
__device__ __forceinline__ uint32_t smem_u32(const void* p) {
    uint32_t a;
    asm("{ .reg .u64 t; cvta.to.shared.u64 t, %1; cvt.u32.u64 %0, t; }" : "=r"(a) : "l"(p));
    return a;
}
__device__ __forceinline__ void cp16(uint32_t dst, const void* src, int sz) {
    asm volatile("cp.async.ca.shared.global [%0], [%1], 16, %2;" :: "r"(dst), "l"(src), "r"(sz));
}
#define CP_COMMIT() asm volatile("cp.async.commit_group;")
#define CP_WAIT2()  asm volatile("cp.async.wait_group 2;")
#define CP_WAIT1()  asm volatile("cp.async.wait_group 1;")
#define CP_WAIT0()  asm volatile("cp.async.wait_group 0;")
__device__ __forceinline__ void ldmx4(uint32_t addr, uint32_t* r) {
    asm volatile("ldmatrix.sync.aligned.m8n8.x4.shared.b16 {%0,%1,%2,%3}, [%4];"
        : "=r"(r[0]), "=r"(r[1]), "=r"(r[2]), "=r"(r[3]) : "r"(addr));
}
__device__ __forceinline__ void hmma(float* d, const uint32_t* a, const uint32_t* b) {
    asm volatile("mma.sync.aligned.m16n8k16.row.col.f32.f16.f16.f32 "
        "{%0,%1,%2,%3}, {%4,%5,%6,%7}, {%8,%9}, {%0,%1,%2,%3};"
        : "+f"(d[0]), "+f"(d[1]), "+f"(d[2]), "+f"(d[3])
        : "r"(a[0]), "r"(a[1]), "r"(a[2]), "r"(a[3]), "r"(b[0]), "r"(b[1]));
}
// 64B-row tile swizzle: conflict-free for 8-row ldmatrix phases
__device__ __forceinline__ uint32_t swz64(int row, int colb) {
    return (uint32_t)(row * 64 + (colb ^ (((row >> 1) & 3) << 4)));
}
__device__ __forceinline__ void split_store(__half* hp, __half* lp, float v) {
    __half h = __float2half_rn(v);
    *hp = h;
    *lp = __float2half_rn(v - __half2float(h));
}

// ---------------- K0: init polys (exact) ----------------
__global__ void k_init(const float* __restrict__ wh, const int* __restrict__ ct_ind,
                       const int* __restrict__ ct_img, float* __restrict__ out_init) {
    int n = blockIdx.x;
    int p = threadIdx.x;
    int ind = ct_ind[n];
    int img = ct_img[n];
    int cx = ind % WW;
    int cy = ind / WW;
    size_t base = (size_t)img * 256 * HW + (size_t)cy * WW + cx;
    float ox = wh[base + (size_t)(2 * p) * HW];
    float oy = wh[base + (size_t)(2 * p + 1) * HW];
    float ix = ox * 10.0f + (float)cx;
    float iy = oy * 10.0f + (float)cy;
    int o = (n * PPTS + p) * 2;
    g_init[o + 0] = ix;
    g_init[o + 1] = iy;
    out_init[o + 0] = ix * 4.0f;
    out_init[o + 1] = iy * 4.0f;
}

// ---------------- prep: NCHW -> NHWC + fp16 hi/lo split ----------------
__global__ void k_prep_x(const float* __restrict__ x) {
    __shared__ float t[32][33];
    int b = blockIdx.z;
    int c0 = blockIdx.y * 32;
    int p0 = blockIdx.x * 32;
    int tx = threadIdx.x, ty = threadIdx.y;
#pragma unroll
    for (int i = 0; i < 32; i += 8)
        t[ty + i][tx] = x[((size_t)b * CIN + c0 + ty + i) * HW + p0 + tx];
    __syncthreads();
#pragma unroll
    for (int i = 0; i < 32; i += 8) {
        size_t o = ((size_t)b * HW + p0 + ty + i) * CIN + c0 + tx;
        split_store(&g_xh_h[o], &g_xh_l[o], t[tx][ty + i]);
    }
}

// ---------------- prep: weights reorder + split ----------------
__global__ void k_prep_w(const float* __restrict__ w1, const float* __restrict__ w2) {
    int i = blockIdx.x * 256 + threadIdx.x;
    if (i < 147456) {
        int oc = i / 576, k = i - oc * 576;
        int tap = k >> 6, ic = k & 63;
        split_store(&g_w1h[i], &g_w1l[i], w1[(oc * 64 + ic) * 9 + tap]);
    } else {
        int j = i - 147456;
        split_store(&g_w2h[j], &g_w2l[j], w2[j]);
    }
}

// ---------------- conv1: implicit GEMM, fp16-split 3-MMA, 2 CTA/SM ----------------
// grid (288, 2, 4), 256 thr. CTA 128px x 128oc, K = 18 chunks of 32 (half-taps).
// 3 stages x 32KB. One __syncthreads per chunk; loads issued before compute.
__global__ __launch_bounds__(256, 2) void k_conv1(const float* __restrict__ b1) {
    extern __shared__ char sm[];
    uint32_t sb = smem_u32(sm);
    int tid = threadIdx.x, lane = tid & 31, wid = tid >> 5;
    int b = blockIdx.z, oh = blockIdx.y;
    int p0 = blockIdx.x * 128;
    int wm = wid & 1, wn = wid >> 1;   // warp tile M64 x N32

    float acc[4][4][4];
#pragma unroll
    for (int i = 0; i < 4; i++)
#pragma unroll
        for (int j = 0; j < 4; j++)
#pragma unroll
            for (int k = 0; k < 4; k++) acc[i][j][k] = 0.0f;

    // hoisted per-thread load geometry
    int seg = tid & 3;
    int row0 = tid >> 2, row1 = row0 + 64;
    int py0 = (p0 + row0) / 192, px0 = (p0 + row0) - py0 * 192;
    int py1 = (p0 + row1) / 192, px1 = (p0 + row1) - py1 * 192;
    uint32_t d0 = swz64(row0, seg * 16);
    uint32_t d1 = swz64(row1, seg * 16);
    const __half* w1h_base = g_w1h + (size_t)(oh * 128 + row0) * 576 + seg * 8;
    const __half* w1l_base = g_w1l + (size_t)(oh * 128 + row0) * 576 + seg * 8;
    const __half* w1h_base1 = g_w1h + (size_t)(oh * 128 + row1) * 576 + seg * 8;
    const __half* w1l_base1 = g_w1l + (size_t)(oh * 128 + row1) * 576 + seg * 8;
    size_t xbase = (size_t)b * HW;

    auto load_chunk = [&](int chunk) {
        uint32_t st = sb + (uint32_t)(chunk % 3) * 32768u;
        int tap = chunk >> 1, half = chunk & 1;
        int dy = tap / 3 - 1, dx = tap % 3 - 1;
        int koff = half * 32 + seg * 8;
        // A rows
        {
            int ny = py0 + dy, nx = px0 + dx;
            bool v = ((unsigned)ny < 192u) && ((unsigned)nx < 192u);
            size_t np = (xbase + (v ? (ny * 192 + nx) : 0)) * 64 + koff;
            int sz = v ? 16 : 0;
            cp16(st + d0, g_xh_h + np, sz);
            cp16(st + 8192u + d0, g_xh_l + np, sz);
        }
        {
            int ny = py1 + dy, nx = px1 + dx;
            bool v = ((unsigned)ny < 192u) && ((unsigned)nx < 192u);
            size_t np = (xbase + (v ? (ny * 192 + nx) : 0)) * 64 + koff;
            int sz = v ? 16 : 0;
            cp16(st + d1, g_xh_h + np, sz);
            cp16(st + 8192u + d1, g_xh_l + np, sz);
        }
        // B rows
        size_t wo = (size_t)tap * 64 + koff - (size_t)seg * 8 + seg * 8; // = tap*64 + koff
        cp16(st + 16384u + d0, w1h_base + tap * 64 + half * 32, 16);
        cp16(st + 24576u + d0, w1l_base + tap * 64 + half * 32, 16);
        cp16(st + 16384u + d1, w1h_base1 + tap * 64 + half * 32, 16);
        cp16(st + 24576u + d1, w1l_base1 + tap * 64 + half * 32, 16);
        (void)wo;
    };

    load_chunk(0); CP_COMMIT();
    load_chunk(1); CP_COMMIT();

    for (int c = 0; c < 18; c++) {
        CP_WAIT1();
        __syncthreads();
        if (c + 2 < 18) load_chunk(c + 2);
        CP_COMMIT();
        uint32_t st = sb + (uint32_t)(c % 3) * 32768u;
#pragma unroll
        for (int k16 = 0; k16 < 2; k16++) {
            int kb = k16 * 32;
            uint32_t ah[4][4], al[4][4];
#pragma unroll
            for (int mt = 0; mt < 4; mt++) {
                int row = wm * 64 + mt * 16 + (lane & 15);
                int colb = kb + (lane >> 4) * 16;
                uint32_t d = swz64(row, colb);
                ldmx4(st + d, ah[mt]);
                ldmx4(st + 8192u + d, al[mt]);
            }
            uint32_t bh[4][2], bl[4][2];
#pragma unroll
            for (int ng = 0; ng < 2; ng++) {
                int row = wn * 32 + ng * 16 + ((lane >> 4) << 3) + (lane & 7);
                int colb = kb + ((lane >> 3) & 1) * 16;
                uint32_t d = swz64(row, colb);
                uint32_t r[4];
                ldmx4(st + 16384u + d, r);
                bh[ng * 2][0] = r[0]; bh[ng * 2][1] = r[1];
                bh[ng * 2 + 1][0] = r[2]; bh[ng * 2 + 1][1] = r[3];
                ldmx4(st + 24576u + d, r);
                bl[ng * 2][0] = r[0]; bl[ng * 2][1] = r[1];
                bl[ng * 2 + 1][0] = r[2]; bl[ng * 2 + 1][1] = r[3];
            }
#pragma unroll
            for (int mt = 0; mt < 4; mt++)
#pragma unroll
                for (int nt = 0; nt < 4; nt++) {
                    hmma(acc[mt][nt], ah[mt], bh[nt]);
                    hmma(acc[mt][nt], al[mt], bh[nt]);
                    hmma(acc[mt][nt], ah[mt], bl[nt]);
                }
        }
    }

    // epilogue: t = relu(D + b1) -> hi/lo fp16 NHWC
#pragma unroll
    for (int mt = 0; mt < 4; mt++) {
        int m = wm * 64 + mt * 16 + (lane >> 2);
#pragma unroll
        for (int nt = 0; nt < 4; nt++) {
            int oc = oh * 128 + wn * 32 + nt * 8 + (lane & 3) * 2;
            float bb0 = __ldg(&b1[oc]), bb1 = __ldg(&b1[oc + 1]);
#pragma unroll
            for (int rh = 0; rh < 2; rh++) {
                int px = p0 + m + rh * 8;
                float t0 = fmaxf(acc[mt][nt][rh * 2 + 0] + bb0, 0.0f);
                float t1 = fmaxf(acc[mt][nt][rh * 2 + 1] + bb1, 0.0f);
                __half h0 = __float2half_rn(t0), h1 = __float2half_rn(t1);
                size_t o = ((size_t)b * HW + px) * 256 + oc;
                *(__half2*)&g_th[o] = __halves2half2(h0, h1);
                *(__half2*)&g_tl[o] = __halves2half2(
                    __float2half_rn(t0 - __half2float(h0)),
                    __float2half_rn(t1 - __half2float(h1)));
            }
        }
    }
}

// ---------------- conv2: 1x1 GEMM 256->64, fused featmul1, 2 CTA/SM ----------------
// grid (288, 1, 4), 256 thr. CTA 128px x 64oc, K = 8 chunks of 32.
// 4 stages x 24KB = 98304 dyn. One sync per chunk, prefetch distance 3.
__global__ __launch_bounds__(256, 2) void k_conv2(const float* __restrict__ b2) {
    extern __shared__ char sm[];
    uint32_t sb = smem_u32(sm);
    int tid = threadIdx.x, lane = tid & 31, wid = tid >> 5;
    int b = blockIdx.z;
    int p0 = blockIdx.x * 128;
    int wm = wid & 3, wn = wid >> 2;   // warp tile M32 x N32

    float acc[2][4][4];
#pragma unroll
    for (int i = 0; i < 2; i++)
#pragma unroll
        for (int j = 0; j < 4; j++)
#pragma unroll
            for (int k = 0; k < 4; k++) acc[i][j][k] = 0.0f;

    int seg = tid & 3;
    int row0 = tid >> 2, row1 = row0 + 64;
    uint32_t d0 = swz64(row0, seg * 16);
    uint32_t d1 = swz64(row1, seg * 16);
    size_t a0 = ((size_t)b * HW + p0 + row0) * 256 + seg * 8;
    size_t a1 = ((size_t)b * HW + p0 + row1) * 256 + seg * 8;
    size_t wp0 = (size_t)row0 * 256 + seg * 8;

    auto load_chunk = [&](int chunk) {
        uint32_t st = sb + (uint32_t)(chunk & 3) * 24576u;
        size_t ko = (size_t)chunk * 32;
        cp16(st + d0, g_th + a0 + ko, 16);
        cp16(st + 8192u + d0, g_tl + a0 + ko, 16);
        cp16(st + d1, g_th + a1 + ko, 16);
        cp16(st + 8192u + d1, g_tl + a1 + ko, 16);
        cp16(st + 16384u + d0, g_w2h + wp0 + ko, 16);
        cp16(st + 20480u + d0, g_w2l + wp0 + ko, 16);
    };

    load_chunk(0); CP_COMMIT();
    load_chunk(1); CP_COMMIT();
    load_chunk(2); CP_COMMIT();

    for (int c = 0; c < 8; c++) {
        CP_WAIT2();
        __syncthreads();
        if (c + 3 < 8) load_chunk(c + 3);
        CP_COMMIT();
        uint32_t st = sb + (uint32_t)(c & 3) * 24576u;
#pragma unroll
        for (int k16 = 0; k16 < 2; k16++) {
            int kb = k16 * 32;
            uint32_t ah[2][4], al[2][4];
#pragma unroll
            for (int mt = 0; mt < 2; mt++) {
                int row = wm * 32 + mt * 16 + (lane & 15);
                int colb = kb + (lane >> 4) * 16;
                uint32_t d = swz64(row, colb);
                ldmx4(st + d, ah[mt]);
                ldmx4(st + 8192u + d, al[mt]);
            }
            uint32_t bh[4][2], bl[4][2];
#pragma unroll
            for (int ng = 0; ng < 2; ng++) {
                int row = wn * 32 + ng * 16 + ((lane >> 4) << 3) + (lane & 7);
                int colb = kb + ((lane >> 3) & 1) * 16;
                uint32_t d = swz64(row, colb);
                uint32_t r[4];
                ldmx4(st + 16384u + d, r);
                bh[ng * 2][0] = r[0]; bh[ng * 2][1] = r[1];
                bh[ng * 2 + 1][0] = r[2]; bh[ng * 2 + 1][1] = r[3];
                ldmx4(st + 20480u + d, r);
                bl[ng * 2][0] = r[0]; bl[ng * 2][1] = r[1];
                bl[ng * 2 + 1][0] = r[2]; bl[ng * 2 + 1][1] = r[3];
            }
#pragma unroll
            for (int mt = 0; mt < 2; mt++)
#pragma unroll
                for (int nt = 0; nt < 4; nt++) {
                    hmma(acc[mt][nt], ah[mt], bh[nt]);
                    hmma(acc[mt][nt], al[mt], bh[nt]);
                    hmma(acc[mt][nt], ah[mt], bl[nt]);
                }
        }
    }

    // epilogue: feat = relu((D + b2) * (1 + union_init)) -> fp32 NHWC
#pragma unroll
    for (int mt = 0; mt < 2; mt++) {
        int m = wm * 32 + mt * 16 + (lane >> 2);
#pragma unroll
        for (int nt = 0; nt < 4; nt++) {
            int oc = wn * 32 + nt * 8 + (lane & 3) * 2;
            float bb0 = __ldg(&b2[oc]), bb1 = __ldg(&b2[oc + 1]);
#pragma unroll
            for (int rh = 0; rh < 2; rh++) {
                int px = p0 + m + rh * 8;
                float u = g_union[b * HW + px];
                float s = 1.0f + u;
                float2 v;
                v.x = fmaxf((acc[mt][nt][rh * 2 + 0] + bb0) * s, 0.0f);
                v.y = fmaxf((acc[mt][nt][rh * 2 + 1] + bb1) * s, 0.0f);
                *(float2*)&g_feat[((size_t)b * HW + px) * 64 + oc] = v;
            }
        }
    }
}

// ---------------- point-in-polygon ----------------
__global__ __launch_bounds__(256) void k_pnp(int src) {
    __shared__ float verts[256];
    __shared__ float xint[8][132];
    __shared__ int cnt[8];
    const float* polys = src ? g_coarse : g_init;
    int poly = blockIdx.y;
    int rb = blockIdx.x * 8;
    int tid = threadIdx.x;
    verts[tid] = polys[poly * 256 + tid];
    if (tid < 8) cnt[tid] = 0;
    __syncthreads();
    for (int i = tid; i < 1024; i += 256) {
        int e = i & 127, r = i >> 7;
        float yy = (float)(rb + r);
        int e2 = (e + 1) & 127;
        float y1 = verts[2 * e + 1];
        float y2 = verts[2 * e2 + 1];
        if ((y1 > yy) != (y2 > yy)) {
            float x1 = verts[2 * e];
            float x2 = verts[2 * e2];
            float den = y2 - y1;
            if (fabsf(den) < 1e-9f) den = 1e-9f;
            float xi = x1 + (x2 - x1) * (yy - y1) / den;
            int s = atomicAdd(&cnt[r], 1);
            xint[r][s] = xi;
        }
    }
    __syncthreads();
    for (int i = tid; i < 1536; i += 256) {
        int r = i / 192;
        int xp = i - r * 192;
        int c = cnt[r];
        float fx = (float)xp;
        unsigned par = 0;
        for (int j = 0; j < c; j++) par ^= (fx < xint[r][j]) ? 1u : 0u;
        g_mask[(size_t)poly * HW + (rb + r) * WW + xp] = (float)par;
    }
}

// ---------------- mask_batch + union ----------------
__global__ void k_mb(const int* __restrict__ ct_num, float* __restrict__ mb) {
    int b = blockIdx.y;
    int px = blockIdx.x * 256 + threadIdx.x;
    int count = ct_num[b];
    int start = (b == 0) ? 0 : ct_num[b - 1];   // reference slicing quirk
    float u = 0.0f;
    for (int c = 0; c < 32; c++) {
        float v = (c < count) ? g_mask[(size_t)(start + c) * HW + px] : 0.0f;
        mb[(size_t)(b * 32 + c) * HW + px] = v;
        u = fmaxf(u, v);
    }
    g_union[b * HW + px] = u;
}

// ---------------- final: featmul pass 2 + NHWC -> NCHW ----------------
__global__ void k_final(float* __restrict__ out) {
    __shared__ float t[32][33];
    int b = blockIdx.z;
    int c0 = blockIdx.y * 32;
    int p0 = blockIdx.x * 32;
    int tx = threadIdx.x, ty = threadIdx.y;
#pragma unroll
    for (int i = 0; i < 32; i += 8) {
        int p = p0 + ty + i;
        float u = g_union[b * HW + p];
        float v = g_feat[((size_t)b * HW + p) * CIN + c0 + tx];
        t[ty + i][tx] = fmaxf(v * (1.0f + u), 0.0f);
    }
    __syncthreads();
#pragma unroll
    for (int i = 0; i < 32; i += 8)
        out[((size_t)b * CIN + c0 + ty + i) * HW + p0 + tx] = t[tx][ty + i];
}

// ---------------- bilinear sampling (NHWC) ----------------
__global__ __launch_bounds__(256) void k_sample(const int* __restrict__ ct_ind,
                                                const int* __restrict__ ct_img) {
    __shared__ float s_w[129][4];
    __shared__ int s_off[129][4];
    int n = blockIdx.x;
    int tid = threadIdx.x;
    int img = ct_img[n];
    if (tid < 129) {
        float ptx, pty;
        if (tid == 0) {
            int ind = ct_ind[n];
            ptx = (float)(ind % WW);
            pty = (float)(ind / WW);
        } else {
            ptx = g_init[(n * PPTS + tid - 1) * 2 + 0];
            pty = g_init[(n * PPTS + tid - 1) * 2 + 1];
        }
        float xs = ptx - 0.5f, ys = pty - 0.5f;
        float x0f = floorf(xs), y0f = floorf(ys);
        float wx = xs - x0f, wy = ys - y0f;
        int x0 = (int)x0f, y0 = (int)y0f;
#pragma unroll
        for (int k = 0; k < 4; k++) {
            int xi = x0 + (k & 1);
            int yi = y0 + (k >> 1);
            bool valid = (xi >= 0) && (xi < WW) && (yi >= 0) && (yi < HH);
            int xc = min(max(xi, 0), WW - 1);
            int yc = min(max(yi, 0), HH - 1);
            s_off[tid][k] = yc * WW + xc;
            float wxx = (k & 1) ? wx : (1.0f - wx);
            float wyy = (k >> 1) ? wy : (1.0f - wy);
            s_w[tid][k] = valid ? wxx * wyy : 0.0f;
        }
    }
    __syncthreads();
    const float* fb = g_feat + (size_t)img * HW * CIN;
    for (int i = tid; i < FPK; i += 256) {
        int pp = i >> 6;
        int c = i & 63;
        float v = s_w[pp][0] * fb[(size_t)s_off[pp][0] * CIN + c]
                + s_w[pp][1] * fb[(size_t)s_off[pp][1] * CIN + c]
                + s_w[pp][2] * fb[(size_t)s_off[pp][2] * CIN + c]
                + s_w[pp][3] * fb[(size_t)s_off[pp][3] * CIN + c];
        g_fp[(size_t)n * FPK + c * 129 + pp] = v;
    }
}

// ---------------- NT GEMMs for offsets (fp32, exact path) ----------------
template <int MODE>
__global__ __launch_bounds__(256) void k_gemm(const float* __restrict__ Bm,
                                              const float* __restrict__ bias,
                                              float* __restrict__ outc) {
    const int K = (MODE == 0) ? FPK : 512;
    const float* A = (MODE == 0) ? (const float*)g_fp : (const float*)g_tmp;
    __shared__ float sA[16][68];
    __shared__ float sB[16][68];
    int m0 = blockIdx.y * 64, n0 = blockIdx.x * 64;
    int tid = threadIdx.x;
    int tx = tid & 15, ty = tid >> 4;
    int kk = tid & 15, rr = tid >> 4;
    float acc[4][4];
#pragma unroll
    for (int i = 0; i < 4; i++)
#pragma unroll
        for (int j = 0; j < 4; j++) acc[i][j] = 0.0f;

    int kbeg = (MODE == 0) ? blockIdx.z * 688 : 0;
    int kend = (MODE == 0) ? kbeg + 688 : 512;
    for (int k0 = kbeg; k0 < kend; k0 += 16) {
        __syncthreads();
#pragma unroll
        for (int pass = 0; pass < 4; pass++) {
            int row = rr + pass * 16;
            sA[kk][row] = A[(size_t)(m0 + row) * K + k0 + kk];
            sB[kk][row] = Bm[(size_t)(n0 + row) * K + k0 + kk];
        }
        __syncthreads();
#pragma unroll
        for (int k2 = 0; k2 < 16; k2++) {
            float4 a4 = *(const float4*)&sA[k2][ty * 4];
            float4 b4 = *(const float4*)&sB[k2][tx * 4];
            acc[0][0] += a4.x * b4.x; acc[0][1] += a4.x * b4.y; acc[0][2] += a4.x * b4.z; acc[0][3] += a4.x * b4.w;
            acc[1][0] += a4.y * b4.x; acc[1][1] += a4.y * b4.y; acc[1][2] += a4.y * b4.z; acc[1][3] += a4.y * b4.w;
            acc[2][0] += a4.z * b4.x; acc[2][1] += a4.z * b4.y; acc[2][2] += a4.z * b4.z; acc[2][3] += a4.z * b4.w;
            acc[3][0] += a4.w * b4.x; acc[3][1] += a4.w * b4.y; acc[3][2] += a4.w * b4.z; acc[3][3] += a4.w * b4.w;
        }
    }
    if (MODE == 0) {
#pragma unroll
        for (int i = 0; i < 4; i++)
#pragma unroll
            for (int j = 0; j < 4; j++)
                g_part[((size_t)blockIdx.z * 128 + m0 + ty * 4 + i) * 512 + n0 + tx * 4 + j] = acc[i][j];
    } else {
#pragma unroll
        for (int i = 0; i < 4; i++) {
            int m = m0 + ty * 4 + i;
#pragma unroll
            for (int j = 0; j < 4; j++) {
                int nn = n0 + tx * 4 + j;
                float v = acc[i][j] + bias[nn];
                float cr = v * 4.0f + g_init[m * 256 + nn];
                g_coarse[m * 256 + nn] = cr;
                outc[m * 256 + nn] = cr * 4.0f;
            }
        }
    }
}

__global__ void k_reduce() {
    int i = blockIdx.x * 256 + threadIdx.x;
    float s = 0.0f;
#pragma unroll
    for (int p = 0; p < NSPLIT; p++) s += g_part[(size_t)p * 65536 + i];
    g_tmp[i] = s;
}

// ---------------- launcher ----------------
extern "C" void kernel_launch(void* const* d_in, const int* in_sizes, int n_in,
                              void* d_out, int out_size) {
    const float* wh     = (const float*)d_in[0];
    const float* cnn    = (const float*)d_in[1];
    const float* w1     = (const float*)d_in[2];
    const float* b1     = (const float*)d_in[3];
    const float* w2     = (const float*)d_in[4];
    const float* b2     = (const float*)d_in[5];
    const float* wpoly  = (const float*)d_in[6];
    const float* wfuse  = (const float*)d_in[7];
    const float* bfuse  = (const float*)d_in[8];
    const int*   ct_ind = (const int*)d_in[9];
    const int*   ct_img = (const int*)d_in[10];
    const int*   ct_num = (const int*)d_in[11];

    float* out        = (float*)d_out;
    float* out_init   = out + O_INIT;
    float* out_coarse = out + O_COARSE;
    float* out_mbi    = out + O_MBI;
    float* out_mbc    = out + O_MBC;
    float* out_feat   = out + O_FEAT;

    cudaFuncSetAttribute(k_conv1, cudaFuncAttributeMaxDynamicSharedMemorySize, 98304);
    cudaFuncSetAttribute(k_conv2, cudaFuncAttributeMaxDynamicSharedMemorySize, 98304);

    k_init<<<128, 128>>>(wh, ct_ind, ct_img, out_init);
    k_prep_x<<<dim3(1152, 2, 4), dim3(32, 8)>>>(cnn);
    k_prep_w<<<640, 256>>>(w1, w2);

    // init-mask path only needs g_init: run before convs so conv2 can fuse featmul1
    k_pnp<<<dim3(24, 64), 256>>>(0);
    k_mb<<<dim3(144, 4), 256>>>(ct_num, out_mbi);

    k_conv1<<<dim3(288, 2, 4), 256, 98304>>>(b1);
    k_conv2<<<dim3(288, 1, 4), 256, 98304>>>(b2);

    k_sample<<<128, 256>>>(ct_ind, ct_img);
    k_gemm<0><<<dim3(8, 2, NSPLIT), 256>>>(wpoly, nullptr, nullptr);
    k_reduce<<<256, 256>>>();
    k_gemm<1><<<dim3(4, 2), 256>>>(wfuse, bfuse, out_coarse);

    k_pnp<<<dim3(24, 64), 256>>>(1);
    k_mb<<<dim3(144, 4), 256>>>(ct_num, out_mbc);
    k_final<<<dim3(1152, 2, 4), dim3(32, 8)>>>(out_feat);
}

// round 8
// speedup vs baseline: 2.4901x; 1.0274x over previous
#include <cuda_runtime.h>
#include <cuda_fp16.h>
#include <cstdint>

// ---------------- problem constants ----------------
#define BATCH   4
#define CIN     64
#define HH      192
#define WW      192
#define HW      36864
#define NPOLY   128
#define PPTS    128
#define FPK     8256
#define NSPLIT  12

// output layout (floats)
#define O_INIT   0
#define O_COARSE 32768
#define O_MBI    65536
#define O_MBC    (65536 + 4718592)
#define O_FEAT   (65536 + 2*4718592)

// conv1 A-slab geometry (32x4 pixel patch, 1-px halo)
#define SLAB_W  34
#define SLAB_H  6
#define SLAB_PX 204            // 6*34
#define SLAB_ZERO 204          // zero row index
#define SLAB_BYTES 26240u      // 205 rows * 128 B
#define B_OFF   52480u         // 2 * SLAB_BYTES
#define B_STAGE 16384u
#define CONV1_SMEM (52480 + 3*16384)   // 101632

// ---------------- device scratch ----------------
__device__ __half g_xh_h[BATCH * HW * CIN];
__device__ __half g_xh_l[BATCH * HW * CIN];
__device__ __half g_w1h[256 * 576];
__device__ __half g_w1l[256 * 576];
__device__ __half g_w2h[64 * 256];
__device__ __half g_w2l[64 * 256];
__device__ __half g_th[(size_t)BATCH * HW * 256];
__device__ __half g_tl[(size_t)BATCH * HW * 256];
__device__ float  g_feat[BATCH * HW * CIN];
__device__ float  g_mask[64 * HW];
__device__ float  g_union[BATCH * HW];
__device__ float  g_init[NPOLY * PPTS * 2];
__device__ float  g_coarse[NPOLY * PPTS * 2];
__device__ float  g_fp[NPOLY * FPK];
__device__ float  g_tmp[NPOLY * 512];
__device__ float  g_part[NSPLIT * NPOLY * 512];

// ---------------- helpers ----------------
__device__ __forceinline__ uint32_t smem_u32(const void* p) {
    uint32_t a;
    asm("{ .reg .u64 t; cvta.to.shared.u64 t, %1; cvt.u32.u64 %0, t; }" : "=r"(a) : "l"(p));
    return a;
}
__device__ __forceinline__ void cp16(uint32_t dst, const void* src, int sz) {
    asm volatile("cp.async.ca.shared.global [%0], [%1], 16, %2;" :: "r"(dst), "l"(src), "r"(sz));
}
#define CP_COMMIT() asm volatile("cp.async.commit_group;")
#define CP_WAIT2()  asm volatile("cp.async.wait_group 2;")
#define CP_WAIT1()  asm volatile("cp.async.wait_group 1;")
__device__ __forceinline__ void ldmx4(uint32_t addr, uint32_t* r) {
    asm volatile("ldmatrix.sync.aligned.m8n8.x4.shared.b16 {%0,%1,%2,%3}, [%4];"
        : "=r"(r[0]), "=r"(r[1]), "=r"(r[2]), "=r"(r[3]) : "r"(addr));
}
__device__ __forceinline__ void hmma(float* d, const uint32_t* a, const uint32_t* b) {
    asm volatile("mma.sync.aligned.m16n8k16.row.col.f32.f16.f16.f32 "
        "{%0,%1,%2,%3}, {%4,%5,%6,%7}, {%8,%9}, {%0,%1,%2,%3};"
        : "+f"(d[0]), "+f"(d[1]), "+f"(d[2]), "+f"(d[3])
        : "r"(a[0]), "r"(a[1]), "r"(a[2]), "r"(a[3]), "r"(b[0]), "r"(b[1]));
}
// 64B-row tile swizzle (for B stages / conv2)
__device__ __forceinline__ uint32_t swz64(int row, int colb) {
    return (uint32_t)(row * 64 + (colb ^ (((row >> 1) & 3) << 4)));
}
// 128B-row slab swizzle
__device__ __forceinline__ uint32_t swz128(int row, int colb) {
    return (uint32_t)(row * 128 + (colb ^ ((row & 7) << 4)));
}
__device__ __forceinline__ void split_store(__half* hp, __half* lp, float v) {
    __half h = __float2half_rn(v);
    *hp = h;
    *lp = __float2half_rn(v - __half2float(h));
}

// ---------------- K0: init polys (exact) ----------------
__global__ void k_init(const float* __restrict__ wh, const int* __restrict__ ct_ind,
                       const int* __restrict__ ct_img, float* __restrict__ out_init) {
    int n = blockIdx.x;
    int p = threadIdx.x;
    int ind = ct_ind[n];
    int img = ct_img[n];
    int cx = ind % WW;
    int cy = ind / WW;
    size_t base = (size_t)img * 256 * HW + (size_t)cy * WW + cx;
    float ox = wh[base + (size_t)(2 * p) * HW];
    float oy = wh[base + (size_t)(2 * p + 1) * HW];
    float ix = ox * 10.0f + (float)cx;
    float iy = oy * 10.0f + (float)cy;
    int o = (n * PPTS + p) * 2;
    g_init[o + 0] = ix;
    g_init[o + 1] = iy;
    out_init[o + 0] = ix * 4.0f;
    out_init[o + 1] = iy * 4.0f;
}

// ---------------- prep: NCHW -> NHWC + fp16 hi/lo split ----------------
__global__ void k_prep_x(const float* __restrict__ x) {
    __shared__ float t[32][33];
    int b = blockIdx.z;
    int c0 = blockIdx.y * 32;
    int p0 = blockIdx.x * 32;
    int tx = threadIdx.x, ty = threadIdx.y;
#pragma unroll
    for (int i = 0; i < 32; i += 8)
        t[ty + i][tx] = x[((size_t)b * CIN + c0 + ty + i) * HW + p0 + tx];
    __syncthreads();
#pragma unroll
    for (int i = 0; i < 32; i += 8) {
        size_t o = ((size_t)b * HW + p0 + ty + i) * CIN + c0 + tx;
        split_store(&g_xh_h[o], &g_xh_l[o], t[tx][ty + i]);
    }
}

// ---------------- prep: weights reorder + split ----------------
__global__ void k_prep_w(const float* __restrict__ w1, const float* __restrict__ w2) {
    int i = blockIdx.x * 256 + threadIdx.x;
    if (i < 147456) {
        int oc = i / 576, k = i - oc * 576;
        int tap = k >> 6, ic = k & 63;
        split_store(&g_w1h[i], &g_w1l[i], w1[(oc * 64 + ic) * 9 + tap]);
    } else {
        int j = i - 147456;
        split_store(&g_w2h[j], &g_w2l[j], w2[j]);
    }
}

// ---------------- conv1: implicit GEMM, 3-term split, resident A slab ----------------
// grid (288, 2, 4), 256 thr. CTA = 32x4 px patch x 128 oc, K = 18 chunks of 32.
// SMEM: Ah slab [0,26240), Al slab [26240,52480), B 3 stages x 16KB @52480.
// Pipeline: prologue commits chunks 0,1; loop: WAIT1 (chunk c ready) -> sync
// (stage (c+2)%3's readers from iter c-1 done) -> issue c+2 -> compute c.
__global__ __launch_bounds__(256, 2) void k_conv1(const float* __restrict__ b1) {
    extern __shared__ char sm[];
    uint32_t sb = smem_u32(sm);
    int tid = threadIdx.x, lane = tid & 31, wid = tid >> 5;
    int b = blockIdx.z, oh = blockIdx.y;
    int px0 = (blockIdx.x % 6) * 32;
    int py0 = (blockIdx.x / 6) * 4;
    int wm = wid & 1, wn = wid >> 1;   // warp tile M64 x N32

    float acc[4][4][4];
#pragma unroll
    for (int i = 0; i < 4; i++)
#pragma unroll
        for (int j = 0; j < 4; j++)
#pragma unroll
            for (int k = 0; k < 4; k++) acc[i][j][k] = 0.0f;

    size_t xbase = (size_t)b * HW;

    // per-lane A-fragment geometry (4 rows per thread: mt 0..3)
    int ry[4], rx[4], sbs[4];
#pragma unroll
    for (int mt = 0; mt < 4; mt++) {
        int r = wm * 64 + mt * 16 + (lane & 15);
        int pr = r >> 5, pc = r & 31;
        ry[mt] = py0 + pr;
        rx[mt] = px0 + pc;
        sbs[mt] = (pr + 1) * SLAB_W + pc + 1;
    }

    // B-load geometry
    int brow = tid >> 1;
    int bq0 = (tid & 1) * 2;
    const __half* w1h_p = g_w1h + (size_t)(oh * 128 + brow) * 576 + bq0 * 8;
    const __half* w1l_p = g_w1l + (size_t)(oh * 128 + brow) * 576 + bq0 * 8;
    uint32_t bd0 = swz64(brow, bq0 * 16);
    uint32_t bd1 = swz64(brow, bq0 * 16 + 16);

    auto load_b = [&](int chunk) {
        uint32_t st = sb + B_OFF + (uint32_t)(chunk % 3) * B_STAGE;
        int tap = chunk >> 1, half = chunk & 1;
        int wo = tap * 64 + half * 32;
        cp16(st + bd0, w1h_p + wo, 16);
        cp16(st + bd1, w1h_p + wo + 8, 16);
        cp16(st + 8192u + bd0, w1l_p + wo, 16);
        cp16(st + 8192u + bd1, w1l_p + wo + 8, 16);
    };

    // group 0: A slabs (hi+lo) + B chunk 0
    for (int i = tid; i < 205 * 8; i += 256) {
        int s = i >> 3, q = i & 7;
        uint32_t d = swz128(s, q * 16);
        int sz = 0;
        size_t np = 0;
        if (s < SLAB_PX) {
            int sy = s / SLAB_W, sx = s - sy * SLAB_W;
            int yy = py0 - 1 + sy, xx = px0 - 1 + sx;
            if ((unsigned)yy < 192u && (unsigned)xx < 192u) {
                np = (xbase + yy * 192 + xx) * 64 + q * 8;
                sz = 16;
            }
        }
        cp16(sb + d, g_xh_h + np, sz);
        cp16(sb + SLAB_BYTES + d, g_xh_l + np, sz);
    }
    load_b(0); CP_COMMIT();
    load_b(1); CP_COMMIT();

    for (int c = 0; c < 18; c++) {
        CP_WAIT1();
        __syncthreads();
        if (c + 2 < 18) load_b(c + 2);
        CP_COMMIT();

        int tap = c >> 1, half = c & 1;
        int dy = tap / 3 - 1, dx = tap % 3 - 1;
        // per-lane slab rows for this tap
        uint32_t sa[4];
#pragma unroll
        for (int mt = 0; mt < 4; mt++) {
            bool v = ((unsigned)(ry[mt] + dy) < 192u) && ((unsigned)(rx[mt] + dx) < 192u);
            sa[mt] = v ? (uint32_t)(sbs[mt] + dy * SLAB_W + dx) : (uint32_t)SLAB_ZERO;
        }
        uint32_t bst = sb + B_OFF + (uint32_t)(c % 3) * B_STAGE;
#pragma unroll
        for (int k16 = 0; k16 < 2; k16++) {
            int kb = k16 * 32;
            uint32_t ah[4][4], al[4][4];
#pragma unroll
            for (int mt = 0; mt < 4; mt++) {
                int colb = half * 64 + kb + (lane >> 4) * 16;
                uint32_t ad = swz128((int)sa[mt], colb);
                ldmx4(sb + ad, ah[mt]);
                ldmx4(sb + SLAB_BYTES + ad, al[mt]);
            }
            uint32_t bh[4][2], bl[4][2];
#pragma unroll
            for (int ng = 0; ng < 2; ng++) {
                int row = wn * 32 + ng * 16 + ((lane >> 4) << 3) + (lane & 7);
                int colb = kb + ((lane >> 3) & 1) * 16;
                uint32_t d = swz64(row, colb);
                uint32_t r[4];
                ldmx4(bst + d, r);
                bh[ng * 2][0] = r[0]; bh[ng * 2][1] = r[1];
                bh[ng * 2 + 1][0] = r[2]; bh[ng * 2 + 1][1] = r[3];
                ldmx4(bst + 8192u + d, r);
                bl[ng * 2][0] = r[0]; bl[ng * 2][1] = r[1];
                bl[ng * 2 + 1][0] = r[2]; bl[ng * 2 + 1][1] = r[3];
            }
#pragma unroll
            for (int mt = 0; mt < 4; mt++)
#pragma unroll
                for (int nt = 0; nt < 4; nt++) {
                    hmma(acc[mt][nt], ah[mt], bh[nt]);
                    hmma(acc[mt][nt], al[mt], bh[nt]);
                    hmma(acc[mt][nt], ah[mt], bl[nt]);
                }
        }
    }

    // epilogue: t = relu(D + b1) -> hi/lo fp16 NHWC
#pragma unroll
    for (int mt = 0; mt < 4; mt++) {
        int m = wm * 64 + mt * 16 + (lane >> 2);
#pragma unroll
        for (int nt = 0; nt < 4; nt++) {
            int oc = oh * 128 + wn * 32 + nt * 8 + (lane & 3) * 2;
            float bb0 = __ldg(&b1[oc]), bb1 = __ldg(&b1[oc + 1]);
#pragma unroll
            for (int rh = 0; rh < 2; rh++) {
                int mm = m + rh * 8;
                int px = (py0 + (mm >> 5)) * 192 + px0 + (mm & 31);
                float t0 = fmaxf(acc[mt][nt][rh * 2 + 0] + bb0, 0.0f);
                float t1 = fmaxf(acc[mt][nt][rh * 2 + 1] + bb1, 0.0f);
                __half h0 = __float2half_rn(t0), h1 = __float2half_rn(t1);
                size_t o = ((size_t)b * HW + px) * 256 + oc;
                *(__half2*)&g_th[o] = __halves2half2(h0, h1);
                *(__half2*)&g_tl[o] = __halves2half2(
                    __float2half_rn(t0 - __half2float(h0)),
                    __float2half_rn(t1 - __half2float(h1)));
            }
        }
    }
}

// ---------------- conv2: 1x1 GEMM 256->64, 3-term split, fused featmul1 ----------------
// grid (288, 1, 4), 256 thr. CTA 128px x 64oc, K = 8 chunks of 32.
// 4 stages x 24KB = 98304 dyn; prefetch distance 3 (safe: (c+3)&3 != c&3).
__global__ __launch_bounds__(256, 2) void k_conv2(const float* __restrict__ b2) {
    extern __shared__ char sm[];
    uint32_t sb = smem_u32(sm);
    int tid = threadIdx.x, lane = tid & 31, wid = tid >> 5;
    int b = blockIdx.z;
    int p0 = blockIdx.x * 128;
    int wm = wid & 3, wn = wid >> 2;   // warp tile M32 x N32

    float acc[2][4][4];
#pragma unroll
    for (int i = 0; i < 2; i++)
#pragma unroll
        for (int j = 0; j < 4; j++)
#pragma unroll
            for (int k = 0; k < 4; k++) acc[i][j][k] = 0.0f;

    int seg = tid & 3;
    int row0 = tid >> 2, row1 = row0 + 64;
    uint32_t d0 = swz64(row0, seg * 16);
    uint32_t d1 = swz64(row1, seg * 16);
    size_t a0 = ((size_t)b * HW + p0 + row0) * 256 + seg * 8;
    size_t a1 = ((size_t)b * HW + p0 + row1) * 256 + seg * 8;
    size_t wp0 = (size_t)row0 * 256 + seg * 8;

    auto load_chunk = [&](int chunk) {
        uint32_t st = sb + (uint32_t)(chunk & 3) * 24576u;
        size_t ko = (size_t)chunk * 32;
        cp16(st + d0, g_th + a0 + ko, 16);
        cp16(st + 8192u + d0, g_tl + a0 + ko, 16);
        cp16(st + d1, g_th + a1 + ko, 16);
        cp16(st + 8192u + d1, g_tl + a1 + ko, 16);
        cp16(st + 16384u + d0, g_w2h + wp0 + ko, 16);
        cp16(st + 20480u + d0, g_w2l + wp0 + ko, 16);
    };

    load_chunk(0); CP_COMMIT();
    load_chunk(1); CP_COMMIT();
    load_chunk(2); CP_COMMIT();

    for (int c = 0; c < 8; c++) {
        CP_WAIT2();
        __syncthreads();
        if (c + 3 < 8) load_chunk(c + 3);
        CP_COMMIT();
        uint32_t st = sb + (uint32_t)(c & 3) * 24576u;
#pragma unroll
        for (int k16 = 0; k16 < 2; k16++) {
            int kb = k16 * 32;
            uint32_t ah[2][4], al[2][4];
#pragma unroll
            for (int mt = 0; mt < 2; mt++) {
                int row = wm * 32 + mt * 16 + (lane & 15);
                int colb = kb + (lane >> 4) * 16;
                uint32_t d = swz64(row, colb);
                ldmx4(st + d, ah[mt]);
                ldmx4(st + 8192u + d, al[mt]);
            }
            uint32_t bh[4][2], bl[4][2];
#pragma unroll
            for (int ng = 0; ng < 2; ng++) {
                int row = wn * 32 + ng * 16 + ((lane >> 4) << 3) + (lane & 7);
                int colb = kb + ((lane >> 3) & 1) * 16;
                uint32_t d = swz64(row, colb);
                uint32_t r[4];
                ldmx4(st + 16384u + d, r);
                bh[ng * 2][0] = r[0]; bh[ng * 2][1] = r[1];
                bh[ng * 2 + 1][0] = r[2]; bh[ng * 2 + 1][1] = r[3];
                ldmx4(st + 20480u + d, r);
                bl[ng * 2][0] = r[0]; bl[ng * 2][1] = r[1];
                bl[ng * 2 + 1][0] = r[2]; bl[ng * 2 + 1][1] = r[3];
            }
#pragma unroll
            for (int mt = 0; mt < 2; mt++)
#pragma unroll
                for (int nt = 0; nt < 4; nt++) {
                    hmma(acc[mt][nt], ah[mt], bh[nt]);
                    hmma(acc[mt][nt], al[mt], bh[nt]);
                    hmma(acc[mt][nt], ah[mt], bl[nt]);
                }
        }
    }

    // epilogue: feat = relu((D + b2) * (1 + union_init)) -> fp32 NHWC
#pragma unroll
    for (int mt = 0; mt < 2; mt++) {
        int m = wm * 32 + mt * 16 + (lane >> 2);
#pragma unroll
        for (int nt = 0; nt < 4; nt++) {
            int oc = wn * 32 + nt * 8 + (lane & 3) * 2;
            float bb0 = __ldg(&b2[oc]), bb1 = __ldg(&b2[oc + 1]);
#pragma unroll
            for (int rh = 0; rh < 2; rh++) {
                int px = p0 + m + rh * 8;
                float u = g_union[b * HW + px];
                float s = 1.0f + u;
                float2 v;
                v.x = fmaxf((acc[mt][nt][rh * 2 + 0] + bb0) * s, 0.0f);
                v.y = fmaxf((acc[mt][nt][rh * 2 + 1] + bb1) * s, 0.0f);
                *(float2*)&g_feat[((size_t)b * HW + px) * 64 + oc] = v;
            }
        }
    }
}

// ---------------- point-in-polygon ----------------
__global__ __launch_bounds__(256) void k_pnp(int src) {
    __shared__ float verts[256];
    __shared__ float xint[8][132];
    __shared__ int cnt[8];
    const float* polys = src ? g_coarse : g_init;
    int poly = blockIdx.y;
    int rb = blockIdx.x * 8;
    int tid = threadIdx.x;
    verts[tid] = polys[poly * 256 + tid];
    if (tid < 8) cnt[tid] = 0;
    __syncthreads();
    for (int i = tid; i < 1024; i += 256) {
        int e = i & 127, r = i >> 7;
        float yy = (float)(rb + r);
        int e2 = (e + 1) & 127;
        float y1 = verts[2 * e + 1];
        float y2 = verts[2 * e2 + 1];
        if ((y1 > yy) != (y2 > yy)) {
            float x1 = verts[2 * e];
            float x2 = verts[2 * e2];
            float den = y2 - y1;
            if (fabsf(den) < 1e-9f) den = 1e-9f;
            float xi = x1 + (x2 - x1) * (yy - y1) / den;
            int s = atomicAdd(&cnt[r], 1);
            xint[r][s] = xi;
        }
    }
    __syncthreads();
    for (int i = tid; i < 1536; i += 256) {
        int r = i / 192;
        int xp = i - r * 192;
        int c = cnt[r];
        float fx = (float)xp;
        unsigned par = 0;
        for (int j = 0; j < c; j++) par ^= (fx < xint[r][j]) ? 1u : 0u;
        g_mask[(size_t)poly * HW + (rb + r) * WW + xp] = (float)par;
    }
}

// ---------------- mask_batch + union ----------------
__global__ void k_mb(const int* __restrict__ ct_num, float* __restrict__ mb) {
    int b = blockIdx.y;
    int px = blockIdx.x * 256 + threadIdx.x;
    int count = ct_num[b];
    int start = (b == 0) ? 0 : ct_num[b - 1];   // reference slicing quirk
    float u = 0.0f;
    for (int c = 0; c < 32; c++) {
        float v = (c < count) ? g_mask[(size_t)(start + c) * HW + px] : 0.0f;
        mb[(size_t)(b * 32 + c) * HW + px] = v;
        u = fmaxf(u, v);
    }
    g_union[b * HW + px] = u;
}

// ---------------- final: featmul pass 2 + NHWC -> NCHW ----------------
__global__ void k_final(float* __restrict__ out) {
    __shared__ float t[32][33];
    int b = blockIdx.z;
    int c0 = blockIdx.y * 32;
    int p0 = blockIdx.x * 32;
    int tx = threadIdx.x, ty = threadIdx.y;
#pragma unroll
    for (int i = 0; i < 32; i += 8) {
        int p = p0 + ty + i;
        float u = g_union[b * HW + p];
        float v = g_feat[((size_t)b * HW + p) * CIN + c0 + tx];
        t[ty + i][tx] = fmaxf(v * (1.0f + u), 0.0f);
    }
    __syncthreads();
#pragma unroll
    for (int i = 0; i < 32; i += 8)
        out[((size_t)b * CIN + c0 + ty + i) * HW + p0 + tx] = t[tx][ty + i];
}

// ---------------- bilinear sampling (NHWC) ----------------
__global__ __launch_bounds__(256) void k_sample(const int* __restrict__ ct_ind,
                                                const int* __restrict__ ct_img) {
    __shared__ float s_w[129][4];
    __shared__ int s_off[129][4];
    int n = blockIdx.x;
    int tid = threadIdx.x;
    int img = ct_img[n];
    if (tid < 129) {
        float ptx, pty;
        if (tid == 0) {
            int ind = ct_ind[n];
            ptx = (float)(ind % WW);
            pty = (float)(ind / WW);
        } else {
            ptx = g_init[(n * PPTS + tid - 1) * 2 + 0];
            pty = g_init[(n * PPTS + tid - 1) * 2 + 1];
        }
        float xs = ptx - 0.5f, ys = pty - 0.5f;
        float x0f = floorf(xs), y0f = floorf(ys);
        float wx = xs - x0f, wy = ys - y0f;
        int x0 = (int)x0f, y0 = (int)y0f;
#pragma unroll
        for (int k = 0; k < 4; k++) {
            int xi = x0 + (k & 1);
            int yi = y0 + (k >> 1);
            bool valid = (xi >= 0) && (xi < WW) && (yi >= 0) && (yi < HH);
            int xc = min(max(xi, 0), WW - 1);
            int yc = min(max(yi, 0), HH - 1);
            s_off[tid][k] = yc * WW + xc;
            float wxx = (k & 1) ? wx : (1.0f - wx);
            float wyy = (k >> 1) ? wy : (1.0f - wy);
            s_w[tid][k] = valid ? wxx * wyy : 0.0f;
        }
    }
    __syncthreads();
    const float* fb = g_feat + (size_t)img * HW * CIN;
    for (int i = tid; i < FPK; i += 256) {
        int pp = i >> 6;
        int c = i & 63;
        float v = s_w[pp][0] * fb[(size_t)s_off[pp][0] * CIN + c]
                + s_w[pp][1] * fb[(size_t)s_off[pp][1] * CIN + c]
                + s_w[pp][2] * fb[(size_t)s_off[pp][2] * CIN + c]
                + s_w[pp][3] * fb[(size_t)s_off[pp][3] * CIN + c];
        g_fp[(size_t)n * FPK + c * 129 + pp] = v;
    }
}

// ---------------- NT GEMMs for offsets (fp32, exact path) ----------------
template <int MODE>
__global__ __launch_bounds__(256) void k_gemm(const float* __restrict__ Bm,
                                              const float* __restrict__ bias,
                                              float* __restrict__ outc) {
    const int K = (MODE == 0) ? FPK : 512;
    const float* A = (MODE == 0) ? (const float*)g_fp : (const float*)g_tmp;
    __shared__ float sA[16][68];
    __shared__ float sB[16][68];
    int m0 = blockIdx.y * 64, n0 = blockIdx.x * 64;
    int tid = threadIdx.x;
    int tx = tid & 15, ty = tid >> 4;
    int kk = tid & 15, rr = tid >> 4;
    float acc[4][4];
#pragma unroll
    for (int i = 0; i < 4; i++)
#pragma unroll
        for (int j = 0; j < 4; j++) acc[i][j] = 0.0f;

    int kbeg = (MODE == 0) ? blockIdx.z * 688 : 0;
    int kend = (MODE == 0) ? kbeg + 688 : 512;
    for (int k0 = kbeg; k0 < kend; k0 += 16) {
        __syncthreads();
#pragma unroll
        for (int pass = 0; pass < 4; pass++) {
            int row = rr + pass * 16;
            sA[kk][row] = A[(size_t)(m0 + row) * K + k0 + kk];
            sB[kk][row] = Bm[(size_t)(n0 + row) * K + k0 + kk];
        }
        __syncthreads();
#pragma unroll
        for (int k2 = 0; k2 < 16; k2++) {
            float4 a4 = *(const float4*)&sA[k2][ty * 4];
            float4 b4 = *(const float4*)&sB[k2][tx * 4];
            acc[0][0] += a4.x * b4.x; acc[0][1] += a4.x * b4.y; acc[0][2] += a4.x * b4.z; acc[0][3] += a4.x * b4.w;
            acc[1][0] += a4.y * b4.x; acc[1][1] += a4.y * b4.y; acc[1][2] += a4.y * b4.z; acc[1][3] += a4.y * b4.w;
            acc[2][0] += a4.z * b4.x; acc[2][1] += a4.z * b4.y; acc[2][2] += a4.z * b4.z; acc[2][3] += a4.z * b4.w;
            acc[3][0] += a4.w * b4.x; acc[3][1] += a4.w * b4.y; acc[3][2] += a4.w * b4.z; acc[3][3] += a4.w * b4.w;
        }
    }
    if (MODE == 0) {
#pragma unroll
        for (int i = 0; i < 4; i++)
#pragma unroll
            for (int j = 0; j < 4; j++)
                g_part[((size_t)blockIdx.z * 128 + m0 + ty * 4 + i) * 512 + n0 + tx * 4 + j] = acc[i][j];
    } else {
#pragma unroll
        for (int i = 0; i < 4; i++) {
            int m = m0 + ty * 4 + i;
#pragma unroll
            for (int j = 0; j < 4; j++) {
                int nn = n0 + tx * 4 + j;
                float v = acc[i][j] + bias[nn];
                float cr = v * 4.0f + g_init[m * 256 + nn];
                g_coarse[m * 256 + nn] = cr;
                outc[m * 256 + nn] = cr * 4.0f;
            }
        }
    }
}

__global__ void k_reduce() {
    int i = blockIdx.x * 256 + threadIdx.x;
    float s = 0.0f;
#pragma unroll
    for (int p = 0; p < NSPLIT; p++) s += g_part[(size_t)p * 65536 + i];
    g_tmp[i] = s;
}

// ---------------- launcher ----------------
extern "C" void kernel_launch(void* const* d_in, const int* in_sizes, int n_in,
                              void* d_out, int out_size) {
    const float* wh     = (const float*)d_in[0];
    const float* cnn    = (const float*)d_in[1];
    const float* w1     = (const float*)d_in[2];
    const float* b1     = (const float*)d_in[3];
    const float* w2     = (const float*)d_in[4];
    const float* b2     = (const float*)d_in[5];
    const float* wpoly  = (const float*)d_in[6];
    const float* wfuse  = (const float*)d_in[7];
    const float* bfuse  = (const float*)d_in[8];
    const int*   ct_ind = (const int*)d_in[9];
    const int*   ct_img = (const int*)d_in[10];
    const int*   ct_num = (const int*)d_in[11];

    float* out        = (float*)d_out;
    float* out_init   = out + O_INIT;
    float* out_coarse = out + O_COARSE;
    float* out_mbi    = out + O_MBI;
    float* out_mbc    = out + O_MBC;
    float* out_feat   = out + O_FEAT;

    cudaFuncSetAttribute(k_conv1, cudaFuncAttributeMaxDynamicSharedMemorySize, CONV1_SMEM);
    cudaFuncSetAttribute(k_conv2, cudaFuncAttributeMaxDynamicSharedMemorySize, 98304);

    k_init<<<128, 128>>>(wh, ct_ind, ct_img, out_init);
    k_prep_x<<<dim3(1152, 2, 4), dim3(32, 8)>>>(cnn);
    k_prep_w<<<640, 256>>>(w1, w2);

    // init-mask path only needs g_init: run before convs so conv2 can fuse featmul1
    k_pnp<<<dim3(24, 64), 256>>>(0);
    k_mb<<<dim3(144, 4), 256>>>(ct_num, out_mbi);

    k_conv1<<<dim3(288, 2, 4), 256, CONV1_SMEM>>>(b1);
    k_conv2<<<dim3(288, 1, 4), 256, 98304>>>(b2);

    k_sample<<<128, 256>>>(ct_ind, ct_img);
    k_gemm<0><<<dim3(8, 2, NSPLIT), 256>>>(wpoly, nullptr, nullptr);
    k_reduce<<<256, 256>>>();
    k_gemm<1><<<dim3(4, 2), 256>>>(wfuse, bfuse, out_coarse);

    k_pnp<<<dim3(24, 64), 256>>>(1);
    k_mb<<<dim3(144, 4), 256>>>(ct_num, out_mbc);
    k_final<<<dim3(1152, 2, 4), dim3(32, 8)>>>(out_feat);
}

// round 9
// speedup vs baseline: 2.5063x; 1.0065x over previous
#include <cuda_runtime.h>
#include <cuda_fp16.h>
#include <cstdint>

// ---------------- problem constants ----------------
#define BATCH   4
#define CIN     64
#define HH      192
#define WW      192
#define HW      36864
#define NPOLY   128
#define PPTS    128
#define FPK     8256
#define NSPLIT  12

// output layout (floats)
#define O_INIT   0
#define O_COARSE 32768
#define O_MBI    65536
#define O_MBC    (65536 + 4718592)
#define O_FEAT   (65536 + 2*4718592)

// conv A-slab geometry (32x4 pixel patch, 1-px halo)
#define SLAB_W  34
#define SLAB_PX 204            // 6*34
#define SLAB_ZERO 204          // zero row index
#define SLAB_BYTES 26240u      // 205 rows * 128 B
#define B_OFF   52480u         // 2 * SLAB_BYTES
#define B_STAGE 32768u         // 256 oc x 32 k x (hi+lo)
#define CONV_SMEM (52480 + 3*32768)   // 150784
// phase-2 t staging reuses the dead A slab: T_HI @0, T_LO @16384

// ---------------- device scratch ----------------
__device__ __half g_xh_h[BATCH * HW * CIN];
__device__ __half g_xh_l[BATCH * HW * CIN];
__device__ __half g_w1h[256 * 576];
__device__ __half g_w1l[256 * 576];
__device__ __half g_w2h[64 * 256];
__device__ __half g_w2l[64 * 256];
__device__ float  g_feat[BATCH * HW * CIN];
__device__ float  g_mask[64 * HW];
__device__ float  g_union[BATCH * HW];
__device__ float  g_init[NPOLY * PPTS * 2];
__device__ float  g_coarse[NPOLY * PPTS * 2];
__device__ float  g_fp[NPOLY * FPK];
__device__ float  g_tmp[NPOLY * 512];
__device__ float  g_part[NSPLIT * NPOLY * 512];

// ---------------- helpers ----------------
__device__ __forceinline__ uint32_t smem_u32(const void* p) {
    uint32_t a;
    asm("{ .reg .u64 t; cvta.to.shared.u64 t, %1; cvt.u32.u64 %0, t; }" : "=r"(a) : "l"(p));
    return a;
}
__device__ __forceinline__ void cp16(uint32_t dst, const void* src, int sz) {
    asm volatile("cp.async.ca.shared.global [%0], [%1], 16, %2;" :: "r"(dst), "l"(src), "r"(sz));
}
#define CP_COMMIT() asm volatile("cp.async.commit_group;")
#define CP_WAIT1()  asm volatile("cp.async.wait_group 1;")
#define CP_WAIT0()  asm volatile("cp.async.wait_group 0;")
__device__ __forceinline__ void ldmx4(uint32_t addr, uint32_t* r) {
    asm volatile("ldmatrix.sync.aligned.m8n8.x4.shared.b16 {%0,%1,%2,%3}, [%4];"
        : "=r"(r[0]), "=r"(r[1]), "=r"(r[2]), "=r"(r[3]) : "r"(addr));
}
__device__ __forceinline__ void hmma(float* d, const uint32_t* a, const uint32_t* b) {
    asm volatile("mma.sync.aligned.m16n8k16.row.col.f32.f16.f16.f32 "
        "{%0,%1,%2,%3}, {%4,%5,%6,%7}, {%8,%9}, {%0,%1,%2,%3};"
        : "+f"(d[0]), "+f"(d[1]), "+f"(d[2]), "+f"(d[3])
        : "r"(a[0]), "r"(a[1]), "r"(a[2]), "r"(a[3]), "r"(b[0]), "r"(b[1]));
}
// 64B-row tile swizzle (B ring)
__device__ __forceinline__ uint32_t swz64(int row, int colb) {
    return (uint32_t)(row * 64 + (colb ^ (((row >> 1) & 3) << 4)));
}
// 128B-row swizzle (A slab, t-stage, w2 tile)
__device__ __forceinline__ uint32_t swz128(int row, int colb) {
    return (uint32_t)(row * 128 + (colb ^ ((row & 7) << 4)));
}
__device__ __forceinline__ void split_store(__half* hp, __half* lp, float v) {
    __half h = __float2half_rn(v);
    *hp = h;
    *lp = __float2half_rn(v - __half2float(h));
}

// ---------------- merged prep: weights + input transpose/split ----------------
__global__ __launch_bounds__(256) void k_prep(const float* __restrict__ x,
                                              const float* __restrict__ w1,
                                              const float* __restrict__ w2) {
    int bid = blockIdx.x;
    if (bid < 640) {
        int i = bid * 256 + threadIdx.x;
        if (i < 147456) {
            int oc = i / 576, k = i - oc * 576;
            int tap = k >> 6, ic = k & 63;
            split_store(&g_w1h[i], &g_w1l[i], w1[(oc * 64 + ic) * 9 + tap]);
        } else {
            int j = i - 147456;
            split_store(&g_w2h[j], &g_w2l[j], w2[j]);
        }
        return;
    }
    // input transpose: 9216 blocks, 32px x 32ch tiles
    __shared__ float t[32][33];
    int xb = bid - 640;
    int pxb = xb % 1152;
    int cy = (xb / 1152) & 1;
    int b = xb / 2304;
    int c0 = cy * 32;
    int p0 = pxb * 32;
    int tx = threadIdx.x & 31, ty = threadIdx.x >> 5;
#pragma unroll
    for (int i = 0; i < 32; i += 8)
        t[ty + i][tx] = x[((size_t)b * CIN + c0 + ty + i) * HW + p0 + tx];
    __syncthreads();
#pragma unroll
    for (int i = 0; i < 32; i += 8) {
        size_t o = ((size_t)b * HW + p0 + ty + i) * CIN + c0 + tx;
        split_store(&g_xh_h[o], &g_xh_l[o], t[tx][ty + i]);
    }
}

// ---------------- K0: init polys (exact) ----------------
__global__ void k_init(const float* __restrict__ wh, const int* __restrict__ ct_ind,
                       const int* __restrict__ ct_img, float* __restrict__ out_init) {
    int n = blockIdx.x;
    int p = threadIdx.x;
    int ind = ct_ind[n];
    int img = ct_img[n];
    int cx = ind % WW;
    int cy = ind / WW;
    size_t base = (size_t)img * 256 * HW + (size_t)cy * WW + cx;
    float ox = wh[base + (size_t)(2 * p) * HW];
    float oy = wh[base + (size_t)(2 * p + 1) * HW];
    float ix = ox * 10.0f + (float)cx;
    float iy = oy * 10.0f + (float)cy;
    int o = (n * PPTS + p) * 2;
    g_init[o + 0] = ix;
    g_init[o + 1] = iy;
    out_init[o + 0] = ix * 4.0f;
    out_init[o + 1] = iy * 4.0f;
}

// ---------------- fused conv1(3x3,64->256,relu) + conv2(1x1,256->64) ----------------
// grid (288, 4), 512 thr. CTA = 32x4 px patch, all 256 oc. 3-term fp16 split.
// conv1: warp tile M64 x N32 (wm=wid&1, wn=wid>>1), K = 18 chunks of 32.
// conv2: t staged per 64-oc piece into dead A slab; warp tile M32 x N16.
__global__ __launch_bounds__(512, 1) void k_conv(const float* __restrict__ b1,
                                                 const float* __restrict__ b2) {
    extern __shared__ char sm[];
    uint32_t sb = smem_u32(sm);
    int tid = threadIdx.x, lane = tid & 31, wid = tid >> 5;
    int b = blockIdx.y;
    int px0 = (blockIdx.x % 6) * 32;
    int py0 = (blockIdx.x / 6) * 4;
    int wm = wid & 1, wn = wid >> 1;      // conv1 tile

    float acc[4][4][4];
#pragma unroll
    for (int i = 0; i < 4; i++)
#pragma unroll
        for (int j = 0; j < 4; j++)
#pragma unroll
            for (int k = 0; k < 4; k++) acc[i][j][k] = 0.0f;

    size_t xbase = (size_t)b * HW;

    // per-lane A-fragment geometry
    int ry[4], rx[4], sbs[4];
#pragma unroll
    for (int mt = 0; mt < 4; mt++) {
        int r = wm * 64 + mt * 16 + (lane & 15);
        int pr = r >> 5, pc = r & 31;
        ry[mt] = py0 + pr;
        rx[mt] = px0 + pc;
        sbs[mt] = (pr + 1) * SLAB_W + pc + 1;
    }

    // B-load geometry (256 rows, 2 threads/row)
    int brow = tid >> 1;
    int bq0 = (tid & 1) * 2;
    const __half* w1h_p = g_w1h + (size_t)brow * 576 + bq0 * 8;
    const __half* w1l_p = g_w1l + (size_t)brow * 576 + bq0 * 8;
    uint32_t bd0 = swz64(brow, bq0 * 16);
    uint32_t bd1 = swz64(brow, bq0 * 16 + 16);

    auto load_b = [&](int chunk) {
        uint32_t st = sb + B_OFF + (uint32_t)(chunk % 3) * B_STAGE;
        int tap = chunk >> 1, half = chunk & 1;
        int wo = tap * 64 + half * 32;
        cp16(st + bd0, w1h_p + wo, 16);
        cp16(st + bd1, w1h_p + wo + 8, 16);
        cp16(st + 16384u + bd0, w1l_p + wo, 16);
        cp16(st + 16384u + bd1, w1l_p + wo + 8, 16);
    };

    // group 0: A slabs (hi+lo) + B chunk 0
    for (int i = tid; i < 205 * 8; i += 512) {
        int s = i >> 3, q = i & 7;
        uint32_t d = swz128(s, q * 16);
        int sz = 0;
        size_t np = 0;
        if (s < SLAB_PX) {
            int sy = s / SLAB_W, sx = s - sy * SLAB_W;
            int yy = py0 - 1 + sy, xx = px0 - 1 + sx;
            if ((unsigned)yy < 192u && (unsigned)xx < 192u) {
                np = (xbase + yy * 192 + xx) * 64 + q * 8;
                sz = 16;
            }
        }
        cp16(sb + d, g_xh_h + np, sz);
        cp16(sb + SLAB_BYTES + d, g_xh_l + np, sz);
    }
    load_b(0); CP_COMMIT();
    load_b(1); CP_COMMIT();

    // ---------------- conv1 main loop ----------------
    for (int c = 0; c < 18; c++) {
        CP_WAIT1();
        __syncthreads();
        if (c + 2 < 18) load_b(c + 2);
        CP_COMMIT();

        int tap = c >> 1, half = c & 1;
        int dy = tap / 3 - 1, dx = tap % 3 - 1;
        uint32_t sa[4];
#pragma unroll
        for (int mt = 0; mt < 4; mt++) {
            bool v = ((unsigned)(ry[mt] + dy) < 192u) && ((unsigned)(rx[mt] + dx) < 192u);
            sa[mt] = v ? (uint32_t)(sbs[mt] + dy * SLAB_W + dx) : (uint32_t)SLAB_ZERO;
        }
        uint32_t bst = sb + B_OFF + (uint32_t)(c % 3) * B_STAGE;
#pragma unroll
        for (int k16 = 0; k16 < 2; k16++) {
            int kb = k16 * 32;
            int acolb = half * 64 + kb + (lane >> 4) * 16;
            int brr = wn * 32 + ((lane >> 4) << 3) + (lane & 7);
            int bcolb = kb + ((lane >> 3) & 1) * 16;
            uint32_t bd_a = swz64(brr, bcolb);
            uint32_t bd_b = swz64(brr + 16, bcolb);

            uint32_t af[4][4];
#pragma unroll
            for (int mt = 0; mt < 4; mt++)
                ldmx4(sb + swz128((int)sa[mt], acolb), af[mt]);
            uint32_t bf[4][2];
            {
                uint32_t r[4];
                ldmx4(bst + bd_a, r);
                bf[0][0] = r[0]; bf[0][1] = r[1]; bf[1][0] = r[2]; bf[1][1] = r[3];
                ldmx4(bst + bd_b, r);
                bf[2][0] = r[0]; bf[2][1] = r[1]; bf[3][0] = r[2]; bf[3][1] = r[3];
            }
            // ah * bh
#pragma unroll
            for (int mt = 0; mt < 4; mt++)
#pragma unroll
                for (int nt = 0; nt < 4; nt++) hmma(acc[mt][nt], af[mt], bf[nt]);
            // al * bh
            uint32_t al[4][4];
#pragma unroll
            for (int mt = 0; mt < 4; mt++)
                ldmx4(sb + SLAB_BYTES + swz128((int)sa[mt], acolb), al[mt]);
#pragma unroll
            for (int mt = 0; mt < 4; mt++)
#pragma unroll
                for (int nt = 0; nt < 4; nt++) hmma(acc[mt][nt], al[mt], bf[nt]);
            // ah * bl (bl overwrites bf)
            {
                uint32_t r[4];
                ldmx4(bst + 16384u + bd_a, r);
                bf[0][0] = r[0]; bf[0][1] = r[1]; bf[1][0] = r[2]; bf[1][1] = r[3];
                ldmx4(bst + 16384u + bd_b, r);
                bf[2][0] = r[0]; bf[2][1] = r[1]; bf[3][0] = r[2]; bf[3][1] = r[3];
            }
#pragma unroll
            for (int mt = 0; mt < 4; mt++)
#pragma unroll
                for (int nt = 0; nt < 4; nt++) hmma(acc[mt][nt], af[mt], bf[nt]);
        }
    }

    // ---------------- conv2 phases (4 x 64-oc pieces) ----------------
    int wm2 = wid & 3, wn2 = wid >> 2;    // conv2 tile M32 x N16
    float acc2[2][2][4];
#pragma unroll
    for (int i = 0; i < 2; i++)
#pragma unroll
        for (int j = 0; j < 2; j++)
#pragma unroll
            for (int k = 0; k < 4; k++) acc2[i][j][k] = 0.0f;

    int w2row = tid >> 3, w2sg = tid & 7;
    uint32_t w2d = swz128(w2row, w2sg * 16);

    for (int ph = 0; ph < 4; ph++) {
        __syncthreads();   // conv1 B-ring reads / prior ph t-reads complete
        // stage w2 K-piece (hi @B_OFF, lo @B_OFF+8192)
        cp16(sb + B_OFF + w2d, g_w2h + (size_t)w2row * 256 + ph * 64 + w2sg * 8, 16);
        cp16(sb + B_OFF + 8192u + w2d, g_w2l + (size_t)w2row * 256 + ph * 64 + w2sg * 8, 16);
        CP_COMMIT();
        // owning warps write t piece (hi @0, lo @16384)
        if ((wn >> 1) == ph) {
            int ocbase = (wn & 1) * 32;
#pragma unroll
            for (int mt = 0; mt < 4; mt++) {
#pragma unroll
                for (int nt = 0; nt < 4; nt++) {
                    int oc_l = ocbase + nt * 8 + (lane & 3) * 2;
                    float bb0 = __ldg(&b1[ph * 64 + oc_l]);
                    float bb1 = __ldg(&b1[ph * 64 + oc_l + 1]);
#pragma unroll
                    for (int rh = 0; rh < 2; rh++) {
                        int row = wm * 64 + mt * 16 + (lane >> 2) + rh * 8;
                        float t0 = fmaxf(acc[mt][nt][rh * 2 + 0] + bb0, 0.0f);
                        float t1 = fmaxf(acc[mt][nt][rh * 2 + 1] + bb1, 0.0f);
                        __half h0 = __float2half_rn(t0), h1 = __float2half_rn(t1);
                        uint32_t ad = (uint32_t)(row * 128 + ((oc_l * 2) ^ ((row & 7) << 4)));
                        *(__half2*)(sm + ad) = __halves2half2(h0, h1);
                        *(__half2*)(sm + 16384 + ad) = __halves2half2(
                            __float2half_rn(t0 - __half2float(h0)),
                            __float2half_rn(t1 - __half2float(h1)));
                    }
                }
            }
        }
        CP_WAIT0();
        __syncthreads();
        // conv2 MMAs over this K-piece (K=64: 2 chunks x 2 k16)
#pragma unroll
        for (int kc = 0; kc < 2; kc++) {
#pragma unroll
            for (int k16 = 0; k16 < 2; k16++) {
                int kcb = kc * 64 + k16 * 32;
                uint32_t af2[2][4];
#pragma unroll
                for (int mt = 0; mt < 2; mt++) {
                    int row = wm2 * 32 + mt * 16 + (lane & 15);
                    int colb = kcb + (lane >> 4) * 16;
                    ldmx4(sb + swz128(row, colb), af2[mt]);
                }
                uint32_t bf2[2][2];
                int brow2 = wn2 * 16 + ((lane >> 4) << 3) + (lane & 7);
                int bcolb2 = kcb + ((lane >> 3) & 1) * 16;
                uint32_t bd2 = swz128(brow2, bcolb2);
                {
                    uint32_t r[4];
                    ldmx4(sb + B_OFF + bd2, r);
                    bf2[0][0] = r[0]; bf2[0][1] = r[1]; bf2[1][0] = r[2]; bf2[1][1] = r[3];
                }
#pragma unroll
                for (int mt = 0; mt < 2; mt++)
#pragma unroll
                    for (int nt = 0; nt < 2; nt++) hmma(acc2[mt][nt], af2[mt], bf2[nt]);
                uint32_t al2[2][4];
#pragma unroll
                for (int mt = 0; mt < 2; mt++) {
                    int row = wm2 * 32 + mt * 16 + (lane & 15);
                    int colb = kcb + (lane >> 4) * 16;
                    ldmx4(sb + 16384u + swz128(row, colb), al2[mt]);
                }
#pragma unroll
                for (int mt = 0; mt < 2; mt++)
#pragma unroll
                    for (int nt = 0; nt < 2; nt++) hmma(acc2[mt][nt], al2[mt], bf2[nt]);
                {
                    uint32_t r[4];
                    ldmx4(sb + B_OFF + 8192u + bd2, r);
                    bf2[0][0] = r[0]; bf2[0][1] = r[1]; bf2[1][0] = r[2]; bf2[1][1] = r[3];
                }
#pragma unroll
                for (int mt = 0; mt < 2; mt++)
#pragma unroll
                    for (int nt = 0; nt < 2; nt++) hmma(acc2[mt][nt], af2[mt], bf2[nt]);
            }
        }
    }

    // epilogue: feat = D2 + b2 (raw; union/relu applied by k_featmul)
#pragma unroll
    for (int mt = 0; mt < 2; mt++) {
#pragma unroll
        for (int nt = 0; nt < 2; nt++) {
            int oc2 = wn2 * 16 + nt * 8 + (lane & 3) * 2;
            float bb0 = __ldg(&b2[oc2]), bb1 = __ldg(&b2[oc2 + 1]);
#pragma unroll
            for (int rh = 0; rh < 2; rh++) {
                int m = wm2 * 32 + mt * 16 + (lane >> 2) + rh * 8;
                int px = (py0 + (m >> 5)) * 192 + px0 + (m & 31);
                float2 v;
                v.x = acc2[mt][nt][rh * 2 + 0] + bb0;
                v.y = acc2[mt][nt][rh * 2 + 1] + bb1;
                *(float2*)&g_feat[((size_t)b * HW + px) * 64 + oc2] = v;
            }
        }
    }
}

// ---------------- point-in-polygon ----------------
__global__ __launch_bounds__(256) void k_pnp(int src) {
    __shared__ float verts[256];
    __shared__ float xint[8][132];
    __shared__ int cnt[8];
    const float* polys = src ? g_coarse : g_init;
    int poly = blockIdx.y;
    int rb = blockIdx.x * 8;
    int tid = threadIdx.x;
    verts[tid] = polys[poly * 256 + tid];
    if (tid < 8) cnt[tid] = 0;
    __syncthreads();
    for (int i = tid; i < 1024; i += 256) {
        int e = i & 127, r = i >> 7;
        float yy = (float)(rb + r);
        int e2 = (e + 1) & 127;
        float y1 = verts[2 * e + 1];
        float y2 = verts[2 * e2 + 1];
        if ((y1 > yy) != (y2 > yy)) {
            float x1 = verts[2 * e];
            float x2 = verts[2 * e2];
            float den = y2 - y1;
            if (fabsf(den) < 1e-9f) den = 1e-9f;
            float xi = x1 + (x2 - x1) * (yy - y1) / den;
            int s = atomicAdd(&cnt[r], 1);
            xint[r][s] = xi;
        }
    }
    __syncthreads();
    for (int i = tid; i < 1536; i += 256) {
        int r = i / 192;
        int xp = i - r * 192;
        int c = cnt[r];
        float fx = (float)xp;
        unsigned par = 0;
        for (int j = 0; j < c; j++) par ^= (fx < xint[r][j]) ? 1u : 0u;
        g_mask[(size_t)poly * HW + (rb + r) * WW + xp] = (float)par;
    }
}

// ---------------- mask_batch + union ----------------
__global__ void k_mb(const int* __restrict__ ct_num, float* __restrict__ mb) {
    int b = blockIdx.y;
    int px = blockIdx.x * 256 + threadIdx.x;
    int count = ct_num[b];
    int start = (b == 0) ? 0 : ct_num[b - 1];   // reference slicing quirk
    float u = 0.0f;
    for (int c = 0; c < 32; c++) {
        float v = (c < count) ? g_mask[(size_t)(start + c) * HW + px] : 0.0f;
        mb[(size_t)(b * 32 + c) * HW + px] = v;
        u = fmaxf(u, v);
    }
    g_union[b * HW + px] = u;
}

// ---------------- featmul pass 1 (NHWC in-place) ----------------
__global__ void k_featmul() {
    int idx = blockIdx.x * 256 + threadIdx.x;
    float u = g_union[idx >> 6];
    float v = g_feat[idx];
    g_feat[idx] = fmaxf(v * (1.0f + u), 0.0f);
}

// ---------------- final: featmul pass 2 + NHWC -> NCHW ----------------
__global__ void k_final(float* __restrict__ out) {
    __shared__ float t[32][33];
    int b = blockIdx.z;
    int c0 = blockIdx.y * 32;
    int p0 = blockIdx.x * 32;
    int tx = threadIdx.x, ty = threadIdx.y;
#pragma unroll
    for (int i = 0; i < 32; i += 8) {
        int p = p0 + ty + i;
        float u = g_union[b * HW + p];
        float v = g_feat[((size_t)b * HW + p) * CIN + c0 + tx];
        t[ty + i][tx] = fmaxf(v * (1.0f + u), 0.0f);
    }
    __syncthreads();
#pragma unroll
    for (int i = 0; i < 32; i += 8)
        out[((size_t)b * CIN + c0 + ty + i) * HW + p0 + tx] = t[tx][ty + i];
}

// ---------------- bilinear sampling (NHWC) ----------------
__global__ __launch_bounds__(256) void k_sample(const int* __restrict__ ct_ind,
                                                const int* __restrict__ ct_img) {
    __shared__ float s_w[129][4];
    __shared__ int s_off[129][4];
    int n = blockIdx.x;
    int tid = threadIdx.x;
    int img = ct_img[n];
    if (tid < 129) {
        float ptx, pty;
        if (tid == 0) {
            int ind = ct_ind[n];
            ptx = (float)(ind % WW);
            pty = (float)(ind / WW);
        } else {
            ptx = g_init[(n * PPTS + tid - 1) * 2 + 0];
            pty = g_init[(n * PPTS + tid - 1) * 2 + 1];
        }
        float xs = ptx - 0.5f, ys = pty - 0.5f;
        float x0f = floorf(xs), y0f = floorf(ys);
        float wx = xs - x0f, wy = ys - y0f;
        int x0 = (int)x0f, y0 = (int)y0f;
#pragma unroll
        for (int k = 0; k < 4; k++) {
            int xi = x0 + (k & 1);
            int yi = y0 + (k >> 1);
            bool valid = (xi >= 0) && (xi < WW) && (yi >= 0) && (yi < HH);
            int xc = min(max(xi, 0), WW - 1);
            int yc = min(max(yi, 0), HH - 1);
            s_off[tid][k] = yc * WW + xc;
            float wxx = (k & 1) ? wx : (1.0f - wx);
            float wyy = (k >> 1) ? wy : (1.0f - wy);
            s_w[tid][k] = valid ? wxx * wyy : 0.0f;
        }
    }
    __syncthreads();
    const float* fb = g_feat + (size_t)img * HW * CIN;
    for (int i = tid; i < FPK; i += 256) {
        int pp = i >> 6;
        int c = i & 63;
        float v = s_w[pp][0] * fb[(size_t)s_off[pp][0] * CIN + c]
                + s_w[pp][1] * fb[(size_t)s_off[pp][1] * CIN + c]
                + s_w[pp][2] * fb[(size_t)s_off[pp][2] * CIN + c]
                + s_w[pp][3] * fb[(size_t)s_off[pp][3] * CIN + c];
        g_fp[(size_t)n * FPK + c * 129 + pp] = v;
    }
}

// ---------------- NT GEMMs for offsets (fp32, exact path) ----------------
template <int MODE>
__global__ __launch_bounds__(256) void k_gemm(const float* __restrict__ Bm,
                                              const float* __restrict__ bias,
                                              float* __restrict__ outc) {
    const int K = (MODE == 0) ? FPK : 512;
    const float* A = (MODE == 0) ? (const float*)g_fp : (const float*)g_tmp;
    __shared__ float sA[16][68];
    __shared__ float sB[16][68];
    int m0 = blockIdx.y * 64, n0 = blockIdx.x * 64;
    int tid = threadIdx.x;
    int tx = tid & 15, ty = tid >> 4;
    int kk = tid & 15, rr = tid >> 4;
    float acc[4][4];
#pragma unroll
    for (int i = 0; i < 4; i++)
#pragma unroll
        for (int j = 0; j < 4; j++) acc[i][j] = 0.0f;

    int kbeg = (MODE == 0) ? blockIdx.z * 688 : 0;
    int kend = (MODE == 0) ? kbeg + 688 : 512;
    for (int k0 = kbeg; k0 < kend; k0 += 16) {
        __syncthreads();
#pragma unroll
        for (int pass = 0; pass < 4; pass++) {
            int row = rr + pass * 16;
            sA[kk][row] = A[(size_t)(m0 + row) * K + k0 + kk];
            sB[kk][row] = Bm[(size_t)(n0 + row) * K + k0 + kk];
        }
        __syncthreads();
#pragma unroll
        for (int k2 = 0; k2 < 16; k2++) {
            float4 a4 = *(const float4*)&sA[k2][ty * 4];
            float4 b4 = *(const float4*)&sB[k2][tx * 4];
            acc[0][0] += a4.x * b4.x; acc[0][1] += a4.x * b4.y; acc[0][2] += a4.x * b4.z; acc[0][3] += a4.x * b4.w;
            acc[1][0] += a4.y * b4.x; acc[1][1] += a4.y * b4.y; acc[1][2] += a4.y * b4.z; acc[1][3] += a4.y * b4.w;
            acc[2][0] += a4.z * b4.x; acc[2][1] += a4.z * b4.y; acc[2][2] += a4.z * b4.z; acc[2][3] += a4.z * b4.w;
            acc[3][0] += a4.w * b4.x; acc[3][1] += a4.w * b4.y; acc[3][2] += a4.w * b4.z; acc[3][3] += a4.w * b4.w;
        }
    }
    if (MODE == 0) {
#pragma unroll
        for (int i = 0; i < 4; i++)
#pragma unroll
            for (int j = 0; j < 4; j++)
                g_part[((size_t)blockIdx.z * 128 + m0 + ty * 4 + i) * 512 + n0 + tx * 4 + j] = acc[i][j];
    } else {
#pragma unroll
        for (int i = 0; i < 4; i++) {
            int m = m0 + ty * 4 + i;
#pragma unroll
            for (int j = 0; j < 4; j++) {
                int nn = n0 + tx * 4 + j;
                float v = acc[i][j] + bias[nn];
                float cr = v * 4.0f + g_init[m * 256 + nn];
                g_coarse[m * 256 + nn] = cr;
                outc[m * 256 + nn] = cr * 4.0f;
            }
        }
    }
}

__global__ void k_reduce() {
    int i = blockIdx.x * 256 + threadIdx.x;
    float s = 0.0f;
#pragma unroll
    for (int p = 0; p < NSPLIT; p++) s += g_part[(size_t)p * 65536 + i];
    g_tmp[i] = s;
}

// ---------------- launcher ----------------
extern "C" void kernel_launch(void* const* d_in, const int* in_sizes, int n_in,
                              void* d_out, int out_size) {
    const float* wh     = (const float*)d_in[0];
    const float* cnn    = (const float*)d_in[1];
    const float* w1     = (const float*)d_in[2];
    const float* b1     = (const float*)d_in[3];
    const float* w2     = (const float*)d_in[4];
    const float* b2     = (const float*)d_in[5];
    const float* wpoly  = (const float*)d_in[6];
    const float* wfuse  = (const float*)d_in[7];
    const float* bfuse  = (const float*)d_in[8];
    const int*   ct_ind = (const int*)d_in[9];
    const int*   ct_img = (const int*)d_in[10];
    const int*   ct_num = (const int*)d_in[11];

    float* out        = (float*)d_out;
    float* out_init   = out + O_INIT;
    float* out_coarse = out + O_COARSE;
    float* out_mbi    = out + O_MBI;
    float* out_mbc    = out + O_MBC;
    float* out_feat   = out + O_FEAT;

    cudaFuncSetAttribute(k_conv, cudaFuncAttributeMaxDynamicSharedMemorySize, CONV_SMEM);

    k_prep<<<9856, 256>>>(cnn, w1, w2);                       // 0
    k_init<<<128, 128>>>(wh, ct_ind, ct_img, out_init);       // 1
    k_pnp<<<dim3(24, 64), 256>>>(0);                          // 2
    k_conv<<<dim3(288, 4), 512, CONV_SMEM>>>(b1, b2);         // 3  <- profiled slot
    k_mb<<<dim3(144, 4), 256>>>(ct_num, out_mbi);             // 4
    k_featmul<<<36864, 256>>>();                              // 5

    k_sample<<<128, 256>>>(ct_ind, ct_img);
    k_gemm<0><<<dim3(8, 2, NSPLIT), 256>>>(wpoly, nullptr, nullptr);
    k_reduce<<<256, 256>>>();
    k_gemm<1><<<dim3(4, 2), 256>>>(wfuse, bfuse, out_coarse);

    k_pnp<<<dim3(24, 64), 256>>>(1);
    k_mb<<<dim3(144, 4), 256>>>(ct_num, out_mbc);
    k_final<<<dim3(1152, 2, 4), dim3(32, 8)>>>(out_feat);
}

// round 10
// speedup vs baseline: 2.6516x; 1.0580x over previous
#include <cuda_runtime.h>
#include <cuda_fp16.h>
#include <cstdint>

// ---------------- problem constants ----------------
#define BATCH   4
#define CIN     64
#define HH      192
#define WW      192
#define HW      36864
#define NPOLY   128
#define PPTS    128
#define FPK     8256
#define NSPLIT  12

// output layout (floats)
#define O_INIT   0
#define O_COARSE 32768
#define O_MBI    65536
#define O_MBC    (65536 + 4718592)
#define O_FEAT   (65536 + 2*4718592)

// conv A-slab geometry (32x4 pixel patch, 1-px halo)
#define SLAB_W  34
#define SLAB_PX 204
#define SLAB_ZERO 204
#define SLAB_BYTES 26240u      // 205 rows * 128 B
#define B_OFF   52480u         // 2 * SLAB_BYTES
#define B_STAGE 32768u
#define CONV_SMEM (52480 + 3*32768)   // 150784

// ---------------- device scratch ----------------
__device__ __half g_xh_h[BATCH * HW * CIN];
__device__ __half g_xh_l[BATCH * HW * CIN];
__device__ __half g_w1h[256 * 576];
__device__ __half g_w1l[256 * 576];
__device__ __half g_w2h[64 * 256];
__device__ __half g_w2l[64 * 256];
__device__ float  g_feat[BATCH * HW * CIN];
__device__ float  g_union[BATCH * HW];
__device__ float  g_init[NPOLY * PPTS * 2];
__device__ float  g_coarse[NPOLY * PPTS * 2];
__device__ float  g_fp[NPOLY * FPK];
__device__ float  g_tmp[NPOLY * 512];
__device__ float  g_part[NSPLIT * NPOLY * 512];

// ---------------- helpers ----------------
__device__ __forceinline__ uint32_t smem_u32(const void* p) {
    uint32_t a;
    asm("{ .reg .u64 t; cvta.to.shared.u64 t, %1; cvt.u32.u64 %0, t; }" : "=r"(a) : "l"(p));
    return a;
}
__device__ __forceinline__ void cp16(uint32_t dst, const void* src, int sz) {
    asm volatile("cp.async.ca.shared.global [%0], [%1], 16, %2;" :: "r"(dst), "l"(src), "r"(sz));
}
#define CP_COMMIT() asm volatile("cp.async.commit_group;")
#define CP_WAIT1()  asm volatile("cp.async.wait_group 1;")
#define CP_WAIT0()  asm volatile("cp.async.wait_group 0;")
__device__ __forceinline__ void ldmx4(uint32_t addr, uint32_t* r) {
    asm volatile("ldmatrix.sync.aligned.m8n8.x4.shared.b16 {%0,%1,%2,%3}, [%4];"
        : "=r"(r[0]), "=r"(r[1]), "=r"(r[2]), "=r"(r[3]) : "r"(addr));
}
__device__ __forceinline__ void hmma(float* d, const uint32_t* a, const uint32_t* b) {
    asm volatile("mma.sync.aligned.m16n8k16.row.col.f32.f16.f16.f32 "
        "{%0,%1,%2,%3}, {%4,%5,%6,%7}, {%8,%9}, {%0,%1,%2,%3};"
        : "+f"(d[0]), "+f"(d[1]), "+f"(d[2]), "+f"(d[3])
        : "r"(a[0]), "r"(a[1]), "r"(a[2]), "r"(a[3]), "r"(b[0]), "r"(b[1]));
}
__device__ __forceinline__ uint32_t swz64(int row, int colb) {
    return (uint32_t)(row * 64 + (colb ^ (((row >> 1) & 3) << 4)));
}
__device__ __forceinline__ uint32_t swz128(int row, int colb) {
    return (uint32_t)(row * 128 + (colb ^ ((row & 7) << 4)));
}
__device__ __forceinline__ void split_store(__half* hp, __half* lp, float v) {
    __half h = __float2half_rn(v);
    *hp = h;
    *lp = __float2half_rn(v - __half2float(h));
}

// ---------------- zero kernel: union + mb slack slots ----------------
__global__ void k_zero(const int* __restrict__ ct_num, float* __restrict__ mb) {
    int i = blockIdx.x * 256 + threadIdx.x;    // 147456 = 4*HW
    ((unsigned*)g_union)[i] = 0u;
    int b = i / HW, px = i - b * HW;
    int cn = ct_num[b];
    for (int c = cn; c < 32; c++)
        mb[(size_t)(b * 32 + c) * HW + px] = 0.0f;
}

// ---------------- pnp body: scanline mask, direct mb writes + union atomics ----
__device__ void pnp_body(int poly, int rg, int src,
                         const float* __restrict__ wh, const int* __restrict__ ct_ind,
                         const int* __restrict__ ct_img, const int* __restrict__ ct_num,
                         float* __restrict__ mb) {
    __shared__ float verts[256];
    __shared__ float xint[8][132];
    __shared__ int cnt[8];
    __shared__ int slots[4];
    int tid = threadIdx.x;
    int rb = rg * 8;

    if (src == 0) {
        // compute init poly verts directly from wh (same FFMA shape as k_init)
        int ind = ct_ind[poly];
        int img = ct_img[poly];
        int cx = ind % WW;
        int cy = ind / WW;
        int p = tid >> 1;
        size_t base = (size_t)img * 256 * HW + (size_t)cy * WW + cx;
        float off = wh[base + (size_t)(2 * p + (tid & 1)) * HW];
        verts[tid] = off * 10.0f + (float)((tid & 1) ? cy : cx);
    } else {
        verts[tid] = g_coarse[poly * 256 + tid];
    }
    if (tid < 8) cnt[tid] = 0;
    if (tid < 4) {
        int cnb = ct_num[tid];
        int start = (tid == 0) ? 0 : ct_num[tid - 1];   // reference slicing quirk
        int c = poly - start;
        slots[tid] = (c >= 0 && c < cnb) ? c : -1;
    }
    __syncthreads();
    for (int i = tid; i < 1024; i += 256) {
        int e = i & 127, r = i >> 7;
        float yy = (float)(rb + r);
        int e2 = (e + 1) & 127;
        float y1 = verts[2 * e + 1];
        float y2 = verts[2 * e2 + 1];
        if ((y1 > yy) != (y2 > yy)) {
            float x1 = verts[2 * e];
            float x2 = verts[2 * e2];
            float den = y2 - y1;
            if (fabsf(den) < 1e-9f) den = 1e-9f;
            float xi = x1 + (x2 - x1) * (yy - y1) / den;
            int s = atomicAdd(&cnt[r], 1);
            xint[r][s] = xi;
        }
    }
    __syncthreads();
    for (int i = tid; i < 1536; i += 256) {
        int r = i / 192;
        int xp = i - r * 192;
        int c = cnt[r];
        float fx = (float)xp;
        unsigned par = 0;
        for (int j = 0; j < c; j++) par ^= (fx < xint[r][j]) ? 1u : 0u;
        float parf = (float)par;
        int px = (rb + r) * WW + xp;
#pragma unroll
        for (int b = 0; b < 4; b++) {
            int sc = slots[b];
            if (sc >= 0) {
                mb[(size_t)(b * 32 + sc) * HW + px] = parf;
                if (par) atomicOr((unsigned*)&g_union[b * HW + px], 0x3F800000u);
            }
        }
    }
}

// ---------------- K0: init polys (exact outputs + g_init) ----------------
__global__ void k_init(const float* __restrict__ wh, const int* __restrict__ ct_ind,
                       const int* __restrict__ ct_img, float* __restrict__ out_init) {
    int n = blockIdx.x;
    int p = threadIdx.x;
    int ind = ct_ind[n];
    int img = ct_img[n];
    int cx = ind % WW;
    int cy = ind / WW;
    size_t base = (size_t)img * 256 * HW + (size_t)cy * WW + cx;
    float ox = wh[base + (size_t)(2 * p) * HW];
    float oy = wh[base + (size_t)(2 * p + 1) * HW];
    float ix = ox * 10.0f + (float)cx;
    float iy = oy * 10.0f + (float)cy;
    int o = (n * PPTS + p) * 2;
    g_init[o + 0] = ix;
    g_init[o + 1] = iy;
    out_init[o + 0] = ix * 4.0f;
    out_init[o + 1] = iy * 4.0f;
}

// ---------------- merged front: weight split + input transpose + pnp(init) ----
// grid 11392 x 256: [0,640) w-split, [640,9856) x-transpose, [9856,11392) pnp0
__global__ __launch_bounds__(256) void k_front(const float* __restrict__ x,
                                               const float* __restrict__ w1,
                                               const float* __restrict__ w2,
                                               const float* __restrict__ wh,
                                               const int* __restrict__ ct_ind,
                                               const int* __restrict__ ct_img,
                                               const int* __restrict__ ct_num,
                                               float* __restrict__ out_mbi) {
    int bid = blockIdx.x;
    if (bid < 640) {
        int i = bid * 256 + threadIdx.x;
        if (i < 147456) {
            int oc = i / 576, k = i - oc * 576;
            int tap = k >> 6, ic = k & 63;
            split_store(&g_w1h[i], &g_w1l[i], w1[(oc * 64 + ic) * 9 + tap]);
        } else {
            int j = i - 147456;
            split_store(&g_w2h[j], &g_w2l[j], w2[j]);
        }
        return;
    }
    if (bid < 9856) {
        __shared__ float t[32][33];
        int xb = bid - 640;
        int pxb = xb % 1152;
        int cy = (xb / 1152) & 1;
        int b = xb / 2304;
        int c0 = cy * 32;
        int p0 = pxb * 32;
        int tx = threadIdx.x & 31, ty = threadIdx.x >> 5;
#pragma unroll
        for (int i = 0; i < 32; i += 8)
            t[ty + i][tx] = x[((size_t)b * CIN + c0 + ty + i) * HW + p0 + tx];
        __syncthreads();
#pragma unroll
        for (int i = 0; i < 32; i += 8) {
            size_t o = ((size_t)b * HW + p0 + ty + i) * CIN + c0 + tx;
            split_store(&g_xh_h[o], &g_xh_l[o], t[tx][ty + i]);
        }
        return;
    }
    int j = bid - 9856;                 // 0..1535
    pnp_body(j % 64, j / 64, 0, wh, ct_ind, ct_img, ct_num, out_mbi);
}

// ---------------- pnp(coarse) standalone ----------------
__global__ __launch_bounds__(256) void k_pnp_c(const int* __restrict__ ct_num,
                                               float* __restrict__ out_mbc) {
    pnp_body(blockIdx.y, blockIdx.x, 1, nullptr, nullptr, nullptr, ct_num, out_mbc);
}

// ---------------- fused conv1 + conv2 (+featmul) ----------------
// grid (288, 4), 512 thr. CTA = 32x4 px patch, all 256 oc. 3-term fp16 split.
__global__ __launch_bounds__(512, 1) void k_conv(const float* __restrict__ b1,
                                                 const float* __restrict__ b2) {
    extern __shared__ char sm[];
    uint32_t sb = smem_u32(sm);
    int tid = threadIdx.x, lane = tid & 31, wid = tid >> 5;
    int b = blockIdx.y;
    int px0 = (blockIdx.x % 6) * 32;
    int py0 = (blockIdx.x / 6) * 4;
    int wm = wid & 1, wn = wid >> 1;

    float acc[4][4][4];
#pragma unroll
    for (int i = 0; i < 4; i++)
#pragma unroll
        for (int j = 0; j < 4; j++)
#pragma unroll
            for (int k = 0; k < 4; k++) acc[i][j][k] = 0.0f;

    size_t xbase = (size_t)b * HW;

    int ry[4], rx[4], sbs[4];
#pragma unroll
    for (int mt = 0; mt < 4; mt++) {
        int r = wm * 64 + mt * 16 + (lane & 15);
        int pr = r >> 5, pc = r & 31;
        ry[mt] = py0 + pr;
        rx[mt] = px0 + pc;
        sbs[mt] = (pr + 1) * SLAB_W + pc + 1;
    }

    int brow = tid >> 1;
    int bq0 = (tid & 1) * 2;
    const __half* w1h_p = g_w1h + (size_t)brow * 576 + bq0 * 8;
    const __half* w1l_p = g_w1l + (size_t)brow * 576 + bq0 * 8;
    uint32_t bd0 = swz64(brow, bq0 * 16);
    uint32_t bd1 = swz64(brow, bq0 * 16 + 16);

    auto load_b = [&](int chunk) {
        uint32_t st = sb + B_OFF + (uint32_t)(chunk % 3) * B_STAGE;
        int tap = chunk >> 1, half = chunk & 1;
        int wo = tap * 64 + half * 32;
        cp16(st + bd0, w1h_p + wo, 16);
        cp16(st + bd1, w1h_p + wo + 8, 16);
        cp16(st + 16384u + bd0, w1l_p + wo, 16);
        cp16(st + 16384u + bd1, w1l_p + wo + 8, 16);
    };

    for (int i = tid; i < 205 * 8; i += 512) {
        int s = i >> 3, q = i & 7;
        uint32_t d = swz128(s, q * 16);
        int sz = 0;
        size_t np = 0;
        if (s < SLAB_PX) {
            int sy = s / SLAB_W, sx = s - sy * SLAB_W;
            int yy = py0 - 1 + sy, xx = px0 - 1 + sx;
            if ((unsigned)yy < 192u && (unsigned)xx < 192u) {
                np = (xbase + yy * 192 + xx) * 64 + q * 8;
                sz = 16;
            }
        }
        cp16(sb + d, g_xh_h + np, sz);
        cp16(sb + SLAB_BYTES + d, g_xh_l + np, sz);
    }
    load_b(0); CP_COMMIT();
    load_b(1); CP_COMMIT();

    for (int c = 0; c < 18; c++) {
        CP_WAIT1();
        __syncthreads();
        if (c + 2 < 18) load_b(c + 2);
        CP_COMMIT();

        int tap = c >> 1, half = c & 1;
        int dy = tap / 3 - 1, dx = tap % 3 - 1;
        uint32_t sa[4];
#pragma unroll
        for (int mt = 0; mt < 4; mt++) {
            bool v = ((unsigned)(ry[mt] + dy) < 192u) && ((unsigned)(rx[mt] + dx) < 192u);
            sa[mt] = v ? (uint32_t)(sbs[mt] + dy * SLAB_W + dx) : (uint32_t)SLAB_ZERO;
        }
        uint32_t bst = sb + B_OFF + (uint32_t)(c % 3) * B_STAGE;
#pragma unroll
        for (int k16 = 0; k16 < 2; k16++) {
            int kb = k16 * 32;
            int acolb = half * 64 + kb + (lane >> 4) * 16;
            int brr = wn * 32 + ((lane >> 4) << 3) + (lane & 7);
            int bcolb = kb + ((lane >> 3) & 1) * 16;
            uint32_t bd_a = swz64(brr, bcolb);
            uint32_t bd_b = swz64(brr + 16, bcolb);

            uint32_t af[4][4];
#pragma unroll
            for (int mt = 0; mt < 4; mt++)
                ldmx4(sb + swz128((int)sa[mt], acolb), af[mt]);
            uint32_t bf[4][2];
            {
                uint32_t r[4];
                ldmx4(bst + bd_a, r);
                bf[0][0] = r[0]; bf[0][1] = r[1]; bf[1][0] = r[2]; bf[1][1] = r[3];
                ldmx4(bst + bd_b, r);
                bf[2][0] = r[0]; bf[2][1] = r[1]; bf[3][0] = r[2]; bf[3][1] = r[3];
            }
#pragma unroll
            for (int mt = 0; mt < 4; mt++)
#pragma unroll
                for (int nt = 0; nt < 4; nt++) hmma(acc[mt][nt], af[mt], bf[nt]);
            uint32_t al[4][4];
#pragma unroll
            for (int mt = 0; mt < 4; mt++)
                ldmx4(sb + SLAB_BYTES + swz128((int)sa[mt], acolb), al[mt]);
#pragma unroll
            for (int mt = 0; mt < 4; mt++)
#pragma unroll
                for (int nt = 0; nt < 4; nt++) hmma(acc[mt][nt], al[mt], bf[nt]);
            {
                uint32_t r[4];
                ldmx4(bst + 16384u + bd_a, r);
                bf[0][0] = r[0]; bf[0][1] = r[1]; bf[1][0] = r[2]; bf[1][1] = r[3];
                ldmx4(bst + 16384u + bd_b, r);
                bf[2][0] = r[0]; bf[2][1] = r[1]; bf[3][0] = r[2]; bf[3][1] = r[3];
            }
#pragma unroll
            for (int mt = 0; mt < 4; mt++)
#pragma unroll
                for (int nt = 0; nt < 4; nt++) hmma(acc[mt][nt], af[mt], bf[nt]);
        }
    }

    // ---------------- conv2 phases (4 x 64-oc pieces) ----------------
    int wm2 = wid & 3, wn2 = wid >> 2;
    float acc2[2][2][4];
#pragma unroll
    for (int i = 0; i < 2; i++)
#pragma unroll
        for (int j = 0; j < 2; j++)
#pragma unroll
            for (int k = 0; k < 4; k++) acc2[i][j][k] = 0.0f;

    int w2row = tid >> 3, w2sg = tid & 7;
    uint32_t w2d = swz128(w2row, w2sg * 16);

    for (int ph = 0; ph < 4; ph++) {
        __syncthreads();
        cp16(sb + B_OFF + w2d, g_w2h + (size_t)w2row * 256 + ph * 64 + w2sg * 8, 16);
        cp16(sb + B_OFF + 8192u + w2d, g_w2l + (size_t)w2row * 256 + ph * 64 + w2sg * 8, 16);
        CP_COMMIT();
        if ((wn >> 1) == ph) {
            int ocbase = (wn & 1) * 32;
#pragma unroll
            for (int mt = 0; mt < 4; mt++) {
#pragma unroll
                for (int nt = 0; nt < 4; nt++) {
                    int oc_l = ocbase + nt * 8 + (lane & 3) * 2;
                    float bb0 = __ldg(&b1[ph * 64 + oc_l]);
                    float bb1 = __ldg(&b1[ph * 64 + oc_l + 1]);
#pragma unroll
                    for (int rh = 0; rh < 2; rh++) {
                        int row = wm * 64 + mt * 16 + (lane >> 2) + rh * 8;
                        float t0 = fmaxf(acc[mt][nt][rh * 2 + 0] + bb0, 0.0f);
                        float t1 = fmaxf(acc[mt][nt][rh * 2 + 1] + bb1, 0.0f);
                        __half h0 = __float2half_rn(t0), h1 = __float2half_rn(t1);
                        uint32_t ad = (uint32_t)(row * 128 + ((oc_l * 2) ^ ((row & 7) << 4)));
                        *(__half2*)(sm + ad) = __halves2half2(h0, h1);
                        *(__half2*)(sm + 16384 + ad) = __halves2half2(
                            __float2half_rn(t0 - __half2float(h0)),
                            __float2half_rn(t1 - __half2float(h1)));
                    }
                }
            }
        }
        CP_WAIT0();
        __syncthreads();
#pragma unroll
        for (int kc = 0; kc < 2; kc++) {
#pragma unroll
            for (int k16 = 0; k16 < 2; k16++) {
                int kcb = kc * 64 + k16 * 32;
                uint32_t af2[2][4];
#pragma unroll
                for (int mt = 0; mt < 2; mt++) {
                    int row = wm2 * 32 + mt * 16 + (lane & 15);
                    int colb = kcb + (lane >> 4) * 16;
                    ldmx4(sb + swz128(row, colb), af2[mt]);
                }
                uint32_t bf2[2][2];
                int brow2 = wn2 * 16 + ((lane >> 4) << 3) + (lane & 7);
                int bcolb2 = kcb + ((lane >> 3) & 1) * 16;
                uint32_t bd2 = swz128(brow2, bcolb2);
                {
                    uint32_t r[4];
                    ldmx4(sb + B_OFF + bd2, r);
                    bf2[0][0] = r[0]; bf2[0][1] = r[1]; bf2[1][0] = r[2]; bf2[1][1] = r[3];
                }
#pragma unroll
                for (int mt = 0; mt < 2; mt++)
#pragma unroll
                    for (int nt = 0; nt < 2; nt++) hmma(acc2[mt][nt], af2[mt], bf2[nt]);
                uint32_t al2[2][4];
#pragma unroll
                for (int mt = 0; mt < 2; mt++) {
                    int row = wm2 * 32 + mt * 16 + (lane & 15);
                    int colb = kcb + (lane >> 4) * 16;
                    ldmx4(sb + 16384u + swz128(row, colb), al2[mt]);
                }
#pragma unroll
                for (int mt = 0; mt < 2; mt++)
#pragma unroll
                    for (int nt = 0; nt < 2; nt++) hmma(acc2[mt][nt], al2[mt], bf2[nt]);
                {
                    uint32_t r[4];
                    ldmx4(sb + B_OFF + 8192u + bd2, r);
                    bf2[0][0] = r[0]; bf2[0][1] = r[1]; bf2[1][0] = r[2]; bf2[1][1] = r[3];
                }
#pragma unroll
                for (int mt = 0; mt < 2; mt++)
#pragma unroll
                    for (int nt = 0; nt < 2; nt++) hmma(acc2[mt][nt], af2[mt], bf2[nt]);
            }
        }
    }

    // epilogue: feat = relu((D2 + b2) * (1 + union_init))  [featmul fused]
#pragma unroll
    for (int mt = 0; mt < 2; mt++) {
#pragma unroll
        for (int nt = 0; nt < 2; nt++) {
            int oc2 = wn2 * 16 + nt * 8 + (lane & 3) * 2;
            float bb0 = __ldg(&b2[oc2]), bb1 = __ldg(&b2[oc2 + 1]);
#pragma unroll
            for (int rh = 0; rh < 2; rh++) {
                int m = wm2 * 32 + mt * 16 + (lane >> 2) + rh * 8;
                int px = (py0 + (m >> 5)) * 192 + px0 + (m & 31);
                float u = g_union[b * HW + px];
                float s = 1.0f + u;
                float2 v;
                v.x = fmaxf((acc2[mt][nt][rh * 2 + 0] + bb0) * s, 0.0f);
                v.y = fmaxf((acc2[mt][nt][rh * 2 + 1] + bb1) * s, 0.0f);
                *(float2*)&g_feat[((size_t)b * HW + px) * 64 + oc2] = v;
            }
        }
    }
}

// ---------------- final: featmul pass 2 + NHWC -> NCHW ----------------
__global__ void k_final(float* __restrict__ out) {
    __shared__ float t[32][33];
    int b = blockIdx.z;
    int c0 = blockIdx.y * 32;
    int p0 = blockIdx.x * 32;
    int tx = threadIdx.x, ty = threadIdx.y;
#pragma unroll
    for (int i = 0; i < 32; i += 8) {
        int p = p0 + ty + i;
        float u = g_union[b * HW + p];
        float v = g_feat[((size_t)b * HW + p) * CIN + c0 + tx];
        t[ty + i][tx] = fmaxf(v * (1.0f + u), 0.0f);
    }
    __syncthreads();
#pragma unroll
    for (int i = 0; i < 32; i += 8)
        out[((size_t)b * CIN + c0 + ty + i) * HW + p0 + tx] = t[tx][ty + i];
}

// ---------------- bilinear sampling (NHWC) ----------------
__global__ __launch_bounds__(256) void k_sample(const int* __restrict__ ct_ind,
                                                const int* __restrict__ ct_img) {
    __shared__ float s_w[129][4];
    __shared__ int s_off[129][4];
    int n = blockIdx.x;
    int tid = threadIdx.x;
    int img = ct_img[n];
    if (tid < 129) {
        float ptx, pty;
        if (tid == 0) {
            int ind = ct_ind[n];
            ptx = (float)(ind % WW);
            pty = (float)(ind / WW);
        } else {
            ptx = g_init[(n * PPTS + tid - 1) * 2 + 0];
            pty = g_init[(n * PPTS + tid - 1) * 2 + 1];
        }
        float xs = ptx - 0.5f, ys = pty - 0.5f;
        float x0f = floorf(xs), y0f = floorf(ys);
        float wx = xs - x0f, wy = ys - y0f;
        int x0 = (int)x0f, y0 = (int)y0f;
#pragma unroll
        for (int k = 0; k < 4; k++) {
            int xi = x0 + (k & 1);
            int yi = y0 + (k >> 1);
            bool valid = (xi >= 0) && (xi < WW) && (yi >= 0) && (yi < HH);
            int xc = min(max(xi, 0), WW - 1);
            int yc = min(max(yi, 0), HH - 1);
            s_off[tid][k] = yc * WW + xc;
            float wxx = (k & 1) ? wx : (1.0f - wx);
            float wyy = (k >> 1) ? wy : (1.0f - wy);
            s_w[tid][k] = valid ? wxx * wyy : 0.0f;
        }
    }
    __syncthreads();
    const float* fb = g_feat + (size_t)img * HW * CIN;
    for (int i = tid; i < FPK; i += 256) {
        int pp = i >> 6;
        int c = i & 63;
        float v = s_w[pp][0] * fb[(size_t)s_off[pp][0] * CIN + c]
                + s_w[pp][1] * fb[(size_t)s_off[pp][1] * CIN + c]
                + s_w[pp][2] * fb[(size_t)s_off[pp][2] * CIN + c]
                + s_w[pp][3] * fb[(size_t)s_off[pp][3] * CIN + c];
        g_fp[(size_t)n * FPK + c * 129 + pp] = v;
    }
}

// ---------------- NT GEMMs for offsets (fp32, exact path) ----------------
template <int MODE>
__global__ __launch_bounds__(256) void k_gemm(const float* __restrict__ Bm,
                                              const float* __restrict__ bias,
                                              float* __restrict__ outc) {
    const int K = (MODE == 0) ? FPK : 512;
    const float* A = (MODE == 0) ? (const float*)g_fp : (const float*)g_tmp;
    __shared__ float sA[16][68];
    __shared__ float sB[16][68];
    int m0 = blockIdx.y * 64, n0 = blockIdx.x * 64;
    int tid = threadIdx.x;
    int tx = tid & 15, ty = tid >> 4;
    int kk = tid & 15, rr = tid >> 4;
    float acc[4][4];
#pragma unroll
    for (int i = 0; i < 4; i++)
#pragma unroll
        for (int j = 0; j < 4; j++) acc[i][j] = 0.0f;

    int kbeg = (MODE == 0) ? blockIdx.z * 688 : 0;
    int kend = (MODE == 0) ? kbeg + 688 : 512;
    for (int k0 = kbeg; k0 < kend; k0 += 16) {
        __syncthreads();
#pragma unroll
        for (int pass = 0; pass < 4; pass++) {
            int row = rr + pass * 16;
            sA[kk][row] = A[(size_t)(m0 + row) * K + k0 + kk];
            sB[kk][row] = Bm[(size_t)(n0 + row) * K + k0 + kk];
        }
        __syncthreads();
#pragma unroll
        for (int k2 = 0; k2 < 16; k2++) {
            float4 a4 = *(const float4*)&sA[k2][ty * 4];
            float4 b4 = *(const float4*)&sB[k2][tx * 4];
            acc[0][0] += a4.x * b4.x; acc[0][1] += a4.x * b4.y; acc[0][2] += a4.x * b4.z; acc[0][3] += a4.x * b4.w;
            acc[1][0] += a4.y * b4.x; acc[1][1] += a4.y * b4.y; acc[1][2] += a4.y * b4.z; acc[1][3] += a4.y * b4.w;
            acc[2][0] += a4.z * b4.x; acc[2][1] += a4.z * b4.y; acc[2][2] += a4.z * b4.z; acc[2][3] += a4.z * b4.w;
            acc[3][0] += a4.w * b4.x; acc[3][1] += a4.w * b4.y; acc[3][2] += a4.w * b4.z; acc[3][3] += a4.w * b4.w;
        }
    }
    if (MODE == 0) {
#pragma unroll
        for (int i = 0; i < 4; i++)
#pragma unroll
            for (int j = 0; j < 4; j++)
                g_part[((size_t)blockIdx.z * 128 + m0 + ty * 4 + i) * 512 + n0 + tx * 4 + j] = acc[i][j];
    } else {
#pragma unroll
        for (int i = 0; i < 4; i++) {
            int m = m0 + ty * 4 + i;
#pragma unroll
            for (int j = 0; j < 4; j++) {
                int nn = n0 + tx * 4 + j;
                float v = acc[i][j] + bias[nn];
                float cr = v * 4.0f + g_init[m * 256 + nn];
                g_coarse[m * 256 + nn] = cr;
                outc[m * 256 + nn] = cr * 4.0f;
            }
        }
    }
}

__global__ void k_reduce() {
    int i = blockIdx.x * 256 + threadIdx.x;
    float s = 0.0f;
#pragma unroll
    for (int p = 0; p < NSPLIT; p++) s += g_part[(size_t)p * 65536 + i];
    g_tmp[i] = s;
}

// ---------------- launcher ----------------
extern "C" void kernel_launch(void* const* d_in, const int* in_sizes, int n_in,
                              void* d_out, int out_size) {
    const float* wh     = (const float*)d_in[0];
    const float* cnn    = (const float*)d_in[1];
    const float* w1     = (const float*)d_in[2];
    const float* b1     = (const float*)d_in[3];
    const float* w2     = (const float*)d_in[4];
    const float* b2     = (const float*)d_in[5];
    const float* wpoly  = (const float*)d_in[6];
    const float* wfuse  = (const float*)d_in[7];
    const float* bfuse  = (const float*)d_in[8];
    const int*   ct_ind = (const int*)d_in[9];
    const int*   ct_img = (const int*)d_in[10];
    const int*   ct_num = (const int*)d_in[11];

    float* out        = (float*)d_out;
    float* out_init   = out + O_INIT;
    float* out_coarse = out + O_COARSE;
    float* out_mbi    = out + O_MBI;
    float* out_mbc    = out + O_MBC;
    float* out_feat   = out + O_FEAT;

    cudaFuncSetAttribute(k_conv, cudaFuncAttributeMaxDynamicSharedMemorySize, CONV_SMEM);

    k_zero<<<576, 256>>>(ct_num, out_mbi);                        // 0
    k_init<<<128, 128>>>(wh, ct_ind, ct_img, out_init);           // 1
    k_front<<<11392, 256>>>(cnn, w1, w2, wh, ct_ind, ct_img, ct_num, out_mbi);  // 2
    k_conv<<<dim3(288, 4), 512, CONV_SMEM>>>(b1, b2);             // 3 <- profiled

    k_sample<<<128, 256>>>(ct_ind, ct_img);
    k_gemm<0><<<dim3(8, 2, NSPLIT), 256>>>(wpoly, nullptr, nullptr);
    k_reduce<<<256, 256>>>();
    k_gemm<1><<<dim3(4, 2), 256>>>(wfuse, bfuse, out_coarse);

    k_zero<<<576, 256>>>(ct_num, out_mbc);
    k_pnp_c<<<dim3(24, 64), 256>>>(ct_num, out_mbc);
    k_final<<<dim3(1152, 2, 4), dim3(32, 8)>>>(out_feat);
}

// round 11
// speedup vs baseline: 2.7016x; 1.0188x over previous
#include <cuda_runtime.h>
#include <cuda_fp16.h>
#include <cstdint>

// ---------------- problem constants ----------------
#define BATCH   4
#define CIN     64
#define HH      192
#define WW      192
#define HW      36864
#define NPOLY   128
#define PPTS    128
#define FPK     8256
#define NSPLIT  12

// output layout (floats)
#define O_INIT   0
#define O_COARSE 32768
#define O_MBI    65536
#define O_MBC    (65536 + 4718592)
#define O_FEAT   (65536 + 2*4718592)

// conv A-slab geometry (32x4 pixel patch, 1-px halo)
#define SLAB_W  34
#define SLAB_PX 204
#define SLAB_ZERO 204
#define SLAB_BYTES 26240u      // 205 rows * 128 B
#define B_OFF   52480u         // 2 * SLAB_BYTES
#define B_STAGE 32768u
#define CONV_SMEM (52480 + 3*32768)   // 150784

// ---------------- device scratch ----------------
__device__ __half g_xh_h[BATCH * HW * CIN];
__device__ __half g_xh_l[BATCH * HW * CIN];
__device__ __half g_w1h[256 * 576];
__device__ __half g_w1l[256 * 576];
__device__ __half g_w2h[64 * 256];
__device__ __half g_w2l[64 * 256];
__device__ float  g_feat[BATCH * HW * CIN];
__device__ float  g_union[BATCH * HW];
__device__ float  g_init[NPOLY * PPTS * 2];
__device__ float  g_coarse[NPOLY * PPTS * 2];
__device__ float  g_fp[NPOLY * FPK];
__device__ float  g_tmp[NPOLY * 512];
__device__ float  g_part[NSPLIT * NPOLY * 512];

// ---------------- helpers ----------------
__device__ __forceinline__ uint32_t smem_u32(const void* p) {
    uint32_t a;
    asm("{ .reg .u64 t; cvta.to.shared.u64 t, %1; cvt.u32.u64 %0, t; }" : "=r"(a) : "l"(p));
    return a;
}
__device__ __forceinline__ void cp16(uint32_t dst, const void* src, int sz) {
    asm volatile("cp.async.ca.shared.global [%0], [%1], 16, %2;" :: "r"(dst), "l"(src), "r"(sz));
}
#define CP_COMMIT() asm volatile("cp.async.commit_group;")
#define CP_WAIT1()  asm volatile("cp.async.wait_group 1;")
#define CP_WAIT0()  asm volatile("cp.async.wait_group 0;")
__device__ __forceinline__ void ldmx4(uint32_t addr, uint32_t* r) {
    asm volatile("ldmatrix.sync.aligned.m8n8.x4.shared.b16 {%0,%1,%2,%3}, [%4];"
        : "=r"(r[0]), "=r"(r[1]), "=r"(r[2]), "=r"(r[3]) : "r"(addr));
}
__device__ __forceinline__ void hmma(float* d, const uint32_t* a, const uint32_t* b) {
    asm volatile("mma.sync.aligned.m16n8k16.row.col.f32.f16.f16.f32 "
        "{%0,%1,%2,%3}, {%4,%5,%6,%7}, {%8,%9}, {%0,%1,%2,%3};"
        : "+f"(d[0]), "+f"(d[1]), "+f"(d[2]), "+f"(d[3])
        : "r"(a[0]), "r"(a[1]), "r"(a[2]), "r"(a[3]), "r"(b[0]), "r"(b[1]));
}
__device__ __forceinline__ uint32_t swz64(int row, int colb) {
    return (uint32_t)(row * 64 + (colb ^ (((row >> 1) & 3) << 4)));
}
__device__ __forceinline__ uint32_t swz128(int row, int colb) {
    return (uint32_t)(row * 128 + (colb ^ ((row & 7) << 4)));
}
__device__ __forceinline__ void split_store(__half* hp, __half* lp, float v) {
    __half h = __float2half_rn(v);
    *hp = h;
    *lp = __float2half_rn(v - __half2float(h));
}

// ---------------- zero kernel: union + mb slack slots ----------------
__global__ void k_zero(const int* __restrict__ ct_num, float* __restrict__ mb) {
    int i = blockIdx.x * 256 + threadIdx.x;
    ((unsigned*)g_union)[i] = 0u;
    int b = i / HW, px = i - b * HW;
    int cn = ct_num[b];
    for (int c = cn; c < 32; c++)
        mb[(size_t)(b * 32 + c) * HW + px] = 0.0f;
}

// ---------------- pnp body ----------------
__device__ void pnp_body(int poly, int rg, int src,
                         const float* __restrict__ wh, const int* __restrict__ ct_ind,
                         const int* __restrict__ ct_img, const int* __restrict__ ct_num,
                         float* __restrict__ mb) {
    __shared__ float verts[256];
    __shared__ float xint[8][132];
    __shared__ int cnt[8];
    __shared__ int slots[4];
    int tid = threadIdx.x;
    int rb = rg * 8;

    if (src == 0) {
        int ind = ct_ind[poly];
        int img = ct_img[poly];
        int cx = ind % WW;
        int cy = ind / WW;
        int p = tid >> 1;
        size_t base = (size_t)img * 256 * HW + (size_t)cy * WW + cx;
        float off = wh[base + (size_t)(2 * p + (tid & 1)) * HW];
        verts[tid] = off * 10.0f + (float)((tid & 1) ? cy : cx);
    } else {
        verts[tid] = g_coarse[poly * 256 + tid];
    }
    if (tid < 8) cnt[tid] = 0;
    if (tid < 4) {
        int cnb = ct_num[tid];
        int start = (tid == 0) ? 0 : ct_num[tid - 1];   // reference slicing quirk
        int c = poly - start;
        slots[tid] = (c >= 0 && c < cnb) ? c : -1;
    }
    __syncthreads();
    for (int i = tid; i < 1024; i += 256) {
        int e = i & 127, r = i >> 7;
        float yy = (float)(rb + r);
        int e2 = (e + 1) & 127;
        float y1 = verts[2 * e + 1];
        float y2 = verts[2 * e2 + 1];
        if ((y1 > yy) != (y2 > yy)) {
            float x1 = verts[2 * e];
            float x2 = verts[2 * e2];
            float den = y2 - y1;
            if (fabsf(den) < 1e-9f) den = 1e-9f;
            float xi = x1 + (x2 - x1) * (yy - y1) / den;
            int s = atomicAdd(&cnt[r], 1);
            xint[r][s] = xi;
        }
    }
    __syncthreads();
    for (int i = tid; i < 1536; i += 256) {
        int r = i / 192;
        int xp = i - r * 192;
        int c = cnt[r];
        float fx = (float)xp;
        unsigned par = 0;
        for (int j = 0; j < c; j++) par ^= (fx < xint[r][j]) ? 1u : 0u;
        float parf = (float)par;
        int px = (rb + r) * WW + xp;
#pragma unroll
        for (int b = 0; b < 4; b++) {
            int sc = slots[b];
            if (sc >= 0) {
                mb[(size_t)(b * 32 + sc) * HW + px] = parf;
                if (par) atomicOr((unsigned*)&g_union[b * HW + px], 0x3F800000u);
            }
        }
    }
}

// ---------------- K0: init polys ----------------
__global__ void k_init(const float* __restrict__ wh, const int* __restrict__ ct_ind,
                       const int* __restrict__ ct_img, float* __restrict__ out_init) {
    int n = blockIdx.x;
    int p = threadIdx.x;
    int ind = ct_ind[n];
    int img = ct_img[n];
    int cx = ind % WW;
    int cy = ind / WW;
    size_t base = (size_t)img * 256 * HW + (size_t)cy * WW + cx;
    float ox = wh[base + (size_t)(2 * p) * HW];
    float oy = wh[base + (size_t)(2 * p + 1) * HW];
    float ix = ox * 10.0f + (float)cx;
    float iy = oy * 10.0f + (float)cy;
    int o = (n * PPTS + p) * 2;
    g_init[o + 0] = ix;
    g_init[o + 1] = iy;
    out_init[o + 0] = ix * 4.0f;
    out_init[o + 1] = iy * 4.0f;
}

// ---------------- merged front ----------------
__global__ __launch_bounds__(256) void k_front(const float* __restrict__ x,
                                               const float* __restrict__ w1,
                                               const float* __restrict__ w2,
                                               const float* __restrict__ wh,
                                               const int* __restrict__ ct_ind,
                                               const int* __restrict__ ct_img,
                                               const int* __restrict__ ct_num,
                                               float* __restrict__ out_mbi) {
    int bid = blockIdx.x;
    if (bid < 640) {
        int i = bid * 256 + threadIdx.x;
        if (i < 147456) {
            int oc = i / 576, k = i - oc * 576;
            int tap = k >> 6, ic = k & 63;
            split_store(&g_w1h[i], &g_w1l[i], w1[(oc * 64 + ic) * 9 + tap]);
        } else {
            int j = i - 147456;
            split_store(&g_w2h[j], &g_w2l[j], w2[j]);
        }
        return;
    }
    if (bid < 9856) {
        __shared__ float t[32][33];
        int xb = bid - 640;
        int pxb = xb % 1152;
        int cy = (xb / 1152) & 1;
        int b = xb / 2304;
        int c0 = cy * 32;
        int p0 = pxb * 32;
        int tx = threadIdx.x & 31, ty = threadIdx.x >> 5;
#pragma unroll
        for (int i = 0; i < 32; i += 8)
            t[ty + i][tx] = x[((size_t)b * CIN + c0 + ty + i) * HW + p0 + tx];
        __syncthreads();
#pragma unroll
        for (int i = 0; i < 32; i += 8) {
            size_t o = ((size_t)b * HW + p0 + ty + i) * CIN + c0 + tx;
            split_store(&g_xh_h[o], &g_xh_l[o], t[tx][ty + i]);
        }
        return;
    }
    int j = bid - 9856;
    pnp_body(j % 64, j / 64, 0, wh, ct_ind, ct_img, ct_num, out_mbi);
}

// ---------------- pnp(coarse) ----------------
__global__ __launch_bounds__(256) void k_pnp_c(const int* __restrict__ ct_num,
                                               float* __restrict__ out_mbc) {
    pnp_body(blockIdx.y, blockIdx.x, 1, nullptr, nullptr, nullptr, ct_num, out_mbc);
}

// ---------------- fused conv1 + conv2 (+featmul) ----------------
__global__ __launch_bounds__(512, 1) void k_conv(const float* __restrict__ b1,
                                                 const float* __restrict__ b2) {
    extern __shared__ char sm[];
    uint32_t sb = smem_u32(sm);
    int tid = threadIdx.x, lane = tid & 31, wid = tid >> 5;
    int b = blockIdx.y;
    int px0 = (blockIdx.x % 6) * 32;
    int py0 = (blockIdx.x / 6) * 4;
    int wm = wid & 1, wn = wid >> 1;

    float acc[4][4][4];
#pragma unroll
    for (int i = 0; i < 4; i++)
#pragma unroll
        for (int j = 0; j < 4; j++)
#pragma unroll
            for (int k = 0; k < 4; k++) acc[i][j][k] = 0.0f;

    size_t xbase = (size_t)b * HW;

    int ry[4], rx[4], sbs[4];
#pragma unroll
    for (int mt = 0; mt < 4; mt++) {
        int r = wm * 64 + mt * 16 + (lane & 15);
        int pr = r >> 5, pc = r & 31;
        ry[mt] = py0 + pr;
        rx[mt] = px0 + pc;
        sbs[mt] = (pr + 1) * SLAB_W + pc + 1;
    }

    int brow = tid >> 1;
    int bq0 = (tid & 1) * 2;
    const __half* w1h_p = g_w1h + (size_t)brow * 576 + bq0 * 8;
    const __half* w1l_p = g_w1l + (size_t)brow * 576 + bq0 * 8;
    uint32_t bd0 = swz64(brow, bq0 * 16);
    uint32_t bd1 = swz64(brow, bq0 * 16 + 16);

    auto load_b = [&](int chunk) {
        uint32_t st = sb + B_OFF + (uint32_t)(chunk % 3) * B_STAGE;
        int tap = chunk >> 1, half = chunk & 1;
        int wo = tap * 64 + half * 32;
        cp16(st + bd0, w1h_p + wo, 16);
        cp16(st + bd1, w1h_p + wo + 8, 16);
        cp16(st + 16384u + bd0, w1l_p + wo, 16);
        cp16(st + 16384u + bd1, w1l_p + wo + 8, 16);
    };

    for (int i = tid; i < 205 * 8; i += 512) {
        int s = i >> 3, q = i & 7;
        uint32_t d = swz128(s, q * 16);
        int sz = 0;
        size_t np = 0;
        if (s < SLAB_PX) {
            int sy = s / SLAB_W, sx = s - sy * SLAB_W;
            int yy = py0 - 1 + sy, xx = px0 - 1 + sx;
            if ((unsigned)yy < 192u && (unsigned)xx < 192u) {
                np = (xbase + yy * 192 + xx) * 64 + q * 8;
                sz = 16;
            }
        }
        cp16(sb + d, g_xh_h + np, sz);
        cp16(sb + SLAB_BYTES + d, g_xh_l + np, sz);
    }
    load_b(0); CP_COMMIT();
    load_b(1); CP_COMMIT();

    for (int c = 0; c < 18; c++) {
        CP_WAIT1();
        __syncthreads();
        if (c + 2 < 18) load_b(c + 2);
        CP_COMMIT();

        int tap = c >> 1, half = c & 1;
        int dy = tap / 3 - 1, dx = tap % 3 - 1;
        uint32_t sa[4];
#pragma unroll
        for (int mt = 0; mt < 4; mt++) {
            bool v = ((unsigned)(ry[mt] + dy) < 192u) && ((unsigned)(rx[mt] + dx) < 192u);
            sa[mt] = v ? (uint32_t)(sbs[mt] + dy * SLAB_W + dx) : (uint32_t)SLAB_ZERO;
        }
        uint32_t bst = sb + B_OFF + (uint32_t)(c % 3) * B_STAGE;
#pragma unroll
        for (int k16 = 0; k16 < 2; k16++) {
            int kb = k16 * 32;
            int acolb = half * 64 + kb + (lane >> 4) * 16;
            int brr = wn * 32 + ((lane >> 4) << 3) + (lane & 7);
            int bcolb = kb + ((lane >> 3) & 1) * 16;
            uint32_t bd_a = swz64(brr, bcolb);
            uint32_t bd_b = swz64(brr + 16, bcolb);

            // load B hi+lo once per k16 (16 regs live)
            uint32_t bh[4][2], bl[4][2];
            {
                uint32_t r[4];
                ldmx4(bst + bd_a, r);
                bh[0][0] = r[0]; bh[0][1] = r[1]; bh[1][0] = r[2]; bh[1][1] = r[3];
                ldmx4(bst + bd_b, r);
                bh[2][0] = r[0]; bh[2][1] = r[1]; bh[3][0] = r[2]; bh[3][1] = r[3];
                ldmx4(bst + 16384u + bd_a, r);
                bl[0][0] = r[0]; bl[0][1] = r[1]; bl[1][0] = r[2]; bl[1][1] = r[3];
                ldmx4(bst + 16384u + bd_b, r);
                bl[2][0] = r[0]; bl[2][1] = r[1]; bl[3][0] = r[2]; bl[3][1] = r[3];
            }
            // per-mt: load A hi+lo (8 regs), fire 12 MMAs
            // per-accumulator order ah*bh -> al*bh -> ah*bl (bit-identical)
#pragma unroll
            for (int mt = 0; mt < 4; mt++) {
                uint32_t ah[4], al[4];
                uint32_t ad = swz128((int)sa[mt], acolb);
                ldmx4(sb + ad, ah);
                ldmx4(sb + SLAB_BYTES + ad, al);
#pragma unroll
                for (int nt = 0; nt < 4; nt++) hmma(acc[mt][nt], ah, bh[nt]);
#pragma unroll
                for (int nt = 0; nt < 4; nt++) hmma(acc[mt][nt], al, bh[nt]);
#pragma unroll
                for (int nt = 0; nt < 4; nt++) hmma(acc[mt][nt], ah, bl[nt]);
            }
        }
    }

    // ---------------- conv2 (4 x 64-oc phases), w2 preloaded once ----------------
    int wm2 = wid & 3, wn2 = wid >> 2;
    float acc2[2][2][4];
#pragma unroll
    for (int i = 0; i < 2; i++)
#pragma unroll
        for (int j = 0; j < 2; j++)
#pragma unroll
            for (int k = 0; k < 4; k++) acc2[i][j][k] = 0.0f;

    int w2row = tid >> 3, w2sg = tid & 7;
    uint32_t w2d = swz128(w2row, w2sg * 16);

    __syncthreads();   // all conv1 B-ring reads complete
    // preload w2 for ALL phases into B stages 0..1 (ph piece: hi @B_OFF+ph*16K, lo +8K)
#pragma unroll
    for (int ph = 0; ph < 4; ph++) {
        cp16(sb + B_OFF + (uint32_t)ph * 16384u + w2d,
             g_w2h + (size_t)w2row * 256 + ph * 64 + w2sg * 8, 16);
        cp16(sb + B_OFF + (uint32_t)ph * 16384u + 8192u + w2d,
             g_w2l + (size_t)w2row * 256 + ph * 64 + w2sg * 8, 16);
    }
    CP_COMMIT();

    for (int ph = 0; ph < 4; ph++) {
        if (ph) __syncthreads();   // prior phase t reads done
        if ((wn >> 1) == ph) {
            int ocbase = (wn & 1) * 32;
#pragma unroll
            for (int mt = 0; mt < 4; mt++) {
#pragma unroll
                for (int nt = 0; nt < 4; nt++) {
                    int oc_l = ocbase + nt * 8 + (lane & 3) * 2;
                    float bb0 = __ldg(&b1[ph * 64 + oc_l]);
                    float bb1 = __ldg(&b1[ph * 64 + oc_l + 1]);
#pragma unroll
                    for (int rh = 0; rh < 2; rh++) {
                        int row = wm * 64 + mt * 16 + (lane >> 2) + rh * 8;
                        float t0 = fmaxf(acc[mt][nt][rh * 2 + 0] + bb0, 0.0f);
                        float t1 = fmaxf(acc[mt][nt][rh * 2 + 1] + bb1, 0.0f);
                        __half h0 = __float2half_rn(t0), h1 = __float2half_rn(t1);
                        uint32_t ad = (uint32_t)(row * 128 + ((oc_l * 2) ^ ((row & 7) << 4)));
                        *(__half2*)(sm + ad) = __halves2half2(h0, h1);
                        *(__half2*)(sm + 16384 + ad) = __halves2half2(
                            __float2half_rn(t0 - __half2float(h0)),
                            __float2half_rn(t1 - __half2float(h1)));
                    }
                }
            }
        }
        if (ph == 0) CP_WAIT0();
        __syncthreads();
        uint32_t wbase = sb + B_OFF + (uint32_t)ph * 16384u;
#pragma unroll
        for (int kc = 0; kc < 2; kc++) {
#pragma unroll
            for (int k16 = 0; k16 < 2; k16++) {
                int kcb = kc * 64 + k16 * 32;
                uint32_t bf2h[2][2], bf2l[2][2];
                int brow2 = wn2 * 16 + ((lane >> 4) << 3) + (lane & 7);
                int bcolb2 = kcb + ((lane >> 3) & 1) * 16;
                uint32_t bd2 = swz128(brow2, bcolb2);
                {
                    uint32_t r[4];
                    ldmx4(wbase + bd2, r);
                    bf2h[0][0] = r[0]; bf2h[0][1] = r[1]; bf2h[1][0] = r[2]; bf2h[1][1] = r[3];
                    ldmx4(wbase + 8192u + bd2, r);
                    bf2l[0][0] = r[0]; bf2l[0][1] = r[1]; bf2l[1][0] = r[2]; bf2l[1][1] = r[3];
                }
#pragma unroll
                for (int mt = 0; mt < 2; mt++) {
                    uint32_t ah[4], al[4];
                    int row = wm2 * 32 + mt * 16 + (lane & 15);
                    int colb = kcb + (lane >> 4) * 16;
                    uint32_t ad = swz128(row, colb);
                    ldmx4(sb + ad, ah);
                    ldmx4(sb + 16384u + ad, al);
#pragma unroll
                    for (int nt = 0; nt < 2; nt++) hmma(acc2[mt][nt], ah, bf2h[nt]);
#pragma unroll
                    for (int nt = 0; nt < 2; nt++) hmma(acc2[mt][nt], al, bf2h[nt]);
#pragma unroll
                    for (int nt = 0; nt < 2; nt++) hmma(acc2[mt][nt], ah, bf2l[nt]);
                }
            }
        }
    }

    // epilogue: feat = relu((D2 + b2) * (1 + union_init))
#pragma unroll
    for (int mt = 0; mt < 2; mt++) {
#pragma unroll
        for (int nt = 0; nt < 2; nt++) {
            int oc2 = wn2 * 16 + nt * 8 + (lane & 3) * 2;
            float bb0 = __ldg(&b2[oc2]), bb1 = __ldg(&b2[oc2 + 1]);
#pragma unroll
            for (int rh = 0; rh < 2; rh++) {
                int m = wm2 * 32 + mt * 16 + (lane >> 2) + rh * 8;
                int px = (py0 + (m >> 5)) * 192 + px0 + (m & 31);
                float u = g_union[b * HW + px];
                float s = 1.0f + u;
                float2 v;
                v.x = fmaxf((acc2[mt][nt][rh * 2 + 0] + bb0) * s, 0.0f);
                v.y = fmaxf((acc2[mt][nt][rh * 2 + 1] + bb1) * s, 0.0f);
                *(float2*)&g_feat[((size_t)b * HW + px) * 64 + oc2] = v;
            }
        }
    }
}

// ---------------- final: featmul pass 2 + NHWC -> NCHW ----------------
__global__ void k_final(float* __restrict__ out) {
    __shared__ float t[32][33];
    int b = blockIdx.z;
    int c0 = blockIdx.y * 32;
    int p0 = blockIdx.x * 32;
    int tx = threadIdx.x, ty = threadIdx.y;
#pragma unroll
    for (int i = 0; i < 32; i += 8) {
        int p = p0 + ty + i;
        float u = g_union[b * HW + p];
        float v = g_feat[((size_t)b * HW + p) * CIN + c0 + tx];
        t[ty + i][tx] = fmaxf(v * (1.0f + u), 0.0f);
    }
    __syncthreads();
#pragma unroll
    for (int i = 0; i < 32; i += 8)
        out[((size_t)b * CIN + c0 + ty + i) * HW + p0 + tx] = t[tx][ty + i];
}

// ---------------- bilinear sampling (NHWC), 2 CTAs per poly ----------------
__global__ __launch_bounds__(256) void k_sample(const int* __restrict__ ct_ind,
                                                const int* __restrict__ ct_img) {
    __shared__ float s_w[129][4];
    __shared__ int s_off[129][4];
    int n = blockIdx.x >> 1;
    int half = blockIdx.x & 1;
    int tid = threadIdx.x;
    int img = ct_img[n];
    if (tid < 129) {
        float ptx, pty;
        if (tid == 0) {
            int ind = ct_ind[n];
            ptx = (float)(ind % WW);
            pty = (float)(ind / WW);
        } else {
            ptx = g_init[(n * PPTS + tid - 1) * 2 + 0];
            pty = g_init[(n * PPTS + tid - 1) * 2 + 1];
        }
        float xs = ptx - 0.5f, ys = pty - 0.5f;
        float x0f = floorf(xs), y0f = floorf(ys);
        float wx = xs - x0f, wy = ys - y0f;
        int x0 = (int)x0f, y0 = (int)y0f;
#pragma unroll
        for (int k = 0; k < 4; k++) {
            int xi = x0 + (k & 1);
            int yi = y0 + (k >> 1);
            bool valid = (xi >= 0) && (xi < WW) && (yi >= 0) && (yi < HH);
            int xc = min(max(xi, 0), WW - 1);
            int yc = min(max(yi, 0), HH - 1);
            s_off[tid][k] = yc * WW + xc;
            float wxx = (k & 1) ? wx : (1.0f - wx);
            float wyy = (k >> 1) ? wy : (1.0f - wy);
            s_w[tid][k] = valid ? wxx * wyy : 0.0f;
        }
    }
    __syncthreads();
    const float* fb = g_feat + (size_t)img * HW * CIN;
    int beg = half * 4128, end = beg + 4128;   // FPK/2
    for (int i = beg + tid; i < end; i += 256) {
        int pp = i >> 6;
        int c = i & 63;
        float v = s_w[pp][0] * fb[(size_t)s_off[pp][0] * CIN + c]
                + s_w[pp][1] * fb[(size_t)s_off[pp][1] * CIN + c]
                + s_w[pp][2] * fb[(size_t)s_off[pp][2] * CIN + c]
                + s_w[pp][3] * fb[(size_t)s_off[pp][3] * CIN + c];
        g_fp[(size_t)n * FPK + c * 129 + pp] = v;
    }
}

// ---------------- NT GEMMs for offsets (fp32, exact path) ----------------
template <int MODE>
__global__ __launch_bounds__(256) void k_gemm(const float* __restrict__ Bm,
                                              const float* __restrict__ bias,
                                              float* __restrict__ outc) {
    const int K = (MODE == 0) ? FPK : 512;
    const float* A = (MODE == 0) ? (const float*)g_fp : (const float*)g_tmp;
    __shared__ float sA[16][68];
    __shared__ float sB[16][68];
    int m0 = blockIdx.y * 64, n0 = blockIdx.x * 64;
    int tid = threadIdx.x;
    int tx = tid & 15, ty = tid >> 4;
    int kk = tid & 15, rr = tid >> 4;
    float acc[4][4];
#pragma unroll
    for (int i = 0; i < 4; i++)
#pragma unroll
        for (int j = 0; j < 4; j++) acc[i][j] = 0.0f;

    int kbeg = (MODE == 0) ? blockIdx.z * 688 : 0;
    int kend = (MODE == 0) ? kbeg + 688 : 512;
    for (int k0 = kbeg; k0 < kend; k0 += 16) {
        __syncthreads();
#pragma unroll
        for (int pass = 0; pass < 4; pass++) {
            int row = rr + pass * 16;
            sA[kk][row] = A[(size_t)(m0 + row) * K + k0 + kk];
            sB[kk][row] = Bm[(size_t)(n0 + row) * K + k0 + kk];
        }
        __syncthreads();
#pragma unroll
        for (int k2 = 0; k2 < 16; k2++) {
            float4 a4 = *(const float4*)&sA[k2][ty * 4];
            float4 b4 = *(const float4*)&sB[k2][tx * 4];
            acc[0][0] += a4.x * b4.x; acc[0][1] += a4.x * b4.y; acc[0][2] += a4.x * b4.z; acc[0][3] += a4.x * b4.w;
            acc[1][0] += a4.y * b4.x; acc[1][1] += a4.y * b4.y; acc[1][2] += a4.y * b4.z; acc[1][3] += a4.y * b4.w;
            acc[2][0] += a4.z * b4.x; acc[2][1] += a4.z * b4.y; acc[2][2] += a4.z * b4.z; acc[2][3] += a4.z * b4.w;
            acc[3][0] += a4.w * b4.x; acc[3][1] += a4.w * b4.y; acc[3][2] += a4.w * b4.z; acc[3][3] += a4.w * b4.w;
        }
    }
    if (MODE == 0) {
#pragma unroll
        for (int i = 0; i < 4; i++)
#pragma unroll
            for (int j = 0; j < 4; j++)
                g_part[((size_t)blockIdx.z * 128 + m0 + ty * 4 + i) * 512 + n0 + tx * 4 + j] = acc[i][j];
    } else {
#pragma unroll
        for (int i = 0; i < 4; i++) {
            int m = m0 + ty * 4 + i;
#pragma unroll
            for (int j = 0; j < 4; j++) {
                int nn = n0 + tx * 4 + j;
                float v = acc[i][j] + bias[nn];
                float cr = v * 4.0f + g_init[m * 256 + nn];
                g_coarse[m * 256 + nn] = cr;
                outc[m * 256 + nn] = cr * 4.0f;
            }
        }
    }
}

__global__ void k_reduce() {
    int i = blockIdx.x * 256 + threadIdx.x;
    float s = 0.0f;
#pragma unroll
    for (int p = 0; p < NSPLIT; p++) s += g_part[(size_t)p * 65536 + i];
    g_tmp[i] = s;
}

// ---------------- launcher ----------------
extern "C" void kernel_launch(void* const* d_in, const int* in_sizes, int n_in,
                              void* d_out, int out_size) {
    const float* wh     = (const float*)d_in[0];
    const float* cnn    = (const float*)d_in[1];
    const float* w1     = (const float*)d_in[2];
    const float* b1     = (const float*)d_in[3];
    const float* w2     = (const float*)d_in[4];
    const float* b2     = (const float*)d_in[5];
    const float* wpoly  = (const float*)d_in[6];
    const float* wfuse  = (const float*)d_in[7];
    const float* bfuse  = (const float*)d_in[8];
    const int*   ct_ind = (const int*)d_in[9];
    const int*   ct_img = (const int*)d_in[10];
    const int*   ct_num = (const int*)d_in[11];

    float* out        = (float*)d_out;
    float* out_init   = out + O_INIT;
    float* out_coarse = out + O_COARSE;
    float* out_mbi    = out + O_MBI;
    float* out_mbc    = out + O_MBC;
    float* out_feat   = out + O_FEAT;

    cudaFuncSetAttribute(k_conv, cudaFuncAttributeMaxDynamicSharedMemorySize, CONV_SMEM);

    k_zero<<<576, 256>>>(ct_num, out_mbi);                        // 0
    k_init<<<128, 128>>>(wh, ct_ind, ct_img, out_init);           // 1
    k_front<<<11392, 256>>>(cnn, w1, w2, wh, ct_ind, ct_img, ct_num, out_mbi);  // 2
    k_conv<<<dim3(288, 4), 512, CONV_SMEM>>>(b1, b2);             // 3 <- profiled

    k_sample<<<256, 256>>>(ct_ind, ct_img);
    k_gemm<0><<<dim3(8, 2, NSPLIT), 256>>>(wpoly, nullptr, nullptr);
    k_reduce<<<256, 256>>>();
    k_gemm<1><<<dim3(4, 2), 256>>>(wfuse, bfuse, out_coarse);

    k_zero<<<576, 256>>>(ct_num, out_mbc);
    k_pnp_c<<<dim3(24, 64), 256>>>(ct_num, out_mbc);
    k_final<<<dim3(1152, 2, 4), dim3(32, 8)>>>(out_feat);
}